// round 7
// baseline (speedup 1.0000x reference)
#include <cuda_runtime.h>
#include <cstdint>
#include <math.h>

#define D_MODEL 1024
#define NH      16
#define DH      64
#define DFF     4096
#define BATCH   4
#define LSEQ    1024
#define MROWS   (BATCH*LSEQ)       // 4096
#define ZHEADS  (BATCH*NH)         // 64

// ---------------- scratch (device globals; no runtime allocation) ----------
__device__ float g_q[(size_t)ZHEADS*LSEQ*DH];          // (b,h,l,d)
__device__ float g_k[(size_t)ZHEADS*LSEQ*DH];
__device__ float g_v[(size_t)ZHEADS*LSEQ*DH];
__device__ float g_heads[(size_t)MROWS*D_MODEL];
__device__ float g_tmp[(size_t)MROWS*D_MODEL];
__device__ float g_h[(size_t)MROWS*D_MODEL];
__device__ float g_ff[(size_t)MROWS*DFF];
__device__ float g_wtqkv[(size_t)3*D_MODEL*D_MODEL];   // [3*1024][1024] (N,K)
__device__ float g_wtp[(size_t)D_MODEL*D_MODEL];
__device__ float g_wt1[(size_t)DFF*D_MODEL];           // [4096][1024]
__device__ float g_wt2[(size_t)D_MODEL*DFF];           // [1024][4096]

// ---------------- helpers ----------------------------------------------------
__device__ __forceinline__ float f2tf32(float f) {
    uint32_t r;
    asm("cvt.rna.tf32.f32 %0, %1;" : "=r"(r) : "f"(f));
    return __uint_as_float(r);
}
__device__ __forceinline__ void mma_tf32(float* d, const uint32_t* a,
                                         const uint32_t* b) {
    asm volatile(
        "mma.sync.aligned.m16n8k8.row.col.f32.tf32.tf32.f32 "
        "{%0,%1,%2,%3}, {%4,%5,%6,%7}, {%8,%9}, {%0,%1,%2,%3};"
        : "+f"(d[0]), "+f"(d[1]), "+f"(d[2]), "+f"(d[3])
        : "r"(a[0]), "r"(a[1]), "r"(a[2]), "r"(a[3]), "r"(b[0]), "r"(b[1]));
}

// ---------------- tf32 mma GEMM: C = A[M,K] @ BT[N,K]^T ---------------------
// 128x128 CTA tile, 8 warps (2x4), warp tile 64x32, K-chunk 32.
// SMEM tiles stored crosswise-permuted: col c -> (c&3)*8 + (c>>2), so each
// thread's fragment values are contiguous float4s (LDS.128, conflict-free).
enum { EPI_QKV = 0, EPI_BIAS_RESID = 1, EPI_BIAS_RELU = 2 };

#define GM_AS_STRIDE 36
#define GM_TILE_F    (128 * GM_AS_STRIDE)            // floats per tile
#define GM_BUF_F     (2 * GM_TILE_F)                 // A + B per stage
#define GM_SMEM_B    (2 * GM_BUF_F * 4)              // 2 stages, bytes = 73728

template<int EPI>
__global__ __launch_bounds__(256) void gemm_mma(
    const float* __restrict__ A, const float* __restrict__ BT,
    float* __restrict__ C, int N, int K,
    const float* __restrict__ bias, const float* __restrict__ resid,
    float* __restrict__ qp, float* __restrict__ kp, float* __restrict__ vp)
{
    extern __shared__ float smem[];

    const int tid  = threadIdx.x;
    const int wid  = tid >> 5;
    const int lane = tid & 31;
    const int g    = lane >> 2;
    const int t4   = lane & 3;
    const int wm   = wid >> 2;          // 0..1  (64-row slab)
    const int wn   = wid & 3;           // 0..3  (32-col slab)
    const int tileM = blockIdx.y * 128;
    const int tileN = blockIdx.x * 128;

    float acc[4][4][4];
#pragma unroll
    for (int i = 0; i < 4; i++)
#pragma unroll
        for (int j = 0; j < 4; j++)
#pragma unroll
            for (int c = 0; c < 4; c++) acc[i][j][c] = 0.f;

    float4 pa[4], pb[4];

    // prefetch chunk 0
#pragma unroll
    for (int i = 0; i < 4; i++) {
        const int idx = i * 256 + tid;
        const int r   = idx >> 3;
        const int c4  = (idx & 7) * 4;
        pa[i] = *(const float4*)(A  + (size_t)(tileM + r) * K + c4);
        pb[i] = *(const float4*)(BT + (size_t)(tileN + r) * K + c4);
    }
    {
        float* As = smem;
        float* Bs = smem + GM_TILE_F;
#pragma unroll
        for (int i = 0; i < 4; i++) {
            const int idx = i * 256 + tid;
            const int r   = idx >> 3;
            const int c4  = (idx & 7) * 4;
            // permuted: value at col c4+j -> [j*8 + c4/4]
            float* ar = As + r * GM_AS_STRIDE + (c4 >> 2);
            ar[0]  = f2tf32(pa[i].x); ar[8]  = f2tf32(pa[i].y);
            ar[16] = f2tf32(pa[i].z); ar[24] = f2tf32(pa[i].w);
            float* br = Bs + r * GM_AS_STRIDE + (c4 >> 2);
            br[0]  = f2tf32(pb[i].x); br[8]  = f2tf32(pb[i].y);
            br[16] = f2tf32(pb[i].z); br[24] = f2tf32(pb[i].w);
        }
    }
    __syncthreads();

    const int KT = K >> 5;
    for (int kt = 0; kt < KT; kt++) {
        const bool more = (kt + 1) < KT;
        if (more) {
            const int k0 = (kt + 1) << 5;
#pragma unroll
            for (int i = 0; i < 4; i++) {
                const int idx = i * 256 + tid;
                const int r   = idx >> 3;
                const int c4  = (idx & 7) * 4;
                pa[i] = *(const float4*)(A  + (size_t)(tileM + r) * K + k0 + c4);
                pb[i] = *(const float4*)(BT + (size_t)(tileN + r) * K + k0 + c4);
            }
        }

        {
            const float* As = smem + (kt & 1) * GM_BUF_F;
            const float* Bs = As + GM_TILE_F;
#pragma unroll
            for (int half = 0; half < 2; half++) {
                float4 aR[4][2], bR[4];
#pragma unroll
                for (int mi = 0; mi < 4; mi++) {
                    const int rb = wm * 64 + mi * 16;
                    aR[mi][0] = *(const float4*)(As + (rb + g    ) * GM_AS_STRIDE + t4 * 8 + half * 4);
                    aR[mi][1] = *(const float4*)(As + (rb + g + 8) * GM_AS_STRIDE + t4 * 8 + half * 4);
                }
#pragma unroll
                for (int ni = 0; ni < 4; ni++) {
                    const int nb = wn * 32 + ni * 8;
                    bR[ni] = *(const float4*)(Bs + (nb + g) * GM_AS_STRIDE + t4 * 8 + half * 4);
                }
#pragma unroll
                for (int s2 = 0; s2 < 2; s2++) {
                    uint32_t af[4][4], bf[4][2];
#pragma unroll
                    for (int mi = 0; mi < 4; mi++) {
                        const float* a0 = (const float*)&aR[mi][0];
                        const float* a1 = (const float*)&aR[mi][1];
                        af[mi][0] = __float_as_uint(a0[2 * s2    ]);
                        af[mi][1] = __float_as_uint(a1[2 * s2    ]);
                        af[mi][2] = __float_as_uint(a0[2 * s2 + 1]);
                        af[mi][3] = __float_as_uint(a1[2 * s2 + 1]);
                    }
#pragma unroll
                    for (int ni = 0; ni < 4; ni++) {
                        const float* bb = (const float*)&bR[ni];
                        bf[ni][0] = __float_as_uint(bb[2 * s2    ]);
                        bf[ni][1] = __float_as_uint(bb[2 * s2 + 1]);
                    }
#pragma unroll
                    for (int mi = 0; mi < 4; mi++)
#pragma unroll
                        for (int ni = 0; ni < 4; ni++)
                            mma_tf32(acc[mi][ni], af[mi], bf[ni]);
                }
            }
        }

        if (more) {
            float* As = smem + ((kt + 1) & 1) * GM_BUF_F;
            float* Bs = As + GM_TILE_F;
#pragma unroll
            for (int i = 0; i < 4; i++) {
                const int idx = i * 256 + tid;
                const int r   = idx >> 3;
                const int c4  = (idx & 7) * 4;
                float* ar = As + r * GM_AS_STRIDE + (c4 >> 2);
                ar[0]  = f2tf32(pa[i].x); ar[8]  = f2tf32(pa[i].y);
                ar[16] = f2tf32(pa[i].z); ar[24] = f2tf32(pa[i].w);
                float* br = Bs + r * GM_AS_STRIDE + (c4 >> 2);
                br[0]  = f2tf32(pb[i].x); br[8]  = f2tf32(pb[i].y);
                br[16] = f2tf32(pb[i].z); br[24] = f2tf32(pb[i].w);
            }
            __syncthreads();
        }
    }

    // epilogue
#pragma unroll
    for (int mi = 0; mi < 4; mi++) {
#pragma unroll
        for (int half = 0; half < 2; half++) {
            const int m = tileM + wm * 64 + mi * 16 + g + half * 8;
#pragma unroll
            for (int ni = 0; ni < 4; ni++) {
                const int n = tileN + wn * 32 + ni * 8 + t4 * 2;
                float v0 = acc[mi][ni][half * 2 + 0];
                float v1 = acc[mi][ni][half * 2 + 1];
                if (EPI == EPI_QKV) {
                    const int b = m >> 10, l = m & 1023;
                    const int which = n >> 10, rem = n & 1023;
                    const int h = rem >> 6, d = rem & 63;
                    float* dst = (which == 0) ? qp : (which == 1) ? kp : vp;
                    float2 o = make_float2(v0, v1);
                    *(float2*)(dst + ((size_t)((b * NH + h) * LSEQ + l)) * DH + d) = o;
                } else {
                    const size_t idx = (size_t)m * N + n;
                    const float2 bb = *(const float2*)(bias + n);
                    v0 += bb.x; v1 += bb.y;
                    if (EPI == EPI_BIAS_RESID) {
                        const float2 rr = *(const float2*)(resid + idx);
                        v0 += rr.x; v1 += rr.y;
                    } else {
                        v0 = fmaxf(v0, 0.f); v1 = fmaxf(v1, 0.f);
                    }
                    *(float2*)(C + idx) = make_float2(v0, v1);
                }
            }
        }
    }
}

// ---------------- fused flash attention --------------------------------------
#define FA_QK_S 68
#define FA_V_S  72
#define FA_P_S  132
#define FA_Q_OFF 0
#define FA_K_OFF (FA_Q_OFF + 128 * FA_QK_S)
#define FA_V_OFF (FA_K_OFF + 128 * FA_QK_S)
#define FA_P_OFF (FA_V_OFF + 128 * FA_V_S)
#define FA_M_OFF (FA_P_OFF + 128 * FA_P_S)
#define FA_SMEM_B ((FA_M_OFF + 128) * 4)      // 174592 bytes

__global__ __launch_bounds__(256) void flash_attn(
    const float* __restrict__ Qg, const float* __restrict__ Kg,
    const float* __restrict__ Vg, const int* __restrict__ mask,
    float* __restrict__ H)
{
    extern __shared__ float smem[];
    float* Qs = smem + FA_Q_OFF;
    float* Ks = smem + FA_K_OFF;
    float* Vs = smem + FA_V_OFF;
    float* Ps = smem + FA_P_OFF;
    int*   Ms = (int*)(smem + FA_M_OFF);

    const int z = blockIdx.y;
    const int b = z >> 4, h = z & 15;
    const float* q  = Qg + (size_t)z * LSEQ * DH;
    const float* kp = Kg + (size_t)z * LSEQ * DH;
    const float* vp = Vg + (size_t)z * LSEQ * DH;
    const int* mb = mask + (size_t)b * LSEQ;
    const int tileQ = blockIdx.x * 128;

    const int tid  = threadIdx.x;
    const int wid  = tid >> 5;
    const int lane = tid & 31;
    const int g    = lane >> 2;
    const int t4   = lane & 3;
    const int rb   = wid * 16;

#pragma unroll
    for (int i = 0; i < 8; i++) {
        const int idx = i * 256 + tid;
        const int r   = idx >> 4;
        const int c4  = (idx & 15) * 4;
        float4 v4 = *(const float4*)(q + (size_t)(tileQ + r) * DH + c4);
        float* dst = Qs + r * FA_QK_S + c4;
        dst[0] = f2tf32(v4.x); dst[1] = f2tf32(v4.y);
        dst[2] = f2tf32(v4.z); dst[3] = f2tf32(v4.w);
    }

    float mrow0 = -1e30f, mrow1 = -1e30f;
    float lrow0 = 0.f, lrow1 = 0.f;
    float oacc[8][4];
#pragma unroll
    for (int i = 0; i < 8; i++)
#pragma unroll
        for (int c = 0; c < 4; c++) oacc[i][c] = 0.f;

    for (int kt = 0; kt < 8; kt++) {
        const int k0 = kt * 128;
        __syncthreads();
#pragma unroll
        for (int i = 0; i < 8; i++) {
            const int idx = i * 256 + tid;
            const int r   = idx >> 4;
            const int c4  = (idx & 15) * 4;
            float4 kv = *(const float4*)(kp + (size_t)(k0 + r) * DH + c4);
            float* kd = Ks + r * FA_QK_S + c4;
            kd[0] = f2tf32(kv.x); kd[1] = f2tf32(kv.y);
            kd[2] = f2tf32(kv.z); kd[3] = f2tf32(kv.w);
            float4 vv = *(const float4*)(vp + (size_t)(k0 + r) * DH + c4);
            float* vd = Vs + r * FA_V_S + c4;
            vd[0] = f2tf32(vv.x); vd[1] = f2tf32(vv.y);
            vd[2] = f2tf32(vv.z); vd[3] = f2tf32(vv.w);
        }
        if (tid < 128) Ms[tid] = mb[k0 + tid];
        __syncthreads();

        float sacc[16][4];
#pragma unroll
        for (int ni = 0; ni < 16; ni++)
#pragma unroll
            for (int c = 0; c < 4; c++) sacc[ni][c] = 0.f;
#pragma unroll
        for (int ks = 0; ks < 8; ks++) {
            const int k = ks * 8;
            uint32_t af[4];
            af[0] = __float_as_uint(Qs[(rb + g    ) * FA_QK_S + k + t4    ]);
            af[1] = __float_as_uint(Qs[(rb + g + 8) * FA_QK_S + k + t4    ]);
            af[2] = __float_as_uint(Qs[(rb + g    ) * FA_QK_S + k + t4 + 4]);
            af[3] = __float_as_uint(Qs[(rb + g + 8) * FA_QK_S + k + t4 + 4]);
#pragma unroll
            for (int ni = 0; ni < 16; ni++) {
                uint32_t bf[2];
                bf[0] = __float_as_uint(Ks[(ni * 8 + g) * FA_QK_S + k + t4    ]);
                bf[1] = __float_as_uint(Ks[(ni * 8 + g) * FA_QK_S + k + t4 + 4]);
                mma_tf32(sacc[ni], af, bf);
            }
        }

        float tm0 = -1e30f, tm1 = -1e30f;
#pragma unroll
        for (int ni = 0; ni < 16; ni++) {
            const int c0 = ni * 8 + t4 * 2, c1 = c0 + 1;
            const bool m0 = (Ms[c0] == 0), m1 = (Ms[c1] == 0);
            float s0 = sacc[ni][0] * 0.125f; if (m0) s0 = -1e10f;
            float s1 = sacc[ni][1] * 0.125f; if (m1) s1 = -1e10f;
            float s2 = sacc[ni][2] * 0.125f; if (m0) s2 = -1e10f;
            float s3 = sacc[ni][3] * 0.125f; if (m1) s3 = -1e10f;
            sacc[ni][0] = s0; sacc[ni][1] = s1; sacc[ni][2] = s2; sacc[ni][3] = s3;
            tm0 = fmaxf(tm0, fmaxf(s0, s1));
            tm1 = fmaxf(tm1, fmaxf(s2, s3));
        }
        tm0 = fmaxf(tm0, __shfl_xor_sync(0xffffffffu, tm0, 1));
        tm0 = fmaxf(tm0, __shfl_xor_sync(0xffffffffu, tm0, 2));
        tm1 = fmaxf(tm1, __shfl_xor_sync(0xffffffffu, tm1, 1));
        tm1 = fmaxf(tm1, __shfl_xor_sync(0xffffffffu, tm1, 2));

        const float mn0 = fmaxf(mrow0, tm0), mn1 = fmaxf(mrow1, tm1);
        const float a0 = __expf(mrow0 - mn0), a1 = __expf(mrow1 - mn1);

        float ps0 = 0.f, ps1 = 0.f;
#pragma unroll
        for (int ni = 0; ni < 16; ni++) {
            const float e0 = __expf(sacc[ni][0] - mn0);
            const float e1 = __expf(sacc[ni][1] - mn0);
            const float e2 = __expf(sacc[ni][2] - mn1);
            const float e3 = __expf(sacc[ni][3] - mn1);
            ps0 += e0 + e1; ps1 += e2 + e3;
            float* p0 = Ps + (rb + g    ) * FA_P_S + ni * 8 + t4 * 2;
            p0[0] = f2tf32(e0); p0[1] = f2tf32(e1);
            float* p1 = Ps + (rb + g + 8) * FA_P_S + ni * 8 + t4 * 2;
            p1[0] = f2tf32(e2); p1[1] = f2tf32(e3);
        }
        ps0 += __shfl_xor_sync(0xffffffffu, ps0, 1);
        ps0 += __shfl_xor_sync(0xffffffffu, ps0, 2);
        ps1 += __shfl_xor_sync(0xffffffffu, ps1, 1);
        ps1 += __shfl_xor_sync(0xffffffffu, ps1, 2);

        lrow0 = lrow0 * a0 + ps0;
        lrow1 = lrow1 * a1 + ps1;
        mrow0 = mn0; mrow1 = mn1;
#pragma unroll
        for (int ni = 0; ni < 8; ni++) {
            oacc[ni][0] *= a0; oacc[ni][1] *= a0;
            oacc[ni][2] *= a1; oacc[ni][3] *= a1;
        }
        __syncwarp();

#pragma unroll
        for (int ks = 0; ks < 16; ks++) {
            const int k = ks * 8;
            uint32_t af[4];
            af[0] = __float_as_uint(Ps[(rb + g    ) * FA_P_S + k + t4    ]);
            af[1] = __float_as_uint(Ps[(rb + g + 8) * FA_P_S + k + t4    ]);
            af[2] = __float_as_uint(Ps[(rb + g    ) * FA_P_S + k + t4 + 4]);
            af[3] = __float_as_uint(Ps[(rb + g + 8) * FA_P_S + k + t4 + 4]);
#pragma unroll
            for (int ni = 0; ni < 8; ni++) {
                uint32_t bf[2];
                bf[0] = __float_as_uint(Vs[(k + t4    ) * FA_V_S + ni * 8 + g]);
                bf[1] = __float_as_uint(Vs[(k + t4 + 4) * FA_V_S + ni * 8 + g]);
                mma_tf32(oacc[ni], af, bf);
            }
        }
    }

    const float i0 = 1.f / lrow0, i1 = 1.f / lrow1;
    const int r0 = tileQ + rb + g, r1 = r0 + 8;
#pragma unroll
    for (int ni = 0; ni < 8; ni++) {
        const int d = ni * 8 + t4 * 2;
        *(float2*)(H + (size_t)(b * LSEQ + r0) * D_MODEL + h * DH + d) =
            make_float2(oacc[ni][0] * i0, oacc[ni][1] * i0);
        *(float2*)(H + (size_t)(b * LSEQ + r1) * D_MODEL + h * DH + d) =
            make_float2(oacc[ni][2] * i1, oacc[ni][3] * i1);
    }
}

// ---------------- weight transposes ------------------------------------------
__global__ __launch_bounds__(256) void transpose_k(
    const float* __restrict__ in, float* __restrict__ out, int K, int N)
{
    __shared__ float t[32][33];
    const int bn = blockIdx.x * 32, bk = blockIdx.y * 32;
    const int tx = threadIdx.x, ty = threadIdx.y;
#pragma unroll
    for (int i = ty; i < 32; i += 8)
        t[i][tx] = in[(size_t)(bk + i) * N + bn + tx];
    __syncthreads();
#pragma unroll
    for (int i = ty; i < 32; i += 8)
        out[(size_t)(bn + i) * K + bk + tx] = t[tx][i];
}

// 4x 1024x1024 transposes in one launch (z selects the matrix)
__global__ __launch_bounds__(256) void transpose_k4(
    const float* __restrict__ i0, const float* __restrict__ i1,
    const float* __restrict__ i2, const float* __restrict__ i3,
    float* __restrict__ o0, float* __restrict__ o1,
    float* __restrict__ o2, float* __restrict__ o3)
{
    __shared__ float t[32][33];
    const float* in = (blockIdx.z == 0) ? i0 : (blockIdx.z == 1) ? i1 :
                      (blockIdx.z == 2) ? i2 : i3;
    float* out = (blockIdx.z == 0) ? o0 : (blockIdx.z == 1) ? o1 :
                 (blockIdx.z == 2) ? o2 : o3;
    const int bn = blockIdx.x * 32, bk = blockIdx.y * 32;
    const int tx = threadIdx.x, ty = threadIdx.y;
#pragma unroll
    for (int i = ty; i < 32; i += 8)
        t[i][tx] = in[(size_t)(bk + i) * 1024 + bn + tx];
    __syncthreads();
#pragma unroll
    for (int i = ty; i < 32; i += 8)
        out[(size_t)(bn + i) * 1024 + bk + tx] = t[tx][i];
}

// ---------------- layernorm --------------------------------------------------
__global__ __launch_bounds__(256) void layernorm(
    const float* __restrict__ X, const float* __restrict__ g,
    const float* __restrict__ be, float* __restrict__ O)
{
    __shared__ float red[8];
    const int r = blockIdx.x;
    const int tid = threadIdx.x;
    const float4 v = *(const float4*)(X + (size_t)r * D_MODEL + tid * 4);

    float s = v.x + v.y + v.z + v.w;
#pragma unroll
    for (int o = 16; o > 0; o >>= 1) s += __shfl_xor_sync(0xffffffffu, s, o);
    if ((tid & 31) == 0) red[tid >> 5] = s;
    __syncthreads();
    s = 0.f;
#pragma unroll
    for (int i = 0; i < 8; i++) s += red[i];
    const float mu = s * (1.f / D_MODEL);
    __syncthreads();

    float dx = v.x - mu, dy = v.y - mu, dz = v.z - mu, dw = v.w - mu;
    float sq = dx * dx + dy * dy + dz * dz + dw * dw;
#pragma unroll
    for (int o = 16; o > 0; o >>= 1) sq += __shfl_xor_sync(0xffffffffu, sq, o);
    if ((tid & 31) == 0) red[tid >> 5] = sq;
    __syncthreads();
    sq = 0.f;
#pragma unroll
    for (int i = 0; i < 8; i++) sq += red[i];
    const float rs = rsqrtf(sq * (1.f / D_MODEL) + 1e-5f);

    const float4 gg = *(const float4*)(g + tid * 4);
    const float4 bb = *(const float4*)(be + tid * 4);
    float4 o;
    o.x = dx * rs * gg.x + bb.x;
    o.y = dy * rs * gg.y + bb.y;
    o.z = dz * rs * gg.z + bb.z;
    o.w = dw * rs * gg.w + bb.w;
    *(float4*)(O + (size_t)r * D_MODEL + tid * 4) = o;
}

// ---------------- launch -----------------------------------------------------
extern "C" void kernel_launch(void* const* d_in, const int* in_sizes, int n_in,
                              void* d_out, int out_size)
{
    const float* x   = (const float*)d_in[0];
    const int*   msk = (const int*)d_in[1];
    const float* Wq  = (const float*)d_in[2];
    const float* Wk  = (const float*)d_in[3];
    const float* Wv  = (const float*)d_in[4];
    const float* Wp  = (const float*)d_in[5];
    const float* bp  = (const float*)d_in[6];
    const float* W1  = (const float*)d_in[7];
    const float* b1  = (const float*)d_in[8];
    const float* W2  = (const float*)d_in[9];
    const float* b2  = (const float*)d_in[10];
    const float* g1  = (const float*)d_in[11];
    const float* be1 = (const float*)d_in[12];
    const float* g2  = (const float*)d_in[13];
    const float* be2 = (const float*)d_in[14];
    float* out = (float*)d_out;

    float *q, *k, *v, *hd, *tmp, *h, *ff, *wtqkv, *wtp, *wt1, *wt2;
    cudaGetSymbolAddress((void**)&q,     g_q);
    cudaGetSymbolAddress((void**)&k,     g_k);
    cudaGetSymbolAddress((void**)&v,     g_v);
    cudaGetSymbolAddress((void**)&hd,    g_heads);
    cudaGetSymbolAddress((void**)&tmp,   g_tmp);
    cudaGetSymbolAddress((void**)&h,     g_h);
    cudaGetSymbolAddress((void**)&ff,    g_ff);
    cudaGetSymbolAddress((void**)&wtqkv, g_wtqkv);
    cudaGetSymbolAddress((void**)&wtp,   g_wtp);
    cudaGetSymbolAddress((void**)&wt1,   g_wt1);
    cudaGetSymbolAddress((void**)&wt2,   g_wt2);

    static bool attr_done = false;
    if (!attr_done) {
        cudaFuncSetAttribute(gemm_mma<EPI_QKV>,
                             cudaFuncAttributeMaxDynamicSharedMemorySize, GM_SMEM_B);
        cudaFuncSetAttribute(gemm_mma<EPI_BIAS_RESID>,
                             cudaFuncAttributeMaxDynamicSharedMemorySize, GM_SMEM_B);
        cudaFuncSetAttribute(gemm_mma<EPI_BIAS_RELU>,
                             cudaFuncAttributeMaxDynamicSharedMemorySize, GM_SMEM_B);
        cudaFuncSetAttribute(flash_attn,
                             cudaFuncAttributeMaxDynamicSharedMemorySize, FA_SMEM_B);
        attr_done = true;
    }

    dim3 blk(256);
    dim3 tb(32, 8);

    // weight transposes -> (N,K) layouts
    transpose_k4<<<dim3(32, 32, 4), tb>>>(
        Wq, Wk, Wv, Wp,
        wtqkv + 0 * 1024 * 1024, wtqkv + 1 * 1024 * 1024,
        wtqkv + 2 * 1024 * 1024, wtp);
    transpose_k<<<dim3(128, 32), tb>>>(W1, wt1, D_MODEL, DFF);   // 1024x4096 -> 4096x1024
    transpose_k<<<dim3(32, 128), tb>>>(W2, wt2, DFF, D_MODEL);   // 4096x1024 -> 1024x4096

    // fused QKV projection (M=4096, N=3072, K=1024), scatter to head layout
    gemm_mma<EPI_QKV><<<dim3(24, 32), blk, GM_SMEM_B>>>(
        x, wtqkv, nullptr, 3072, 1024, nullptr, nullptr, q, k, v);

    // fused attention: QK^T/8 -> masked online softmax -> P V  (per head/q-tile)
    flash_attn<<<dim3(8, ZHEADS), blk, FA_SMEM_B>>>(q, k, v, msk, hd);

    // proj + bias + residual, LN1
    gemm_mma<EPI_BIAS_RESID><<<dim3(8, 32), blk, GM_SMEM_B>>>(
        hd, wtp, tmp, 1024, 1024, bp, x, nullptr, nullptr, nullptr);
    layernorm<<<MROWS, blk>>>(tmp, g1, be1, h);

    // FF1 (ReLU), FF2 + bias + residual, LN2
    gemm_mma<EPI_BIAS_RELU><<<dim3(32, 32), blk, GM_SMEM_B>>>(
        h, wt1, ff, 4096, 1024, b1, nullptr, nullptr, nullptr, nullptr);
    gemm_mma<EPI_BIAS_RESID><<<dim3(8, 32), blk, GM_SMEM_B>>>(
        ff, wt2, tmp, 1024, 4096, b2, h, nullptr, nullptr, nullptr);
    layernorm<<<MROWS, blk>>>(tmp, g2, be2, out);
}

// round 8
// speedup vs baseline: 1.4594x; 1.4594x over previous
#include <cuda_runtime.h>
#include <cstdint>
#include <math.h>

#define D_MODEL 1024
#define NH      16
#define DH      64
#define DFF     4096
#define BATCH   4
#define LSEQ    1024
#define MROWS   (BATCH*LSEQ)       // 4096
#define ZHEADS  (BATCH*NH)         // 64

// ---------------- scratch (device globals; no runtime allocation) ----------
__device__ float g_q[(size_t)ZHEADS*LSEQ*DH];          // (b,h,l,d)
__device__ float g_k[(size_t)ZHEADS*LSEQ*DH];
__device__ float g_v[(size_t)ZHEADS*LSEQ*DH];
__device__ float g_heads[(size_t)MROWS*D_MODEL];       // tf32-rounded (flash epi)
__device__ float g_tmp[(size_t)MROWS*D_MODEL];
__device__ float g_h[(size_t)MROWS*D_MODEL];           // fp32 (residual)
__device__ float g_hr[(size_t)MROWS*D_MODEL];          // tf32-rounded twin of h
__device__ float g_xr[(size_t)MROWS*D_MODEL];          // tf32-rounded twin of x
__device__ float g_ff[(size_t)MROWS*DFF];              // tf32-rounded (FF1 epi)
__device__ float g_wtqkv[(size_t)3*D_MODEL*D_MODEL];   // rounded, (N,K)
__device__ float g_wtp[(size_t)D_MODEL*D_MODEL];       // rounded
__device__ float g_wt1[(size_t)DFF*D_MODEL];           // rounded
__device__ float g_wt2[(size_t)D_MODEL*DFF];           // rounded

// ---------------- helpers ----------------------------------------------------
__device__ __forceinline__ float f2tf32(float f) {
    uint32_t r;
    asm("cvt.rna.tf32.f32 %0, %1;" : "=r"(r) : "f"(f));
    return __uint_as_float(r);
}
__device__ __forceinline__ uint32_t smem_u32(const void* p) {
    uint32_t a;
    asm("{ .reg .u64 t; cvta.to.shared.u64 t, %1; cvt.u32.u64 %0, t; }"
        : "=r"(a) : "l"(p));
    return a;
}
__device__ __forceinline__ void cp16(uint32_t s, const float* g) {
    asm volatile("cp.async.cg.shared.global [%0], [%1], 16;" :: "r"(s), "l"(g));
}
#define CP_COMMIT() asm volatile("cp.async.commit_group;" ::: "memory")
#define CP_WAIT1()  asm volatile("cp.async.wait_group 1;" ::: "memory")

__device__ __forceinline__ void mma_tf32(float* d, const uint32_t* a,
                                         const uint32_t* b) {
    asm volatile(
        "mma.sync.aligned.m16n8k8.row.col.f32.tf32.tf32.f32 "
        "{%0,%1,%2,%3}, {%4,%5,%6,%7}, {%8,%9}, {%0,%1,%2,%3};"
        : "+f"(d[0]), "+f"(d[1]), "+f"(d[2]), "+f"(d[3])
        : "r"(a[0]), "r"(a[1]), "r"(a[2]), "r"(a[3]), "r"(b[0]), "r"(b[1]));
}

// ---------------- tf32 mma GEMM: C = A[M,K] @ BT[N,K]^T ---------------------
// Inputs MUST be pre-rounded to tf32 (RN) in global memory.
// 128x128 CTA tile, 8 warps (2x4), warp tile 64x32, K-chunk 32.
// 3-stage cp.async pipeline, no register staging.
enum { EPI_QKV = 0, EPI_BIAS_RESID = 1, EPI_BIAS_RELU = 2 };

#define GM_S      36
#define GM_TILE_F (128 * GM_S)
#define GM_BUF_F  (2 * GM_TILE_F)
#define GM_SMEM_B (3 * GM_BUF_F * 4)     // 110592 bytes

template<int EPI>
__global__ __launch_bounds__(256, 2) void gemm_mma(
    const float* __restrict__ A, const float* __restrict__ BT,
    float* __restrict__ C, int N, int K,
    const float* __restrict__ bias, const float* __restrict__ resid,
    float* __restrict__ qp, float* __restrict__ kp, float* __restrict__ vp)
{
    extern __shared__ float smem[];
    const uint32_t sb = smem_u32(smem);

    const int tid  = threadIdx.x;
    const int wid  = tid >> 5;
    const int lane = tid & 31;
    const int g    = lane >> 2;
    const int t4   = lane & 3;
    const int wm   = wid >> 2;
    const int wn   = wid & 3;
    const int tileM = blockIdx.y * 128;
    const int tileN = blockIdx.x * 128;

    const int lr  = tid >> 3;           // 0..31, row in half-tile
    const int lc4 = (tid & 7) * 4;      // col group

    float acc[4][4][4];
#pragma unroll
    for (int i = 0; i < 4; i++)
#pragma unroll
        for (int j = 0; j < 4; j++)
#pragma unroll
            for (int c = 0; c < 4; c++) acc[i][j][c] = 0.f;

    const int KT = K >> 5;

    // prologue: stages 0,1
#pragma unroll
    for (int s = 0; s < 2; s++) {
        const int k0 = s << 5;
        const uint32_t sba = sb + (uint32_t)(s * GM_BUF_F) * 4;
#pragma unroll
        for (int i = 0; i < 4; i++) {
            const int r = lr + i * 32;
            cp16(sba + (r * GM_S + lc4) * 4,
                 A + (size_t)(tileM + r) * K + k0 + lc4);
            cp16(sba + (GM_TILE_F + r * GM_S + lc4) * 4,
                 BT + (size_t)(tileN + r) * K + k0 + lc4);
        }
        CP_COMMIT();
    }

    for (int kt = 0; kt < KT; kt++) {
        CP_WAIT1();
        __syncthreads();

        // issue chunk kt+2 into stage (kt+2)%3 (safe: stage's last compute was kt-1)
        if (kt + 2 < KT) {
            const int k0 = (kt + 2) << 5;
            const uint32_t sba = sb + (uint32_t)(((kt + 2) % 3) * GM_BUF_F) * 4;
#pragma unroll
            for (int i = 0; i < 4; i++) {
                const int r = lr + i * 32;
                cp16(sba + (r * GM_S + lc4) * 4,
                     A + (size_t)(tileM + r) * K + k0 + lc4);
                cp16(sba + (GM_TILE_F + r * GM_S + lc4) * 4,
                     BT + (size_t)(tileN + r) * K + k0 + lc4);
            }
        }
        CP_COMMIT();

        const float* As = smem + (kt % 3) * GM_BUF_F;
        const float* Bs = As + GM_TILE_F;
#pragma unroll
        for (int ks = 0; ks < 4; ks++) {
            const int k = ks * 8;
            uint32_t af[4][4], bf[4][2];
#pragma unroll
            for (int mi = 0; mi < 4; mi++) {
                const int rb = wm * 64 + mi * 16;
                af[mi][0] = __float_as_uint(As[(rb + g    ) * GM_S + k + t4    ]);
                af[mi][1] = __float_as_uint(As[(rb + g + 8) * GM_S + k + t4    ]);
                af[mi][2] = __float_as_uint(As[(rb + g    ) * GM_S + k + t4 + 4]);
                af[mi][3] = __float_as_uint(As[(rb + g + 8) * GM_S + k + t4 + 4]);
            }
#pragma unroll
            for (int ni = 0; ni < 4; ni++) {
                const int nb = wn * 32 + ni * 8;
                bf[ni][0] = __float_as_uint(Bs[(nb + g) * GM_S + k + t4    ]);
                bf[ni][1] = __float_as_uint(Bs[(nb + g) * GM_S + k + t4 + 4]);
            }
#pragma unroll
            for (int mi = 0; mi < 4; mi++)
#pragma unroll
                for (int ni = 0; ni < 4; ni++)
                    mma_tf32(acc[mi][ni], af[mi], bf[ni]);
        }
    }

    // epilogue
#pragma unroll
    for (int mi = 0; mi < 4; mi++) {
#pragma unroll
        for (int half = 0; half < 2; half++) {
            const int m = tileM + wm * 64 + mi * 16 + g + half * 8;
#pragma unroll
            for (int ni = 0; ni < 4; ni++) {
                const int n = tileN + wn * 32 + ni * 8 + t4 * 2;
                float v0 = acc[mi][ni][half * 2 + 0];
                float v1 = acc[mi][ni][half * 2 + 1];
                if (EPI == EPI_QKV) {
                    const int b = m >> 10, l = m & 1023;
                    const int which = n >> 10, rem = n & 1023;
                    const int h = rem >> 6, d = rem & 63;
                    float* dst = (which == 0) ? qp : (which == 1) ? kp : vp;
                    *(float2*)(dst + ((size_t)((b * NH + h) * LSEQ + l)) * DH + d) =
                        make_float2(v0, v1);
                } else {
                    const size_t idx = (size_t)m * N + n;
                    const float2 bb = *(const float2*)(bias + n);
                    v0 += bb.x; v1 += bb.y;
                    if (EPI == EPI_BIAS_RESID) {
                        const float2 rr = *(const float2*)(resid + idx);
                        v0 += rr.x; v1 += rr.y;
                    } else { // RELU, output feeds next GEMM -> round to tf32
                        v0 = f2tf32(fmaxf(v0, 0.f));
                        v1 = f2tf32(fmaxf(v1, 0.f));
                    }
                    *(float2*)(C + idx) = make_float2(v0, v1);
                }
            }
        }
    }
}

// ---------------- fused flash attention --------------------------------------
#define FA_QK_S 68
#define FA_V_S  72
#define FA_P_S  132
#define FA_Q_OFF 0
#define FA_K_OFF (FA_Q_OFF + 128 * FA_QK_S)
#define FA_V_OFF (FA_K_OFF + 128 * FA_QK_S)
#define FA_P_OFF (FA_V_OFF + 128 * FA_V_S)
#define FA_M_OFF (FA_P_OFF + 128 * FA_P_S)
#define FA_SMEM_B ((FA_M_OFF + 128) * 4)      // 174592 bytes

__global__ __launch_bounds__(256) void flash_attn(
    const float* __restrict__ Qg, const float* __restrict__ Kg,
    const float* __restrict__ Vg, const int* __restrict__ mask,
    float* __restrict__ H)
{
    extern __shared__ float smem[];
    float* Qs = smem + FA_Q_OFF;
    float* Ks = smem + FA_K_OFF;
    float* Vs = smem + FA_V_OFF;
    float* Ps = smem + FA_P_OFF;
    int*   Ms = (int*)(smem + FA_M_OFF);

    const int z = blockIdx.y;
    const int b = z >> 4, h = z & 15;
    const float* q  = Qg + (size_t)z * LSEQ * DH;
    const float* kp = Kg + (size_t)z * LSEQ * DH;
    const float* vp = Vg + (size_t)z * LSEQ * DH;
    const int* mb = mask + (size_t)b * LSEQ;
    const int tileQ = blockIdx.x * 128;

    const int tid  = threadIdx.x;
    const int wid  = tid >> 5;
    const int lane = tid & 31;
    const int g    = lane >> 2;
    const int t4   = lane & 3;
    const int rb   = wid * 16;

#pragma unroll
    for (int i = 0; i < 8; i++) {
        const int idx = i * 256 + tid;
        const int r   = idx >> 4;
        const int c4  = (idx & 15) * 4;
        float4 v4 = *(const float4*)(q + (size_t)(tileQ + r) * DH + c4);
        float* dst = Qs + r * FA_QK_S + c4;
        dst[0] = f2tf32(v4.x); dst[1] = f2tf32(v4.y);
        dst[2] = f2tf32(v4.z); dst[3] = f2tf32(v4.w);
    }

    float mrow0 = -1e30f, mrow1 = -1e30f;
    float lrow0 = 0.f, lrow1 = 0.f;
    float oacc[8][4];
#pragma unroll
    for (int i = 0; i < 8; i++)
#pragma unroll
        for (int c = 0; c < 4; c++) oacc[i][c] = 0.f;

    for (int kt = 0; kt < 8; kt++) {
        const int k0 = kt * 128;
        __syncthreads();
#pragma unroll
        for (int i = 0; i < 8; i++) {
            const int idx = i * 256 + tid;
            const int r   = idx >> 4;
            const int c4  = (idx & 15) * 4;
            float4 kv = *(const float4*)(kp + (size_t)(k0 + r) * DH + c4);
            float* kd = Ks + r * FA_QK_S + c4;
            kd[0] = f2tf32(kv.x); kd[1] = f2tf32(kv.y);
            kd[2] = f2tf32(kv.z); kd[3] = f2tf32(kv.w);
            float4 vv = *(const float4*)(vp + (size_t)(k0 + r) * DH + c4);
            float* vd = Vs + r * FA_V_S + c4;
            vd[0] = f2tf32(vv.x); vd[1] = f2tf32(vv.y);
            vd[2] = f2tf32(vv.z); vd[3] = f2tf32(vv.w);
        }
        if (tid < 128) Ms[tid] = mb[k0 + tid];
        __syncthreads();

        float sacc[16][4];
#pragma unroll
        for (int ni = 0; ni < 16; ni++)
#pragma unroll
            for (int c = 0; c < 4; c++) sacc[ni][c] = 0.f;
#pragma unroll
        for (int ks = 0; ks < 8; ks++) {
            const int k = ks * 8;
            uint32_t af[4];
            af[0] = __float_as_uint(Qs[(rb + g    ) * FA_QK_S + k + t4    ]);
            af[1] = __float_as_uint(Qs[(rb + g + 8) * FA_QK_S + k + t4    ]);
            af[2] = __float_as_uint(Qs[(rb + g    ) * FA_QK_S + k + t4 + 4]);
            af[3] = __float_as_uint(Qs[(rb + g + 8) * FA_QK_S + k + t4 + 4]);
#pragma unroll
            for (int ni = 0; ni < 16; ni++) {
                uint32_t bf[2];
                bf[0] = __float_as_uint(Ks[(ni * 8 + g) * FA_QK_S + k + t4    ]);
                bf[1] = __float_as_uint(Ks[(ni * 8 + g) * FA_QK_S + k + t4 + 4]);
                mma_tf32(sacc[ni], af, bf);
            }
        }

        float tm0 = -1e30f, tm1 = -1e30f;
#pragma unroll
        for (int ni = 0; ni < 16; ni++) {
            const int c0 = ni * 8 + t4 * 2, c1 = c0 + 1;
            const bool m0 = (Ms[c0] == 0), m1 = (Ms[c1] == 0);
            float s0 = sacc[ni][0] * 0.125f; if (m0) s0 = -1e10f;
            float s1 = sacc[ni][1] * 0.125f; if (m1) s1 = -1e10f;
            float s2 = sacc[ni][2] * 0.125f; if (m0) s2 = -1e10f;
            float s3 = sacc[ni][3] * 0.125f; if (m1) s3 = -1e10f;
            sacc[ni][0] = s0; sacc[ni][1] = s1; sacc[ni][2] = s2; sacc[ni][3] = s3;
            tm0 = fmaxf(tm0, fmaxf(s0, s1));
            tm1 = fmaxf(tm1, fmaxf(s2, s3));
        }
        tm0 = fmaxf(tm0, __shfl_xor_sync(0xffffffffu, tm0, 1));
        tm0 = fmaxf(tm0, __shfl_xor_sync(0xffffffffu, tm0, 2));
        tm1 = fmaxf(tm1, __shfl_xor_sync(0xffffffffu, tm1, 1));
        tm1 = fmaxf(tm1, __shfl_xor_sync(0xffffffffu, tm1, 2));

        const float mn0 = fmaxf(mrow0, tm0), mn1 = fmaxf(mrow1, tm1);
        const float a0 = __expf(mrow0 - mn0), a1 = __expf(mrow1 - mn1);

        float ps0 = 0.f, ps1 = 0.f;
#pragma unroll
        for (int ni = 0; ni < 16; ni++) {
            const float e0 = __expf(sacc[ni][0] - mn0);
            const float e1 = __expf(sacc[ni][1] - mn0);
            const float e2 = __expf(sacc[ni][2] - mn1);
            const float e3 = __expf(sacc[ni][3] - mn1);
            ps0 += e0 + e1; ps1 += e2 + e3;
            float* p0 = Ps + (rb + g    ) * FA_P_S + ni * 8 + t4 * 2;
            p0[0] = f2tf32(e0); p0[1] = f2tf32(e1);
            float* p1 = Ps + (rb + g + 8) * FA_P_S + ni * 8 + t4 * 2;
            p1[0] = f2tf32(e2); p1[1] = f2tf32(e3);
        }
        ps0 += __shfl_xor_sync(0xffffffffu, ps0, 1);
        ps0 += __shfl_xor_sync(0xffffffffu, ps0, 2);
        ps1 += __shfl_xor_sync(0xffffffffu, ps1, 1);
        ps1 += __shfl_xor_sync(0xffffffffu, ps1, 2);

        lrow0 = lrow0 * a0 + ps0;
        lrow1 = lrow1 * a1 + ps1;
        mrow0 = mn0; mrow1 = mn1;
#pragma unroll
        for (int ni = 0; ni < 8; ni++) {
            oacc[ni][0] *= a0; oacc[ni][1] *= a0;
            oacc[ni][2] *= a1; oacc[ni][3] *= a1;
        }
        __syncwarp();

#pragma unroll
        for (int ks = 0; ks < 16; ks++) {
            const int k = ks * 8;
            uint32_t af[4];
            af[0] = __float_as_uint(Ps[(rb + g    ) * FA_P_S + k + t4    ]);
            af[1] = __float_as_uint(Ps[(rb + g + 8) * FA_P_S + k + t4    ]);
            af[2] = __float_as_uint(Ps[(rb + g    ) * FA_P_S + k + t4 + 4]);
            af[3] = __float_as_uint(Ps[(rb + g + 8) * FA_P_S + k + t4 + 4]);
#pragma unroll
            for (int ni = 0; ni < 8; ni++) {
                uint32_t bf[2];
                bf[0] = __float_as_uint(Vs[(k + t4    ) * FA_V_S + ni * 8 + g]);
                bf[1] = __float_as_uint(Vs[(k + t4 + 4) * FA_V_S + ni * 8 + g]);
                mma_tf32(oacc[ni], af, bf);
            }
        }
    }

    // normalize + ROUND (hd feeds the proj GEMM which expects tf32 inputs)
    const float i0 = 1.f / lrow0, i1 = 1.f / lrow1;
    const int r0 = tileQ + rb + g, r1 = r0 + 8;
#pragma unroll
    for (int ni = 0; ni < 8; ni++) {
        const int d = ni * 8 + t4 * 2;
        *(float2*)(H + (size_t)(b * LSEQ + r0) * D_MODEL + h * DH + d) =
            make_float2(f2tf32(oacc[ni][0] * i0), f2tf32(oacc[ni][1] * i0));
        *(float2*)(H + (size_t)(b * LSEQ + r1) * D_MODEL + h * DH + d) =
            make_float2(f2tf32(oacc[ni][2] * i1), f2tf32(oacc[ni][3] * i1));
    }
}

// ---------------- weight transposes (round to tf32 on store) -----------------
__global__ __launch_bounds__(256) void transpose_k(
    const float* __restrict__ in, float* __restrict__ out, int K, int N)
{
    __shared__ float t[32][33];
    const int bn = blockIdx.x * 32, bk = blockIdx.y * 32;
    const int tx = threadIdx.x, ty = threadIdx.y;
#pragma unroll
    for (int i = ty; i < 32; i += 8)
        t[i][tx] = in[(size_t)(bk + i) * N + bn + tx];
    __syncthreads();
#pragma unroll
    for (int i = ty; i < 32; i += 8)
        out[(size_t)(bn + i) * K + bk + tx] = f2tf32(t[tx][i]);
}

__global__ __launch_bounds__(256) void transpose_k4(
    const float* __restrict__ i0, const float* __restrict__ i1,
    const float* __restrict__ i2, const float* __restrict__ i3,
    float* __restrict__ o0, float* __restrict__ o1,
    float* __restrict__ o2, float* __restrict__ o3)
{
    __shared__ float t[32][33];
    const float* in = (blockIdx.z == 0) ? i0 : (blockIdx.z == 1) ? i1 :
                      (blockIdx.z == 2) ? i2 : i3;
    float* out = (blockIdx.z == 0) ? o0 : (blockIdx.z == 1) ? o1 :
                 (blockIdx.z == 2) ? o2 : o3;
    const int bn = blockIdx.x * 32, bk = blockIdx.y * 32;
    const int tx = threadIdx.x, ty = threadIdx.y;
#pragma unroll
    for (int i = ty; i < 32; i += 8)
        t[i][tx] = in[(size_t)(bk + i) * 1024 + bn + tx];
    __syncthreads();
#pragma unroll
    for (int i = ty; i < 32; i += 8)
        out[(size_t)(bn + i) * 1024 + bk + tx] = f2tf32(t[tx][i]);
}

// ---------------- round-copy (x -> tf32 twin) --------------------------------
__global__ __launch_bounds__(256) void round_copy(
    const float* __restrict__ in, float* __restrict__ out)
{
    const size_t i = ((size_t)blockIdx.x * 256 + threadIdx.x) * 4;
    float4 v = *(const float4*)(in + i);
    v.x = f2tf32(v.x); v.y = f2tf32(v.y);
    v.z = f2tf32(v.z); v.w = f2tf32(v.w);
    *(float4*)(out + i) = v;
}

// ---------------- layernorm (optional rounded twin output) -------------------
__global__ __launch_bounds__(256) void layernorm(
    const float* __restrict__ X, const float* __restrict__ g,
    const float* __restrict__ be, float* __restrict__ O,
    float* __restrict__ Or)
{
    __shared__ float red[8];
    const int r = blockIdx.x;
    const int tid = threadIdx.x;
    const float4 v = *(const float4*)(X + (size_t)r * D_MODEL + tid * 4);

    float s = v.x + v.y + v.z + v.w;
#pragma unroll
    for (int o = 16; o > 0; o >>= 1) s += __shfl_xor_sync(0xffffffffu, s, o);
    if ((tid & 31) == 0) red[tid >> 5] = s;
    __syncthreads();
    s = 0.f;
#pragma unroll
    for (int i = 0; i < 8; i++) s += red[i];
    const float mu = s * (1.f / D_MODEL);
    __syncthreads();

    float dx = v.x - mu, dy = v.y - mu, dz = v.z - mu, dw = v.w - mu;
    float sq = dx * dx + dy * dy + dz * dz + dw * dw;
#pragma unroll
    for (int o = 16; o > 0; o >>= 1) sq += __shfl_xor_sync(0xffffffffu, sq, o);
    if ((tid & 31) == 0) red[tid >> 5] = sq;
    __syncthreads();
    sq = 0.f;
#pragma unroll
    for (int i = 0; i < 8; i++) sq += red[i];
    const float rs = rsqrtf(sq * (1.f / D_MODEL) + 1e-5f);

    const float4 gg = *(const float4*)(g + tid * 4);
    const float4 bb = *(const float4*)(be + tid * 4);
    float4 o;
    o.x = dx * rs * gg.x + bb.x;
    o.y = dy * rs * gg.y + bb.y;
    o.z = dz * rs * gg.z + bb.z;
    o.w = dw * rs * gg.w + bb.w;
    *(float4*)(O + (size_t)r * D_MODEL + tid * 4) = o;
    if (Or) {
        float4 q;
        q.x = f2tf32(o.x); q.y = f2tf32(o.y);
        q.z = f2tf32(o.z); q.w = f2tf32(o.w);
        *(float4*)(Or + (size_t)r * D_MODEL + tid * 4) = q;
    }
}

// ---------------- launch -----------------------------------------------------
extern "C" void kernel_launch(void* const* d_in, const int* in_sizes, int n_in,
                              void* d_out, int out_size)
{
    const float* x   = (const float*)d_in[0];
    const int*   msk = (const int*)d_in[1];
    const float* Wq  = (const float*)d_in[2];
    const float* Wk  = (const float*)d_in[3];
    const float* Wv  = (const float*)d_in[4];
    const float* Wp  = (const float*)d_in[5];
    const float* bp  = (const float*)d_in[6];
    const float* W1  = (const float*)d_in[7];
    const float* b1  = (const float*)d_in[8];
    const float* W2  = (const float*)d_in[9];
    const float* b2  = (const float*)d_in[10];
    const float* g1  = (const float*)d_in[11];
    const float* be1 = (const float*)d_in[12];
    const float* g2  = (const float*)d_in[13];
    const float* be2 = (const float*)d_in[14];
    float* out = (float*)d_out;

    float *q, *k, *v, *hd, *tmp, *h, *hr, *xr, *ff, *wtqkv, *wtp, *wt1, *wt2;
    cudaGetSymbolAddress((void**)&q,     g_q);
    cudaGetSymbolAddress((void**)&k,     g_k);
    cudaGetSymbolAddress((void**)&v,     g_v);
    cudaGetSymbolAddress((void**)&hd,    g_heads);
    cudaGetSymbolAddress((void**)&tmp,   g_tmp);
    cudaGetSymbolAddress((void**)&h,     g_h);
    cudaGetSymbolAddress((void**)&hr,    g_hr);
    cudaGetSymbolAddress((void**)&xr,    g_xr);
    cudaGetSymbolAddress((void**)&ff,    g_ff);
    cudaGetSymbolAddress((void**)&wtqkv, g_wtqkv);
    cudaGetSymbolAddress((void**)&wtp,   g_wtp);
    cudaGetSymbolAddress((void**)&wt1,   g_wt1);
    cudaGetSymbolAddress((void**)&wt2,   g_wt2);

    static bool attr_done = false;
    if (!attr_done) {
        cudaFuncSetAttribute(gemm_mma<EPI_QKV>,
                             cudaFuncAttributeMaxDynamicSharedMemorySize, GM_SMEM_B);
        cudaFuncSetAttribute(gemm_mma<EPI_BIAS_RESID>,
                             cudaFuncAttributeMaxDynamicSharedMemorySize, GM_SMEM_B);
        cudaFuncSetAttribute(gemm_mma<EPI_BIAS_RELU>,
                             cudaFuncAttributeMaxDynamicSharedMemorySize, GM_SMEM_B);
        cudaFuncSetAttribute(flash_attn,
                             cudaFuncAttributeMaxDynamicSharedMemorySize, FA_SMEM_B);
        attr_done = true;
    }

    dim3 blk(256);
    dim3 tb(32, 8);

    // weight transposes (rounded) + rounded x twin
    transpose_k4<<<dim3(32, 32, 4), tb>>>(
        Wq, Wk, Wv, Wp,
        wtqkv + 0 * 1024 * 1024, wtqkv + 1 * 1024 * 1024,
        wtqkv + 2 * 1024 * 1024, wtp);
    transpose_k<<<dim3(128, 32), tb>>>(W1, wt1, D_MODEL, DFF);
    transpose_k<<<dim3(32, 128), tb>>>(W2, wt2, DFF, D_MODEL);
    round_copy<<<MROWS * D_MODEL / 1024, blk>>>(x, xr);

    // fused QKV projection (rounded inputs), scatter to head layout
    gemm_mma<EPI_QKV><<<dim3(24, 32), blk, GM_SMEM_B>>>(
        xr, wtqkv, nullptr, 3072, 1024, nullptr, nullptr, q, k, v);

    // fused attention (writes rounded hd)
    flash_attn<<<dim3(8, ZHEADS), blk, FA_SMEM_B>>>(q, k, v, msk, hd);

    // proj + bias + residual(x fp32), LN1 (h fp32 + hr rounded)
    gemm_mma<EPI_BIAS_RESID><<<dim3(8, 32), blk, GM_SMEM_B>>>(
        hd, wtp, tmp, 1024, 1024, bp, x, nullptr, nullptr, nullptr);
    layernorm<<<MROWS, blk>>>(tmp, g1, be1, h, hr);

    // FF1 (ReLU, writes rounded ff), FF2 + bias + residual(h fp32), LN2
    gemm_mma<EPI_BIAS_RELU><<<dim3(32, 32), blk, GM_SMEM_B>>>(
        hr, wt1, ff, 4096, 1024, b1, nullptr, nullptr, nullptr, nullptr);
    gemm_mma<EPI_BIAS_RESID><<<dim3(8, 32), blk, GM_SMEM_B>>>(
        ff, wt2, tmp, 1024, 4096, b2, h, nullptr, nullptr, nullptr);
    layernorm<<<MROWS, blk>>>(tmp, g2, be2, out, nullptr);
}

// round 9
// speedup vs baseline: 2.0635x; 1.4139x over previous
#include <cuda_runtime.h>
#include <cuda_fp16.h>
#include <cstdint>
#include <math.h>

#define D_MODEL 1024
#define NH      16
#define DH      64
#define DFF     4096
#define BATCH   4
#define LSEQ    1024
#define MROWS   (BATCH*LSEQ)       // 4096
#define ZHEADS  (BATCH*NH)         // 64

// ---------------- scratch (device globals; no runtime allocation) ----------
__device__ float  g_q[(size_t)ZHEADS*LSEQ*DH];          // fp32 (flash input)
__device__ float  g_k[(size_t)ZHEADS*LSEQ*DH];
__device__ float  g_v[(size_t)ZHEADS*LSEQ*DH];
__device__ __half g_heads[(size_t)MROWS*D_MODEL];       // fp16 (flash epi)
__device__ float  g_tmp[(size_t)MROWS*D_MODEL];
__device__ float  g_h[(size_t)MROWS*D_MODEL];           // fp32 residual
__device__ __half g_hh[(size_t)MROWS*D_MODEL];          // fp16 twin of h
__device__ __half g_xh[(size_t)MROWS*D_MODEL];          // fp16 twin of x
__device__ __half g_ff[(size_t)MROWS*DFF];              // fp16 (FF1 epi)
__device__ __half g_wtqkv[(size_t)3*D_MODEL*D_MODEL];   // fp16, (N,K)
__device__ __half g_wtp[(size_t)D_MODEL*D_MODEL];
__device__ __half g_wt1[(size_t)DFF*D_MODEL];
__device__ __half g_wt2[(size_t)D_MODEL*DFF];

// ---------------- helpers ----------------------------------------------------
__device__ __forceinline__ float f2tf32(float f) {
    uint32_t r;
    asm("cvt.rna.tf32.f32 %0, %1;" : "=r"(r) : "f"(f));
    return __uint_as_float(r);
}
__device__ __forceinline__ uint32_t smem_u32(const void* p) {
    uint32_t a;
    asm("{ .reg .u64 t; cvta.to.shared.u64 t, %1; cvt.u32.u64 %0, t; }"
        : "=r"(a) : "l"(p));
    return a;
}
__device__ __forceinline__ void cp16(uint32_t s, const void* g) {
    asm volatile("cp.async.cg.shared.global [%0], [%1], 16;" :: "r"(s), "l"(g));
}
#define CP_COMMIT() asm volatile("cp.async.commit_group;" ::: "memory")
#define CP_WAIT1()  asm volatile("cp.async.wait_group 1;" ::: "memory")

__device__ __forceinline__ void mma_tf32(float* d, const uint32_t* a,
                                         const uint32_t* b) {
    asm volatile(
        "mma.sync.aligned.m16n8k8.row.col.f32.tf32.tf32.f32 "
        "{%0,%1,%2,%3}, {%4,%5,%6,%7}, {%8,%9}, {%0,%1,%2,%3};"
        : "+f"(d[0]), "+f"(d[1]), "+f"(d[2]), "+f"(d[3])
        : "r"(a[0]), "r"(a[1]), "r"(a[2]), "r"(a[3]), "r"(b[0]), "r"(b[1]));
}
__device__ __forceinline__ void mma_f16(float* d, const uint32_t* a,
                                        const uint32_t* b) {
    asm volatile(
        "mma.sync.aligned.m16n8k16.row.col.f32.f16.f16.f32 "
        "{%0,%1,%2,%3}, {%4,%5,%6,%7}, {%8,%9}, {%0,%1,%2,%3};"
        : "+f"(d[0]), "+f"(d[1]), "+f"(d[2]), "+f"(d[3])
        : "r"(a[0]), "r"(a[1]), "r"(a[2]), "r"(a[3]), "r"(b[0]), "r"(b[1]));
}

// ---------------- fp16 mma GEMM: C = A[M,K] @ BT[N,K]^T ---------------------
// Inputs are fp16. 128x128 CTA tile, 8 warps (2x4), warp tile 64x32,
// K-chunk 32 (2 k-steps of 16). 3-stage cp.async pipeline.
enum { EPI_QKV = 0, EPI_BIAS_RESID = 1, EPI_BIAS_RELU = 2 };

#define GM_S      40                      // halves per row (20 banks: conflict-free)
#define GM_TILE_H (128 * GM_S)
#define GM_BUF_H  (2 * GM_TILE_H)
#define GM_SMEM_B (3 * GM_BUF_H * 2)      // 61440 bytes

template<int EPI>
__global__ __launch_bounds__(256, 2) void gemm_mma(
    const __half* __restrict__ A, const __half* __restrict__ BT,
    float* __restrict__ Cf, __half* __restrict__ Ch, int N, int K,
    const float* __restrict__ bias, const float* __restrict__ resid,
    float* __restrict__ qp, float* __restrict__ kp, float* __restrict__ vp)
{
    extern __shared__ __half smemh[];
    const uint32_t sb = smem_u32(smemh);

    const int tid  = threadIdx.x;
    const int wid  = tid >> 5;
    const int lane = tid & 31;
    const int g    = lane >> 2;
    const int t4   = lane & 3;
    const int wm   = wid >> 2;
    const int wn   = wid & 3;
    const int tileM = blockIdx.y * 128;
    const int tileN = blockIdx.x * 128;

    const int lr  = tid >> 2;           // 0..63
    const int lc8 = (tid & 3) * 8;      // half-offset of 16B segment

    float acc[4][4][4];
#pragma unroll
    for (int i = 0; i < 4; i++)
#pragma unroll
        for (int j = 0; j < 4; j++)
#pragma unroll
            for (int c = 0; c < 4; c++) acc[i][j][c] = 0.f;

    const int KT = K >> 5;

#pragma unroll
    for (int s = 0; s < 2; s++) {
        const int k0 = s << 5;
        const uint32_t sba = sb + (uint32_t)(s * GM_BUF_H) * 2;
#pragma unroll
        for (int i = 0; i < 2; i++) {
            const int r = lr + i * 64;
            cp16(sba + (r * GM_S + lc8) * 2,
                 A + (size_t)(tileM + r) * K + k0 + lc8);
            cp16(sba + (GM_TILE_H + r * GM_S + lc8) * 2,
                 BT + (size_t)(tileN + r) * K + k0 + lc8);
        }
        CP_COMMIT();
    }

    for (int kt = 0; kt < KT; kt++) {
        CP_WAIT1();
        __syncthreads();

        if (kt + 2 < KT) {
            const int k0 = (kt + 2) << 5;
            const uint32_t sba = sb + (uint32_t)(((kt + 2) % 3) * GM_BUF_H) * 2;
#pragma unroll
            for (int i = 0; i < 2; i++) {
                const int r = lr + i * 64;
                cp16(sba + (r * GM_S + lc8) * 2,
                     A + (size_t)(tileM + r) * K + k0 + lc8);
                cp16(sba + (GM_TILE_H + r * GM_S + lc8) * 2,
                     BT + (size_t)(tileN + r) * K + k0 + lc8);
            }
        }
        CP_COMMIT();

        const __half* As = smemh + (kt % 3) * GM_BUF_H;
        const __half* Bs = As + GM_TILE_H;
#pragma unroll
        for (int ks = 0; ks < 2; ks++) {
            const int k = ks * 16;
            uint32_t af[4][4], bf[4][2];
#pragma unroll
            for (int mi = 0; mi < 4; mi++) {
                const int rb = wm * 64 + mi * 16;
                af[mi][0] = *(const uint32_t*)(As + (rb + g    ) * GM_S + k + 2 * t4    );
                af[mi][1] = *(const uint32_t*)(As + (rb + g + 8) * GM_S + k + 2 * t4    );
                af[mi][2] = *(const uint32_t*)(As + (rb + g    ) * GM_S + k + 2 * t4 + 8);
                af[mi][3] = *(const uint32_t*)(As + (rb + g + 8) * GM_S + k + 2 * t4 + 8);
            }
#pragma unroll
            for (int ni = 0; ni < 4; ni++) {
                const int nb = wn * 32 + ni * 8;
                bf[ni][0] = *(const uint32_t*)(Bs + (nb + g) * GM_S + k + 2 * t4    );
                bf[ni][1] = *(const uint32_t*)(Bs + (nb + g) * GM_S + k + 2 * t4 + 8);
            }
#pragma unroll
            for (int mi = 0; mi < 4; mi++)
#pragma unroll
                for (int ni = 0; ni < 4; ni++)
                    mma_f16(acc[mi][ni], af[mi], bf[ni]);
        }
    }

    // epilogue
#pragma unroll
    for (int mi = 0; mi < 4; mi++) {
#pragma unroll
        for (int half = 0; half < 2; half++) {
            const int m = tileM + wm * 64 + mi * 16 + g + half * 8;
#pragma unroll
            for (int ni = 0; ni < 4; ni++) {
                const int n = tileN + wn * 32 + ni * 8 + t4 * 2;
                float v0 = acc[mi][ni][half * 2 + 0];
                float v1 = acc[mi][ni][half * 2 + 1];
                if (EPI == EPI_QKV) {
                    const int b = m >> 10, l = m & 1023;
                    const int which = n >> 10, rem = n & 1023;
                    const int h = rem >> 6, d = rem & 63;
                    float* dst = (which == 0) ? qp : (which == 1) ? kp : vp;
                    *(float2*)(dst + ((size_t)((b * NH + h) * LSEQ + l)) * DH + d) =
                        make_float2(v0, v1);
                } else {
                    const size_t idx = (size_t)m * N + n;
                    const float2 bb = *(const float2*)(bias + n);
                    v0 += bb.x; v1 += bb.y;
                    if (EPI == EPI_BIAS_RESID) {
                        const float2 rr = *(const float2*)(resid + idx);
                        v0 += rr.x; v1 += rr.y;
                        *(float2*)(Cf + idx) = make_float2(v0, v1);
                    } else { // RELU -> fp16 (feeds next GEMM)
                        v0 = fmaxf(v0, 0.f); v1 = fmaxf(v1, 0.f);
                        *(__half2*)(Ch + idx) = __floats2half2_rn(v0, v1);
                    }
                }
            }
        }
    }
}

// ---------------- fused flash attention (tf32 path, unchanged) ---------------
#define FA_QK_S 68
#define FA_V_S  72
#define FA_P_S  132
#define FA_Q_OFF 0
#define FA_K_OFF (FA_Q_OFF + 128 * FA_QK_S)
#define FA_V_OFF (FA_K_OFF + 128 * FA_QK_S)
#define FA_P_OFF (FA_V_OFF + 128 * FA_V_S)
#define FA_M_OFF (FA_P_OFF + 128 * FA_P_S)
#define FA_SMEM_B ((FA_M_OFF + 128) * 4)      // 174592 bytes

__global__ __launch_bounds__(256) void flash_attn(
    const float* __restrict__ Qg, const float* __restrict__ Kg,
    const float* __restrict__ Vg, const int* __restrict__ mask,
    __half* __restrict__ H)
{
    extern __shared__ float smem[];
    float* Qs = smem + FA_Q_OFF;
    float* Ks = smem + FA_K_OFF;
    float* Vs = smem + FA_V_OFF;
    float* Ps = smem + FA_P_OFF;
    int*   Ms = (int*)(smem + FA_M_OFF);

    const int z = blockIdx.y;
    const int b = z >> 4, h = z & 15;
    const float* q  = Qg + (size_t)z * LSEQ * DH;
    const float* kp = Kg + (size_t)z * LSEQ * DH;
    const float* vp = Vg + (size_t)z * LSEQ * DH;
    const int* mb = mask + (size_t)b * LSEQ;
    const int tileQ = blockIdx.x * 128;

    const int tid  = threadIdx.x;
    const int wid  = tid >> 5;
    const int lane = tid & 31;
    const int g    = lane >> 2;
    const int t4   = lane & 3;
    const int rb   = wid * 16;

#pragma unroll
    for (int i = 0; i < 8; i++) {
        const int idx = i * 256 + tid;
        const int r   = idx >> 4;
        const int c4  = (idx & 15) * 4;
        float4 v4 = *(const float4*)(q + (size_t)(tileQ + r) * DH + c4);
        float* dst = Qs + r * FA_QK_S + c4;
        dst[0] = f2tf32(v4.x); dst[1] = f2tf32(v4.y);
        dst[2] = f2tf32(v4.z); dst[3] = f2tf32(v4.w);
    }

    float mrow0 = -1e30f, mrow1 = -1e30f;
    float lrow0 = 0.f, lrow1 = 0.f;
    float oacc[8][4];
#pragma unroll
    for (int i = 0; i < 8; i++)
#pragma unroll
        for (int c = 0; c < 4; c++) oacc[i][c] = 0.f;

    for (int kt = 0; kt < 8; kt++) {
        const int k0 = kt * 128;
        __syncthreads();
#pragma unroll
        for (int i = 0; i < 8; i++) {
            const int idx = i * 256 + tid;
            const int r   = idx >> 4;
            const int c4  = (idx & 15) * 4;
            float4 kv = *(const float4*)(kp + (size_t)(k0 + r) * DH + c4);
            float* kd = Ks + r * FA_QK_S + c4;
            kd[0] = f2tf32(kv.x); kd[1] = f2tf32(kv.y);
            kd[2] = f2tf32(kv.z); kd[3] = f2tf32(kv.w);
            float4 vv = *(const float4*)(vp + (size_t)(k0 + r) * DH + c4);
            float* vd = Vs + r * FA_V_S + c4;
            vd[0] = f2tf32(vv.x); vd[1] = f2tf32(vv.y);
            vd[2] = f2tf32(vv.z); vd[3] = f2tf32(vv.w);
        }
        if (tid < 128) Ms[tid] = mb[k0 + tid];
        __syncthreads();

        float sacc[16][4];
#pragma unroll
        for (int ni = 0; ni < 16; ni++)
#pragma unroll
            for (int c = 0; c < 4; c++) sacc[ni][c] = 0.f;
#pragma unroll
        for (int ks = 0; ks < 8; ks++) {
            const int k = ks * 8;
            uint32_t af[4];
            af[0] = __float_as_uint(Qs[(rb + g    ) * FA_QK_S + k + t4    ]);
            af[1] = __float_as_uint(Qs[(rb + g + 8) * FA_QK_S + k + t4    ]);
            af[2] = __float_as_uint(Qs[(rb + g    ) * FA_QK_S + k + t4 + 4]);
            af[3] = __float_as_uint(Qs[(rb + g + 8) * FA_QK_S + k + t4 + 4]);
#pragma unroll
            for (int ni = 0; ni < 16; ni++) {
                uint32_t bf[2];
                bf[0] = __float_as_uint(Ks[(ni * 8 + g) * FA_QK_S + k + t4    ]);
                bf[1] = __float_as_uint(Ks[(ni * 8 + g) * FA_QK_S + k + t4 + 4]);
                mma_tf32(sacc[ni], af, bf);
            }
        }

        float tm0 = -1e30f, tm1 = -1e30f;
#pragma unroll
        for (int ni = 0; ni < 16; ni++) {
            const int c0 = ni * 8 + t4 * 2, c1 = c0 + 1;
            const bool m0 = (Ms[c0] == 0), m1 = (Ms[c1] == 0);
            float s0 = sacc[ni][0] * 0.125f; if (m0) s0 = -1e10f;
            float s1 = sacc[ni][1] * 0.125f; if (m1) s1 = -1e10f;
            float s2 = sacc[ni][2] * 0.125f; if (m0) s2 = -1e10f;
            float s3 = sacc[ni][3] * 0.125f; if (m1) s3 = -1e10f;
            sacc[ni][0] = s0; sacc[ni][1] = s1; sacc[ni][2] = s2; sacc[ni][3] = s3;
            tm0 = fmaxf(tm0, fmaxf(s0, s1));
            tm1 = fmaxf(tm1, fmaxf(s2, s3));
        }
        tm0 = fmaxf(tm0, __shfl_xor_sync(0xffffffffu, tm0, 1));
        tm0 = fmaxf(tm0, __shfl_xor_sync(0xffffffffu, tm0, 2));
        tm1 = fmaxf(tm1, __shfl_xor_sync(0xffffffffu, tm1, 1));
        tm1 = fmaxf(tm1, __shfl_xor_sync(0xffffffffu, tm1, 2));

        const float mn0 = fmaxf(mrow0, tm0), mn1 = fmaxf(mrow1, tm1);
        const float a0 = __expf(mrow0 - mn0), a1 = __expf(mrow1 - mn1);

        float ps0 = 0.f, ps1 = 0.f;
#pragma unroll
        for (int ni = 0; ni < 16; ni++) {
            const float e0 = __expf(sacc[ni][0] - mn0);
            const float e1 = __expf(sacc[ni][1] - mn0);
            const float e2 = __expf(sacc[ni][2] - mn1);
            const float e3 = __expf(sacc[ni][3] - mn1);
            ps0 += e0 + e1; ps1 += e2 + e3;
            float* p0 = Ps + (rb + g    ) * FA_P_S + ni * 8 + t4 * 2;
            p0[0] = f2tf32(e0); p0[1] = f2tf32(e1);
            float* p1 = Ps + (rb + g + 8) * FA_P_S + ni * 8 + t4 * 2;
            p1[0] = f2tf32(e2); p1[1] = f2tf32(e3);
        }
        ps0 += __shfl_xor_sync(0xffffffffu, ps0, 1);
        ps0 += __shfl_xor_sync(0xffffffffu, ps0, 2);
        ps1 += __shfl_xor_sync(0xffffffffu, ps1, 1);
        ps1 += __shfl_xor_sync(0xffffffffu, ps1, 2);

        lrow0 = lrow0 * a0 + ps0;
        lrow1 = lrow1 * a1 + ps1;
        mrow0 = mn0; mrow1 = mn1;
#pragma unroll
        for (int ni = 0; ni < 8; ni++) {
            oacc[ni][0] *= a0; oacc[ni][1] *= a0;
            oacc[ni][2] *= a1; oacc[ni][3] *= a1;
        }
        __syncwarp();

#pragma unroll
        for (int ks = 0; ks < 16; ks++) {
            const int k = ks * 8;
            uint32_t af[4];
            af[0] = __float_as_uint(Ps[(rb + g    ) * FA_P_S + k + t4    ]);
            af[1] = __float_as_uint(Ps[(rb + g + 8) * FA_P_S + k + t4    ]);
            af[2] = __float_as_uint(Ps[(rb + g    ) * FA_P_S + k + t4 + 4]);
            af[3] = __float_as_uint(Ps[(rb + g + 8) * FA_P_S + k + t4 + 4]);
#pragma unroll
            for (int ni = 0; ni < 8; ni++) {
                uint32_t bf[2];
                bf[0] = __float_as_uint(Vs[(k + t4    ) * FA_V_S + ni * 8 + g]);
                bf[1] = __float_as_uint(Vs[(k + t4 + 4) * FA_V_S + ni * 8 + g]);
                mma_tf32(oacc[ni], af, bf);
            }
        }
    }

    // normalize + convert to fp16 (hd feeds the fp16 proj GEMM)
    const float i0 = 1.f / lrow0, i1 = 1.f / lrow1;
    const int r0 = tileQ + rb + g, r1 = r0 + 8;
#pragma unroll
    for (int ni = 0; ni < 8; ni++) {
        const int d = ni * 8 + t4 * 2;
        *(__half2*)(H + (size_t)(b * LSEQ + r0) * D_MODEL + h * DH + d) =
            __floats2half2_rn(oacc[ni][0] * i0, oacc[ni][1] * i0);
        *(__half2*)(H + (size_t)(b * LSEQ + r1) * D_MODEL + h * DH + d) =
            __floats2half2_rn(oacc[ni][2] * i1, oacc[ni][3] * i1);
    }
}

// ---------------- weight transposes (convert to fp16 on store) ---------------
__global__ __launch_bounds__(256) void transpose_k(
    const float* __restrict__ in, __half* __restrict__ out, int K, int N)
{
    __shared__ float t[32][33];
    const int bn = blockIdx.x * 32, bk = blockIdx.y * 32;
    const int tx = threadIdx.x, ty = threadIdx.y;
#pragma unroll
    for (int i = ty; i < 32; i += 8)
        t[i][tx] = in[(size_t)(bk + i) * N + bn + tx];
    __syncthreads();
#pragma unroll
    for (int i = ty; i < 32; i += 8)
        out[(size_t)(bn + i) * K + bk + tx] = __float2half_rn(t[tx][i]);
}

__global__ __launch_bounds__(256) void transpose_k4(
    const float* __restrict__ i0, const float* __restrict__ i1,
    const float* __restrict__ i2, const float* __restrict__ i3,
    __half* __restrict__ o0, __half* __restrict__ o1,
    __half* __restrict__ o2, __half* __restrict__ o3)
{
    __shared__ float t[32][33];
    const float* in = (blockIdx.z == 0) ? i0 : (blockIdx.z == 1) ? i1 :
                      (blockIdx.z == 2) ? i2 : i3;
    __half* out = (blockIdx.z == 0) ? o0 : (blockIdx.z == 1) ? o1 :
                  (blockIdx.z == 2) ? o2 : o3;
    const int bn = blockIdx.x * 32, bk = blockIdx.y * 32;
    const int tx = threadIdx.x, ty = threadIdx.y;
#pragma unroll
    for (int i = ty; i < 32; i += 8)
        t[i][tx] = in[(size_t)(bk + i) * 1024 + bn + tx];
    __syncthreads();
#pragma unroll
    for (int i = ty; i < 32; i += 8)
        out[(size_t)(bn + i) * 1024 + bk + tx] = __float2half_rn(t[tx][i]);
}

// ---------------- round-copy (x -> fp16 twin) --------------------------------
__global__ __launch_bounds__(256) void half_copy(
    const float* __restrict__ in, __half* __restrict__ out)
{
    const size_t i = ((size_t)blockIdx.x * 256 + threadIdx.x) * 4;
    float4 v = *(const float4*)(in + i);
    __half2 lo = __floats2half2_rn(v.x, v.y);
    __half2 hi = __floats2half2_rn(v.z, v.w);
    *(__half2*)(out + i)     = lo;
    *(__half2*)(out + i + 2) = hi;
}

// ---------------- layernorm (optional fp16 twin output) ----------------------
__global__ __launch_bounds__(256) void layernorm(
    const float* __restrict__ X, const float* __restrict__ g,
    const float* __restrict__ be, float* __restrict__ O,
    __half* __restrict__ Or)
{
    __shared__ float red[8];
    const int r = blockIdx.x;
    const int tid = threadIdx.x;
    const float4 v = *(const float4*)(X + (size_t)r * D_MODEL + tid * 4);

    float s = v.x + v.y + v.z + v.w;
#pragma unroll
    for (int o = 16; o > 0; o >>= 1) s += __shfl_xor_sync(0xffffffffu, s, o);
    if ((tid & 31) == 0) red[tid >> 5] = s;
    __syncthreads();
    s = 0.f;
#pragma unroll
    for (int i = 0; i < 8; i++) s += red[i];
    const float mu = s * (1.f / D_MODEL);
    __syncthreads();

    float dx = v.x - mu, dy = v.y - mu, dz = v.z - mu, dw = v.w - mu;
    float sq = dx * dx + dy * dy + dz * dz + dw * dw;
#pragma unroll
    for (int o = 16; o > 0; o >>= 1) sq += __shfl_xor_sync(0xffffffffu, sq, o);
    if ((tid & 31) == 0) red[tid >> 5] = sq;
    __syncthreads();
    sq = 0.f;
#pragma unroll
    for (int i = 0; i < 8; i++) sq += red[i];
    const float rs = rsqrtf(sq * (1.f / D_MODEL) + 1e-5f);

    const float4 gg = *(const float4*)(g + tid * 4);
    const float4 bb = *(const float4*)(be + tid * 4);
    float4 o;
    o.x = dx * rs * gg.x + bb.x;
    o.y = dy * rs * gg.y + bb.y;
    o.z = dz * rs * gg.z + bb.z;
    o.w = dw * rs * gg.w + bb.w;
    *(float4*)(O + (size_t)r * D_MODEL + tid * 4) = o;
    if (Or) {
        *(__half2*)(Or + (size_t)r * D_MODEL + tid * 4)     = __floats2half2_rn(o.x, o.y);
        *(__half2*)(Or + (size_t)r * D_MODEL + tid * 4 + 2) = __floats2half2_rn(o.z, o.w);
    }
}

// ---------------- launch -----------------------------------------------------
extern "C" void kernel_launch(void* const* d_in, const int* in_sizes, int n_in,
                              void* d_out, int out_size)
{
    const float* x   = (const float*)d_in[0];
    const int*   msk = (const int*)d_in[1];
    const float* Wq  = (const float*)d_in[2];
    const float* Wk  = (const float*)d_in[3];
    const float* Wv  = (const float*)d_in[4];
    const float* Wp  = (const float*)d_in[5];
    const float* bp  = (const float*)d_in[6];
    const float* W1  = (const float*)d_in[7];
    const float* b1  = (const float*)d_in[8];
    const float* W2  = (const float*)d_in[9];
    const float* b2  = (const float*)d_in[10];
    const float* g1  = (const float*)d_in[11];
    const float* be1 = (const float*)d_in[12];
    const float* g2  = (const float*)d_in[13];
    const float* be2 = (const float*)d_in[14];
    float* out = (float*)d_out;

    float *q, *k, *v, *tmp, *h;
    __half *hd, *hh, *xh, *ff, *wtqkv, *wtp, *wt1, *wt2;
    cudaGetSymbolAddress((void**)&q,     g_q);
    cudaGetSymbolAddress((void**)&k,     g_k);
    cudaGetSymbolAddress((void**)&v,     g_v);
    cudaGetSymbolAddress((void**)&hd,    g_heads);
    cudaGetSymbolAddress((void**)&tmp,   g_tmp);
    cudaGetSymbolAddress((void**)&h,     g_h);
    cudaGetSymbolAddress((void**)&hh,    g_hh);
    cudaGetSymbolAddress((void**)&xh,    g_xh);
    cudaGetSymbolAddress((void**)&ff,    g_ff);
    cudaGetSymbolAddress((void**)&wtqkv, g_wtqkv);
    cudaGetSymbolAddress((void**)&wtp,   g_wtp);
    cudaGetSymbolAddress((void**)&wt1,   g_wt1);
    cudaGetSymbolAddress((void**)&wt2,   g_wt2);

    static bool attr_done = false;
    if (!attr_done) {
        cudaFuncSetAttribute(gemm_mma<EPI_QKV>,
                             cudaFuncAttributeMaxDynamicSharedMemorySize, GM_SMEM_B);
        cudaFuncSetAttribute(gemm_mma<EPI_BIAS_RESID>,
                             cudaFuncAttributeMaxDynamicSharedMemorySize, GM_SMEM_B);
        cudaFuncSetAttribute(gemm_mma<EPI_BIAS_RELU>,
                             cudaFuncAttributeMaxDynamicSharedMemorySize, GM_SMEM_B);
        cudaFuncSetAttribute(flash_attn,
                             cudaFuncAttributeMaxDynamicSharedMemorySize, FA_SMEM_B);
        attr_done = true;
    }

    dim3 blk(256);
    dim3 tb(32, 8);

    // weight transposes (fp16) + fp16 x twin
    transpose_k4<<<dim3(32, 32, 4), tb>>>(
        Wq, Wk, Wv, Wp,
        wtqkv + 0 * 1024 * 1024, wtqkv + 1 * 1024 * 1024,
        wtqkv + 2 * 1024 * 1024, wtp);
    transpose_k<<<dim3(128, 32), tb>>>(W1, wt1, D_MODEL, DFF);
    transpose_k<<<dim3(32, 128), tb>>>(W2, wt2, DFF, D_MODEL);
    half_copy<<<MROWS * D_MODEL / 1024, blk>>>(x, xh);

    // fused QKV projection (fp16 in, fp32 out), scatter to head layout
    gemm_mma<EPI_QKV><<<dim3(24, 32), blk, GM_SMEM_B>>>(
        xh, wtqkv, nullptr, nullptr, 3072, 1024, nullptr, nullptr, q, k, v);

    // fused attention (tf32 math, writes fp16 hd)
    flash_attn<<<dim3(8, ZHEADS), blk, FA_SMEM_B>>>(q, k, v, msk, hd);

    // proj + bias + residual(x fp32), LN1 (h fp32 + hh fp16)
    gemm_mma<EPI_BIAS_RESID><<<dim3(8, 32), blk, GM_SMEM_B>>>(
        hd, wtp, tmp, nullptr, 1024, 1024, bp, x, nullptr, nullptr, nullptr);
    layernorm<<<MROWS, blk>>>(tmp, g1, be1, h, hh);

    // FF1 (ReLU -> fp16 ff), FF2 + bias + residual(h fp32), LN2
    gemm_mma<EPI_BIAS_RELU><<<dim3(32, 32), blk, GM_SMEM_B>>>(
        hh, wt1, nullptr, ff, 4096, 1024, b1, nullptr, nullptr, nullptr, nullptr);
    gemm_mma<EPI_BIAS_RESID><<<dim3(8, 32), blk, GM_SMEM_B>>>(
        ff, wt2, tmp, nullptr, 1024, 4096, b2, h, nullptr, nullptr, nullptr);
    layernorm<<<MROWS, blk>>>(tmp, g2, be2, out, nullptr);
}

// round 10
// speedup vs baseline: 2.1940x; 1.0632x over previous
#include <cuda_runtime.h>
#include <cuda_fp16.h>
#include <cstdint>
#include <math.h>

#define D_MODEL 1024
#define NH      16
#define DH      64
#define DFF     4096
#define BATCH   4
#define LSEQ    1024
#define MROWS   (BATCH*LSEQ)       // 4096
#define ZHEADS  (BATCH*NH)         // 64

// ---------------- scratch (device globals; no runtime allocation) ----------
__device__ __half g_q[(size_t)ZHEADS*LSEQ*DH];          // fp16 (b,h,l,d)
__device__ __half g_k[(size_t)ZHEADS*LSEQ*DH];
__device__ __half g_v[(size_t)ZHEADS*LSEQ*DH];
__device__ __half g_heads[(size_t)MROWS*D_MODEL];       // fp16 (flash epi)
__device__ float  g_tmp[(size_t)MROWS*D_MODEL];
__device__ float  g_h[(size_t)MROWS*D_MODEL];           // fp32 residual
__device__ __half g_hh[(size_t)MROWS*D_MODEL];          // fp16 twin of h
__device__ __half g_xh[(size_t)MROWS*D_MODEL];          // fp16 twin of x
__device__ __half g_ff[(size_t)MROWS*DFF];              // fp16 (FF1 epi)
__device__ __half g_wtqkv[(size_t)3*D_MODEL*D_MODEL];   // fp16, (N,K)
__device__ __half g_wtp[(size_t)D_MODEL*D_MODEL];
__device__ __half g_wt1[(size_t)DFF*D_MODEL];
__device__ __half g_wt2[(size_t)D_MODEL*DFF];

// ---------------- helpers ----------------------------------------------------
__device__ __forceinline__ uint32_t smem_u32(const void* p) {
    uint32_t a;
    asm("{ .reg .u64 t; cvta.to.shared.u64 t, %1; cvt.u32.u64 %0, t; }"
        : "=r"(a) : "l"(p));
    return a;
}
__device__ __forceinline__ void cp16(uint32_t s, const void* g) {
    asm volatile("cp.async.cg.shared.global [%0], [%1], 16;" :: "r"(s), "l"(g));
}
#define CP_COMMIT() asm volatile("cp.async.commit_group;" ::: "memory")
#define CP_WAIT1()  asm volatile("cp.async.wait_group 1;" ::: "memory")

__device__ __forceinline__ void mma_f16(float* d, const uint32_t* a,
                                        const uint32_t* b) {
    asm volatile(
        "mma.sync.aligned.m16n8k16.row.col.f32.f16.f16.f32 "
        "{%0,%1,%2,%3}, {%4,%5,%6,%7}, {%8,%9}, {%0,%1,%2,%3};"
        : "+f"(d[0]), "+f"(d[1]), "+f"(d[2]), "+f"(d[3])
        : "r"(a[0]), "r"(a[1]), "r"(a[2]), "r"(a[3]), "r"(b[0]), "r"(b[1]));
}

// ---------------- fp16 mma GEMM: C = A[M,K] @ BT[N,K]^T ---------------------
enum { EPI_QKV = 0, EPI_BIAS_RESID = 1, EPI_BIAS_RELU = 2 };

#define GM_S      40
#define GM_TILE_H (128 * GM_S)
#define GM_BUF_H  (2 * GM_TILE_H)
#define GM_SMEM_B (3 * GM_BUF_H * 2)      // 61440 bytes

template<int EPI>
__global__ __launch_bounds__(256, 2) void gemm_mma(
    const __half* __restrict__ A, const __half* __restrict__ BT,
    float* __restrict__ Cf, __half* __restrict__ Ch, int N, int K,
    const float* __restrict__ bias, const float* __restrict__ resid,
    __half* __restrict__ qp, __half* __restrict__ kp, __half* __restrict__ vp)
{
    extern __shared__ __half smemh[];
    const uint32_t sb = smem_u32(smemh);

    const int tid  = threadIdx.x;
    const int wid  = tid >> 5;
    const int lane = tid & 31;
    const int g    = lane >> 2;
    const int t4   = lane & 3;
    const int wm   = wid >> 2;
    const int wn   = wid & 3;
    const int tileM = blockIdx.y * 128;
    const int tileN = blockIdx.x * 128;

    const int lr  = tid >> 2;
    const int lc8 = (tid & 3) * 8;

    float acc[4][4][4];
#pragma unroll
    for (int i = 0; i < 4; i++)
#pragma unroll
        for (int j = 0; j < 4; j++)
#pragma unroll
            for (int c = 0; c < 4; c++) acc[i][j][c] = 0.f;

    const int KT = K >> 5;

#pragma unroll
    for (int s = 0; s < 2; s++) {
        const int k0 = s << 5;
        const uint32_t sba = sb + (uint32_t)(s * GM_BUF_H) * 2;
#pragma unroll
        for (int i = 0; i < 2; i++) {
            const int r = lr + i * 64;
            cp16(sba + (r * GM_S + lc8) * 2,
                 A + (size_t)(tileM + r) * K + k0 + lc8);
            cp16(sba + (GM_TILE_H + r * GM_S + lc8) * 2,
                 BT + (size_t)(tileN + r) * K + k0 + lc8);
        }
        CP_COMMIT();
    }

    for (int kt = 0; kt < KT; kt++) {
        CP_WAIT1();
        __syncthreads();

        if (kt + 2 < KT) {
            const int k0 = (kt + 2) << 5;
            const uint32_t sba = sb + (uint32_t)(((kt + 2) % 3) * GM_BUF_H) * 2;
#pragma unroll
            for (int i = 0; i < 2; i++) {
                const int r = lr + i * 64;
                cp16(sba + (r * GM_S + lc8) * 2,
                     A + (size_t)(tileM + r) * K + k0 + lc8);
                cp16(sba + (GM_TILE_H + r * GM_S + lc8) * 2,
                     BT + (size_t)(tileN + r) * K + k0 + lc8);
            }
        }
        CP_COMMIT();

        const __half* As = smemh + (kt % 3) * GM_BUF_H;
        const __half* Bs = As + GM_TILE_H;
#pragma unroll
        for (int ks = 0; ks < 2; ks++) {
            const int k = ks * 16;
            uint32_t af[4][4], bf[4][2];
#pragma unroll
            for (int mi = 0; mi < 4; mi++) {
                const int rb = wm * 64 + mi * 16;
                af[mi][0] = *(const uint32_t*)(As + (rb + g    ) * GM_S + k + 2 * t4    );
                af[mi][1] = *(const uint32_t*)(As + (rb + g + 8) * GM_S + k + 2 * t4    );
                af[mi][2] = *(const uint32_t*)(As + (rb + g    ) * GM_S + k + 2 * t4 + 8);
                af[mi][3] = *(const uint32_t*)(As + (rb + g + 8) * GM_S + k + 2 * t4 + 8);
            }
#pragma unroll
            for (int ni = 0; ni < 4; ni++) {
                const int nb = wn * 32 + ni * 8;
                bf[ni][0] = *(const uint32_t*)(Bs + (nb + g) * GM_S + k + 2 * t4    );
                bf[ni][1] = *(const uint32_t*)(Bs + (nb + g) * GM_S + k + 2 * t4 + 8);
            }
#pragma unroll
            for (int mi = 0; mi < 4; mi++)
#pragma unroll
                for (int ni = 0; ni < 4; ni++)
                    mma_f16(acc[mi][ni], af[mi], bf[ni]);
        }
    }

#pragma unroll
    for (int mi = 0; mi < 4; mi++) {
#pragma unroll
        for (int half = 0; half < 2; half++) {
            const int m = tileM + wm * 64 + mi * 16 + g + half * 8;
#pragma unroll
            for (int ni = 0; ni < 4; ni++) {
                const int n = tileN + wn * 32 + ni * 8 + t4 * 2;
                float v0 = acc[mi][ni][half * 2 + 0];
                float v1 = acc[mi][ni][half * 2 + 1];
                if (EPI == EPI_QKV) {
                    const int b = m >> 10, l = m & 1023;
                    const int which = n >> 10, rem = n & 1023;
                    const int h = rem >> 6, d = rem & 63;
                    __half* dst = (which == 0) ? qp : (which == 1) ? kp : vp;
                    *(__half2*)(dst + ((size_t)((b * NH + h) * LSEQ + l)) * DH + d) =
                        __floats2half2_rn(v0, v1);
                } else {
                    const size_t idx = (size_t)m * N + n;
                    const float2 bb = *(const float2*)(bias + n);
                    v0 += bb.x; v1 += bb.y;
                    if (EPI == EPI_BIAS_RESID) {
                        const float2 rr = *(const float2*)(resid + idx);
                        v0 += rr.x; v1 += rr.y;
                        *(float2*)(Cf + idx) = make_float2(v0, v1);
                    } else {
                        v0 = fmaxf(v0, 0.f); v1 = fmaxf(v1, 0.f);
                        *(__half2*)(Ch + idx) = __floats2half2_rn(v0, v1);
                    }
                }
            }
        }
    }
}

// ---------------- fused flash attention (fp16 MMA) ---------------------------
// Qs/Ks: [128][72] halves (row=seq, col=d). Vt: [64][136] halves (row=d,
// col=key, transposed at fill). Ps: [128][136] halves.
#define FQ_S   72
#define FVT_S  136
#define FP_S   136
#define FQ_OFF  0
#define FK_OFF  (FQ_OFF + 128 * FQ_S)          // 9216
#define FVT_OFF (FK_OFF + 128 * FQ_S)          // 18432
#define FP_OFF  (FVT_OFF + 64 * FVT_S)         // 27136
#define FM_OFF  (FP_OFF + 128 * FP_S)          // 44544 halves
#define FA_SMEM_B (FM_OFF * 2 + 128 * 4)       // 89600 bytes

__global__ __launch_bounds__(256, 2) void flash_attn(
    const __half* __restrict__ Qg, const __half* __restrict__ Kg,
    const __half* __restrict__ Vg, const int* __restrict__ mask,
    __half* __restrict__ H)
{
    extern __shared__ __half smh[];
    __half* Qs = smh + FQ_OFF;
    __half* Ks = smh + FK_OFF;
    __half* Vt = smh + FVT_OFF;
    __half* Ps = smh + FP_OFF;
    int*    Ms = (int*)(smh + FM_OFF);

    const int z = blockIdx.y;
    const int b = z >> 4, h = z & 15;
    const __half* q  = Qg + (size_t)z * LSEQ * DH;
    const __half* kp = Kg + (size_t)z * LSEQ * DH;
    const __half* vp = Vg + (size_t)z * LSEQ * DH;
    const int* mb = mask + (size_t)b * LSEQ;
    const int tileQ = blockIdx.x * 128;

    const int tid  = threadIdx.x;
    const int wid  = tid >> 5;
    const int lane = tid & 31;
    const int g    = lane >> 2;
    const int t4   = lane & 3;
    const int rb   = wid * 16;

    // Q tile: 128 rows x 64 halves, 8 halves per thread-iter
#pragma unroll
    for (int i = 0; i < 4; i++) {
        const int idx = i * 256 + tid;
        const int r   = idx >> 3;
        const int c8  = (idx & 7) * 8;
        *(uint4*)(Qs + r * FQ_S + c8) =
            *(const uint4*)(q + (size_t)(tileQ + r) * DH + c8);
    }

    float mrow0 = -1e30f, mrow1 = -1e30f;
    float lrow0 = 0.f, lrow1 = 0.f;
    float oacc[8][4];
#pragma unroll
    for (int i = 0; i < 8; i++)
#pragma unroll
        for (int c = 0; c < 4; c++) oacc[i][c] = 0.f;

    for (int kt = 0; kt < 8; kt++) {
        const int k0 = kt * 128;
        __syncthreads();
        // K tile (row=key, col=d) and V tile transposed (row=d, col=key)
#pragma unroll
        for (int i = 0; i < 4; i++) {
            const int idx = i * 256 + tid;
            const int r   = idx >> 3;
            const int c8  = (idx & 7) * 8;
            *(uint4*)(Ks + r * FQ_S + c8) =
                *(const uint4*)(kp + (size_t)(k0 + r) * DH + c8);
            uint4 vv = *(const uint4*)(vp + (size_t)(k0 + r) * DH + c8);
            const __half* vh = (const __half*)&vv;
#pragma unroll
            for (int j = 0; j < 8; j++)
                Vt[(c8 + j) * FVT_S + r] = vh[j];
        }
        if (tid < 128) Ms[tid] = mb[k0 + tid];
        __syncthreads();

        // S = Q K^T  (fp16, 4 k-steps of 16)
        float sacc[16][4];
#pragma unroll
        for (int ni = 0; ni < 16; ni++)
#pragma unroll
            for (int c = 0; c < 4; c++) sacc[ni][c] = 0.f;
#pragma unroll
        for (int ks = 0; ks < 4; ks++) {
            const int k = ks * 16;
            uint32_t af[4];
            af[0] = *(const uint32_t*)(Qs + (rb + g    ) * FQ_S + k + 2 * t4    );
            af[1] = *(const uint32_t*)(Qs + (rb + g + 8) * FQ_S + k + 2 * t4    );
            af[2] = *(const uint32_t*)(Qs + (rb + g    ) * FQ_S + k + 2 * t4 + 8);
            af[3] = *(const uint32_t*)(Qs + (rb + g + 8) * FQ_S + k + 2 * t4 + 8);
#pragma unroll
            for (int ni = 0; ni < 16; ni++) {
                uint32_t bf[2];
                bf[0] = *(const uint32_t*)(Ks + (ni * 8 + g) * FQ_S + k + 2 * t4    );
                bf[1] = *(const uint32_t*)(Ks + (ni * 8 + g) * FQ_S + k + 2 * t4 + 8);
                mma_f16(sacc[ni], af, bf);
            }
        }

        float tm0 = -1e30f, tm1 = -1e30f;
#pragma unroll
        for (int ni = 0; ni < 16; ni++) {
            const int c0 = ni * 8 + t4 * 2, c1 = c0 + 1;
            const bool m0 = (Ms[c0] == 0), m1 = (Ms[c1] == 0);
            float s0 = sacc[ni][0] * 0.125f; if (m0) s0 = -1e10f;
            float s1 = sacc[ni][1] * 0.125f; if (m1) s1 = -1e10f;
            float s2 = sacc[ni][2] * 0.125f; if (m0) s2 = -1e10f;
            float s3 = sacc[ni][3] * 0.125f; if (m1) s3 = -1e10f;
            sacc[ni][0] = s0; sacc[ni][1] = s1; sacc[ni][2] = s2; sacc[ni][3] = s3;
            tm0 = fmaxf(tm0, fmaxf(s0, s1));
            tm1 = fmaxf(tm1, fmaxf(s2, s3));
        }
        tm0 = fmaxf(tm0, __shfl_xor_sync(0xffffffffu, tm0, 1));
        tm0 = fmaxf(tm0, __shfl_xor_sync(0xffffffffu, tm0, 2));
        tm1 = fmaxf(tm1, __shfl_xor_sync(0xffffffffu, tm1, 1));
        tm1 = fmaxf(tm1, __shfl_xor_sync(0xffffffffu, tm1, 2));

        const float mn0 = fmaxf(mrow0, tm0), mn1 = fmaxf(mrow1, tm1);
        const float a0 = __expf(mrow0 - mn0), a1 = __expf(mrow1 - mn1);

        float ps0 = 0.f, ps1 = 0.f;
#pragma unroll
        for (int ni = 0; ni < 16; ni++) {
            const float e0 = __expf(sacc[ni][0] - mn0);
            const float e1 = __expf(sacc[ni][1] - mn0);
            const float e2 = __expf(sacc[ni][2] - mn1);
            const float e3 = __expf(sacc[ni][3] - mn1);
            ps0 += e0 + e1; ps1 += e2 + e3;
            *(__half2*)(Ps + (rb + g    ) * FP_S + ni * 8 + t4 * 2) =
                __floats2half2_rn(e0, e1);
            *(__half2*)(Ps + (rb + g + 8) * FP_S + ni * 8 + t4 * 2) =
                __floats2half2_rn(e2, e3);
        }
        ps0 += __shfl_xor_sync(0xffffffffu, ps0, 1);
        ps0 += __shfl_xor_sync(0xffffffffu, ps0, 2);
        ps1 += __shfl_xor_sync(0xffffffffu, ps1, 1);
        ps1 += __shfl_xor_sync(0xffffffffu, ps1, 2);

        lrow0 = lrow0 * a0 + ps0;
        lrow1 = lrow1 * a1 + ps1;
        mrow0 = mn0; mrow1 = mn1;
#pragma unroll
        for (int ni = 0; ni < 8; ni++) {
            oacc[ni][0] *= a0; oacc[ni][1] *= a0;
            oacc[ni][2] *= a1; oacc[ni][3] *= a1;
        }
        __syncwarp();   // P rows are per-warp

        // O += P V  (fp16, 8 k-steps of 16; B from transposed Vt)
#pragma unroll
        for (int ks = 0; ks < 8; ks++) {
            const int k = ks * 16;
            uint32_t af[4];
            af[0] = *(const uint32_t*)(Ps + (rb + g    ) * FP_S + k + 2 * t4    );
            af[1] = *(const uint32_t*)(Ps + (rb + g + 8) * FP_S + k + 2 * t4    );
            af[2] = *(const uint32_t*)(Ps + (rb + g    ) * FP_S + k + 2 * t4 + 8);
            af[3] = *(const uint32_t*)(Ps + (rb + g + 8) * FP_S + k + 2 * t4 + 8);
#pragma unroll
            for (int ni = 0; ni < 8; ni++) {
                uint32_t bf[2];
                bf[0] = *(const uint32_t*)(Vt + (ni * 8 + g) * FVT_S + k + 2 * t4    );
                bf[1] = *(const uint32_t*)(Vt + (ni * 8 + g) * FVT_S + k + 2 * t4 + 8);
                mma_f16(oacc[ni], af, bf);
            }
        }
    }

    const float i0 = 1.f / lrow0, i1 = 1.f / lrow1;
    const int r0 = tileQ + rb + g, r1 = r0 + 8;
#pragma unroll
    for (int ni = 0; ni < 8; ni++) {
        const int d = ni * 8 + t4 * 2;
        *(__half2*)(H + (size_t)(b * LSEQ + r0) * D_MODEL + h * DH + d) =
            __floats2half2_rn(oacc[ni][0] * i0, oacc[ni][1] * i0);
        *(__half2*)(H + (size_t)(b * LSEQ + r1) * D_MODEL + h * DH + d) =
            __floats2half2_rn(oacc[ni][2] * i1, oacc[ni][3] * i1);
    }
}

// ---------------- weight transposes (convert to fp16 on store) ---------------
__global__ __launch_bounds__(256) void transpose_k(
    const float* __restrict__ in, __half* __restrict__ out, int K, int N)
{
    __shared__ float t[32][33];
    const int bn = blockIdx.x * 32, bk = blockIdx.y * 32;
    const int tx = threadIdx.x, ty = threadIdx.y;
#pragma unroll
    for (int i = ty; i < 32; i += 8)
        t[i][tx] = in[(size_t)(bk + i) * N + bn + tx];
    __syncthreads();
#pragma unroll
    for (int i = ty; i < 32; i += 8)
        out[(size_t)(bn + i) * K + bk + tx] = __float2half_rn(t[tx][i]);
}

__global__ __launch_bounds__(256) void transpose_k4(
    const float* __restrict__ i0, const float* __restrict__ i1,
    const float* __restrict__ i2, const float* __restrict__ i3,
    __half* __restrict__ o0, __half* __restrict__ o1,
    __half* __restrict__ o2, __half* __restrict__ o3)
{
    __shared__ float t[32][33];
    const float* in = (blockIdx.z == 0) ? i0 : (blockIdx.z == 1) ? i1 :
                      (blockIdx.z == 2) ? i2 : i3;
    __half* out = (blockIdx.z == 0) ? o0 : (blockIdx.z == 1) ? o1 :
                  (blockIdx.z == 2) ? o2 : o3;
    const int bn = blockIdx.x * 32, bk = blockIdx.y * 32;
    const int tx = threadIdx.x, ty = threadIdx.y;
#pragma unroll
    for (int i = ty; i < 32; i += 8)
        t[i][tx] = in[(size_t)(bk + i) * 1024 + bn + tx];
    __syncthreads();
#pragma unroll
    for (int i = ty; i < 32; i += 8)
        out[(size_t)(bn + i) * 1024 + bk + tx] = __float2half_rn(t[tx][i]);
}

// ---------------- half-copy (x -> fp16 twin) ---------------------------------
__global__ __launch_bounds__(256) void half_copy(
    const float* __restrict__ in, __half* __restrict__ out)
{
    const size_t i = ((size_t)blockIdx.x * 256 + threadIdx.x) * 4;
    float4 v = *(const float4*)(in + i);
    *(__half2*)(out + i)     = __floats2half2_rn(v.x, v.y);
    *(__half2*)(out + i + 2) = __floats2half2_rn(v.z, v.w);
}

// ---------------- layernorm (optional fp16 twin output) ----------------------
__global__ __launch_bounds__(256) void layernorm(
    const float* __restrict__ X, const float* __restrict__ g,
    const float* __restrict__ be, float* __restrict__ O,
    __half* __restrict__ Or)
{
    __shared__ float red[8];
    const int r = blockIdx.x;
    const int tid = threadIdx.x;
    const float4 v = *(const float4*)(X + (size_t)r * D_MODEL + tid * 4);

    float s = v.x + v.y + v.z + v.w;
#pragma unroll
    for (int o = 16; o > 0; o >>= 1) s += __shfl_xor_sync(0xffffffffu, s, o);
    if ((tid & 31) == 0) red[tid >> 5] = s;
    __syncthreads();
    s = 0.f;
#pragma unroll
    for (int i = 0; i < 8; i++) s += red[i];
    const float mu = s * (1.f / D_MODEL);
    __syncthreads();

    float dx = v.x - mu, dy = v.y - mu, dz = v.z - mu, dw = v.w - mu;
    float sq = dx * dx + dy * dy + dz * dz + dw * dw;
#pragma unroll
    for (int o = 16; o > 0; o >>= 1) sq += __shfl_xor_sync(0xffffffffu, sq, o);
    if ((tid & 31) == 0) red[tid >> 5] = sq;
    __syncthreads();
    sq = 0.f;
#pragma unroll
    for (int i = 0; i < 8; i++) sq += red[i];
    const float rs = rsqrtf(sq * (1.f / D_MODEL) + 1e-5f);

    const float4 gg = *(const float4*)(g + tid * 4);
    const float4 bb = *(const float4*)(be + tid * 4);
    float4 o;
    o.x = dx * rs * gg.x + bb.x;
    o.y = dy * rs * gg.y + bb.y;
    o.z = dz * rs * gg.z + bb.z;
    o.w = dw * rs * gg.w + bb.w;
    *(float4*)(O + (size_t)r * D_MODEL + tid * 4) = o;
    if (Or) {
        *(__half2*)(Or + (size_t)r * D_MODEL + tid * 4)     = __floats2half2_rn(o.x, o.y);
        *(__half2*)(Or + (size_t)r * D_MODEL + tid * 4 + 2) = __floats2half2_rn(o.z, o.w);
    }
}

// ---------------- launch -----------------------------------------------------
extern "C" void kernel_launch(void* const* d_in, const int* in_sizes, int n_in,
                              void* d_out, int out_size)
{
    const float* x   = (const float*)d_in[0];
    const int*   msk = (const int*)d_in[1];
    const float* Wq  = (const float*)d_in[2];
    const float* Wk  = (const float*)d_in[3];
    const float* Wv  = (const float*)d_in[4];
    const float* Wp  = (const float*)d_in[5];
    const float* bp  = (const float*)d_in[6];
    const float* W1  = (const float*)d_in[7];
    const float* b1  = (const float*)d_in[8];
    const float* W2  = (const float*)d_in[9];
    const float* b2  = (const float*)d_in[10];
    const float* g1  = (const float*)d_in[11];
    const float* be1 = (const float*)d_in[12];
    const float* g2  = (const float*)d_in[13];
    const float* be2 = (const float*)d_in[14];
    float* out = (float*)d_out;

    float *tmp, *h;
    __half *q, *k, *v, *hd, *hh, *xh, *ff, *wtqkv, *wtp, *wt1, *wt2;
    cudaGetSymbolAddress((void**)&q,     g_q);
    cudaGetSymbolAddress((void**)&k,     g_k);
    cudaGetSymbolAddress((void**)&v,     g_v);
    cudaGetSymbolAddress((void**)&hd,    g_heads);
    cudaGetSymbolAddress((void**)&tmp,   g_tmp);
    cudaGetSymbolAddress((void**)&h,     g_h);
    cudaGetSymbolAddress((void**)&hh,    g_hh);
    cudaGetSymbolAddress((void**)&xh,    g_xh);
    cudaGetSymbolAddress((void**)&ff,    g_ff);
    cudaGetSymbolAddress((void**)&wtqkv, g_wtqkv);
    cudaGetSymbolAddress((void**)&wtp,   g_wtp);
    cudaGetSymbolAddress((void**)&wt1,   g_wt1);
    cudaGetSymbolAddress((void**)&wt2,   g_wt2);

    static bool attr_done = false;
    if (!attr_done) {
        cudaFuncSetAttribute(gemm_mma<EPI_QKV>,
                             cudaFuncAttributeMaxDynamicSharedMemorySize, GM_SMEM_B);
        cudaFuncSetAttribute(gemm_mma<EPI_BIAS_RESID>,
                             cudaFuncAttributeMaxDynamicSharedMemorySize, GM_SMEM_B);
        cudaFuncSetAttribute(gemm_mma<EPI_BIAS_RELU>,
                             cudaFuncAttributeMaxDynamicSharedMemorySize, GM_SMEM_B);
        cudaFuncSetAttribute(flash_attn,
                             cudaFuncAttributeMaxDynamicSharedMemorySize, FA_SMEM_B);
        attr_done = true;
    }

    dim3 blk(256);
    dim3 tb(32, 8);

    transpose_k4<<<dim3(32, 32, 4), tb>>>(
        Wq, Wk, Wv, Wp,
        wtqkv + 0 * 1024 * 1024, wtqkv + 1 * 1024 * 1024,
        wtqkv + 2 * 1024 * 1024, wtp);
    transpose_k<<<dim3(128, 32), tb>>>(W1, wt1, D_MODEL, DFF);
    transpose_k<<<dim3(32, 128), tb>>>(W2, wt2, DFF, D_MODEL);
    half_copy<<<MROWS * D_MODEL / 1024, blk>>>(x, xh);

    // fused QKV projection (fp16 in/out), scatter to head layout
    gemm_mma<EPI_QKV><<<dim3(24, 32), blk, GM_SMEM_B>>>(
        xh, wtqkv, nullptr, nullptr, 3072, 1024, nullptr, nullptr, q, k, v);

    // fused attention (fp16 MMA, fp32 softmax)
    flash_attn<<<dim3(8, ZHEADS), blk, FA_SMEM_B>>>(q, k, v, msk, hd);

    // proj + bias + residual(x fp32), LN1 (h fp32 + hh fp16)
    gemm_mma<EPI_BIAS_RESID><<<dim3(8, 32), blk, GM_SMEM_B>>>(
        hd, wtp, tmp, nullptr, 1024, 1024, bp, x, nullptr, nullptr, nullptr);
    layernorm<<<MROWS, blk>>>(tmp, g1, be1, h, hh);

    // FF1 (ReLU -> fp16 ff), FF2 + bias + residual(h fp32), LN2
    gemm_mma<EPI_BIAS_RELU><<<dim3(32, 32), blk, GM_SMEM_B>>>(
        hh, wt1, nullptr, ff, 4096, 1024, b1, nullptr, nullptr, nullptr, nullptr);
    gemm_mma<EPI_BIAS_RESID><<<dim3(8, 32), blk, GM_SMEM_B>>>(
        ff, wt2, tmp, nullptr, 1024, 4096, b2, h, nullptr, nullptr, nullptr);
    layernorm<<<MROWS, blk>>>(tmp, g2, be2, out, nullptr);
}

// round 11
// speedup vs baseline: 2.3508x; 1.0715x over previous
#include <cuda_runtime.h>
#include <cuda_fp16.h>
#include <cstdint>
#include <math.h>

#define D_MODEL 1024
#define NH      16
#define DH      64
#define DFF     4096
#define BATCH   4
#define LSEQ    1024
#define MROWS   (BATCH*LSEQ)       // 4096
#define ZHEADS  (BATCH*NH)         // 64

// ---------------- scratch (device globals; no runtime allocation) ----------
__device__ __half g_q[(size_t)ZHEADS*LSEQ*DH];          // fp16 (b,h,l,d)
__device__ __half g_k[(size_t)ZHEADS*LSEQ*DH];
__device__ __half g_v[(size_t)ZHEADS*LSEQ*DH];
__device__ __half g_heads[(size_t)MROWS*D_MODEL];       // fp16 (flash epi)
__device__ float  g_tmp[(size_t)MROWS*D_MODEL];
__device__ float  g_h[(size_t)MROWS*D_MODEL];           // fp32 residual
__device__ __half g_hh[(size_t)MROWS*D_MODEL];          // fp16 twin of h
__device__ __half g_xh[(size_t)MROWS*D_MODEL];          // fp16 twin of x
__device__ __half g_ff[(size_t)MROWS*DFF];              // fp16 (FF1 epi)
__device__ __half g_wtqkv[(size_t)3*D_MODEL*D_MODEL];   // fp16, (N,K)
__device__ __half g_wtp[(size_t)D_MODEL*D_MODEL];
__device__ __half g_wt1[(size_t)DFF*D_MODEL];
__device__ __half g_wt2[(size_t)D_MODEL*DFF];

// ---------------- helpers ----------------------------------------------------
__device__ __forceinline__ uint32_t smem_u32(const void* p) {
    uint32_t a;
    asm("{ .reg .u64 t; cvta.to.shared.u64 t, %1; cvt.u32.u64 %0, t; }"
        : "=r"(a) : "l"(p));
    return a;
}
__device__ __forceinline__ void cp16(uint32_t s, const void* g) {
    asm volatile("cp.async.cg.shared.global [%0], [%1], 16;" :: "r"(s), "l"(g));
}
#define CP_COMMIT() asm volatile("cp.async.commit_group;" ::: "memory")
#define CP_WAIT1()  asm volatile("cp.async.wait_group 1;" ::: "memory")

__device__ __forceinline__ void mma_f16(float* d, const uint32_t* a,
                                        const uint32_t* b) {
    asm volatile(
        "mma.sync.aligned.m16n8k16.row.col.f32.f16.f16.f32 "
        "{%0,%1,%2,%3}, {%4,%5,%6,%7}, {%8,%9}, {%0,%1,%2,%3};"
        : "+f"(d[0]), "+f"(d[1]), "+f"(d[2]), "+f"(d[3])
        : "r"(a[0]), "r"(a[1]), "r"(a[2]), "r"(a[3]), "r"(b[0]), "r"(b[1]));
}
__device__ __forceinline__ void ldsm_x4(uint32_t* r, uint32_t addr) {
    asm volatile("ldmatrix.sync.aligned.m8n8.x4.shared.b16 {%0,%1,%2,%3}, [%4];"
        : "=r"(r[0]), "=r"(r[1]), "=r"(r[2]), "=r"(r[3]) : "r"(addr));
}
__device__ __forceinline__ void ldsm_x4_t(uint32_t* r, uint32_t addr) {
    asm volatile("ldmatrix.sync.aligned.m8n8.x4.trans.shared.b16 {%0,%1,%2,%3}, [%4];"
        : "=r"(r[0]), "=r"(r[1]), "=r"(r[2]), "=r"(r[3]) : "r"(addr));
}

// ---------------- fp16 mma GEMM: C = A[M,K] @ BT[N,K]^T ---------------------
enum { EPI_QKV = 0, EPI_BIAS_RESID = 1, EPI_BIAS_RELU = 2 };

#define GM_S      40
#define GM_TILE_H (128 * GM_S)
#define GM_BUF_H  (2 * GM_TILE_H)
#define GM_SMEM_B (3 * GM_BUF_H * 2)      // 61440 bytes

template<int EPI>
__global__ __launch_bounds__(256, 2) void gemm_mma(
    const __half* __restrict__ A, const __half* __restrict__ BT,
    float* __restrict__ Cf, __half* __restrict__ Ch, int N, int K,
    const float* __restrict__ bias, const float* __restrict__ resid,
    __half* __restrict__ qp, __half* __restrict__ kp, __half* __restrict__ vp)
{
    extern __shared__ __half smemh[];
    const uint32_t sb = smem_u32(smemh);

    const int tid  = threadIdx.x;
    const int wid  = tid >> 5;
    const int lane = tid & 31;
    const int g    = lane >> 2;
    const int t4   = lane & 3;
    const int wm   = wid >> 2;
    const int wn   = wid & 3;
    const int tileM = blockIdx.y * 128;
    const int tileN = blockIdx.x * 128;

    const int lr  = tid >> 2;
    const int lc8 = (tid & 3) * 8;

    float acc[4][4][4];
#pragma unroll
    for (int i = 0; i < 4; i++)
#pragma unroll
        for (int j = 0; j < 4; j++)
#pragma unroll
            for (int c = 0; c < 4; c++) acc[i][j][c] = 0.f;

    const int KT = K >> 5;

#pragma unroll
    for (int s = 0; s < 2; s++) {
        const int k0 = s << 5;
        const uint32_t sba = sb + (uint32_t)(s * GM_BUF_H) * 2;
#pragma unroll
        for (int i = 0; i < 2; i++) {
            const int r = lr + i * 64;
            cp16(sba + (r * GM_S + lc8) * 2,
                 A + (size_t)(tileM + r) * K + k0 + lc8);
            cp16(sba + (GM_TILE_H + r * GM_S + lc8) * 2,
                 BT + (size_t)(tileN + r) * K + k0 + lc8);
        }
        CP_COMMIT();
    }

    for (int kt = 0; kt < KT; kt++) {
        CP_WAIT1();
        __syncthreads();

        if (kt + 2 < KT) {
            const int k0 = (kt + 2) << 5;
            const uint32_t sba = sb + (uint32_t)(((kt + 2) % 3) * GM_BUF_H) * 2;
#pragma unroll
            for (int i = 0; i < 2; i++) {
                const int r = lr + i * 64;
                cp16(sba + (r * GM_S + lc8) * 2,
                     A + (size_t)(tileM + r) * K + k0 + lc8);
                cp16(sba + (GM_TILE_H + r * GM_S + lc8) * 2,
                     BT + (size_t)(tileN + r) * K + k0 + lc8);
            }
        }
        CP_COMMIT();

        const __half* As = smemh + (kt % 3) * GM_BUF_H;
        const __half* Bs = As + GM_TILE_H;
#pragma unroll
        for (int ks = 0; ks < 2; ks++) {
            const int k = ks * 16;
            uint32_t af[4][4], bf[4][2];
#pragma unroll
            for (int mi = 0; mi < 4; mi++) {
                const int rb = wm * 64 + mi * 16;
                af[mi][0] = *(const uint32_t*)(As + (rb + g    ) * GM_S + k + 2 * t4    );
                af[mi][1] = *(const uint32_t*)(As + (rb + g + 8) * GM_S + k + 2 * t4    );
                af[mi][2] = *(const uint32_t*)(As + (rb + g    ) * GM_S + k + 2 * t4 + 8);
                af[mi][3] = *(const uint32_t*)(As + (rb + g + 8) * GM_S + k + 2 * t4 + 8);
            }
#pragma unroll
            for (int ni = 0; ni < 4; ni++) {
                const int nb = wn * 32 + ni * 8;
                bf[ni][0] = *(const uint32_t*)(Bs + (nb + g) * GM_S + k + 2 * t4    );
                bf[ni][1] = *(const uint32_t*)(Bs + (nb + g) * GM_S + k + 2 * t4 + 8);
            }
#pragma unroll
            for (int mi = 0; mi < 4; mi++)
#pragma unroll
                for (int ni = 0; ni < 4; ni++)
                    mma_f16(acc[mi][ni], af[mi], bf[ni]);
        }
    }

#pragma unroll
    for (int mi = 0; mi < 4; mi++) {
#pragma unroll
        for (int half = 0; half < 2; half++) {
            const int m = tileM + wm * 64 + mi * 16 + g + half * 8;
#pragma unroll
            for (int ni = 0; ni < 4; ni++) {
                const int n = tileN + wn * 32 + ni * 8 + t4 * 2;
                float v0 = acc[mi][ni][half * 2 + 0];
                float v1 = acc[mi][ni][half * 2 + 1];
                if (EPI == EPI_QKV) {
                    const int b = m >> 10, l = m & 1023;
                    const int which = n >> 10, rem = n & 1023;
                    const int h = rem >> 6, d = rem & 63;
                    __half* dst = (which == 0) ? qp : (which == 1) ? kp : vp;
                    *(__half2*)(dst + ((size_t)((b * NH + h) * LSEQ + l)) * DH + d) =
                        __floats2half2_rn(v0, v1);
                } else {
                    const size_t idx = (size_t)m * N + n;
                    const float2 bb = *(const float2*)(bias + n);
                    v0 += bb.x; v1 += bb.y;
                    if (EPI == EPI_BIAS_RESID) {
                        const float2 rr = *(const float2*)(resid + idx);
                        v0 += rr.x; v1 += rr.y;
                        *(float2*)(Cf + idx) = make_float2(v0, v1);
                    } else {
                        v0 = fmaxf(v0, 0.f); v1 = fmaxf(v1, 0.f);
                        *(__half2*)(Ch + idx) = __floats2half2_rn(v0, v1);
                    }
                }
            }
        }
    }
}

// ---------------- fused flash attention (fp16 MMA + ldmatrix) ----------------
// Qs/Ks/Vs: [128][72] halves, natural (seq, d) layout. Ps: [128][136].
// V fragments via ldmatrix.trans (no transposed store needed).
#define FQ_S   72
#define FV_S   72
#define FP_S   136
#define FQ_OFF  0
#define FK_OFF  (FQ_OFF + 128 * FQ_S)          // 9216
#define FV_OFF  (FK_OFF + 128 * FQ_S)          // 18432
#define FP_OFF  (FV_OFF + 128 * FV_S)          // 27648
#define FM_OFF  (FP_OFF + 128 * FP_S)          // 45056 halves
#define FA_SMEM_B (FM_OFF * 2 + 128 * 4)       // 90624 bytes

__global__ __launch_bounds__(256, 2) void flash_attn(
    const __half* __restrict__ Qg, const __half* __restrict__ Kg,
    const __half* __restrict__ Vg, const int* __restrict__ mask,
    __half* __restrict__ H)
{
    extern __shared__ __half smh[];
    __half* Qs = smh + FQ_OFF;
    __half* Ks = smh + FK_OFF;
    __half* Vs = smh + FV_OFF;
    __half* Ps = smh + FP_OFF;
    int*    Ms = (int*)(smh + FM_OFF);
    const uint32_t sb = smem_u32(smh);

    const int z = blockIdx.y;
    const int b = z >> 4, h = z & 15;
    const __half* q  = Qg + (size_t)z * LSEQ * DH;
    const __half* kp = Kg + (size_t)z * LSEQ * DH;
    const __half* vp = Vg + (size_t)z * LSEQ * DH;
    const int* mb = mask + (size_t)b * LSEQ;
    const int tileQ = blockIdx.x * 128;

    const int tid  = threadIdx.x;
    const int wid  = tid >> 5;
    const int lane = tid & 31;
    const int g    = lane >> 2;
    const int t4   = lane & 3;
    const int rb   = wid * 16;
    const int j8   = lane >> 3;
    const int r8   = lane & 7;

    // per-lane ldmatrix base addresses (bytes)
    // A-frag (Q/P): mat j -> row rb + (j&1)*8 + r8, col (j>>1)*8
    const uint32_t qa = sb + (uint32_t)((FQ_OFF + (rb + (j8 & 1) * 8 + r8) * FQ_S
                                         + (j8 >> 1) * 8) << 1);
    const uint32_t pa = sb + (uint32_t)((FP_OFF + (rb + (j8 & 1) * 8 + r8) * FP_S
                                         + (j8 >> 1) * 8) << 1);
    // B-frag (K, non-trans): mat j -> row (j>>1)*8 + r8 (+ nb), col (j&1)*8 (+ k)
    const uint32_t ka = sb + (uint32_t)((FK_OFF + ((j8 >> 1) * 8 + r8) * FQ_S
                                         + (j8 & 1) * 8) << 1);
    // B-frag (V, trans): mat j -> key row (j&1)*8 + r8 (+ k), d col (j>>1)*8 (+ nb)
    const uint32_t va = sb + (uint32_t)((FV_OFF + ((j8 & 1) * 8 + r8) * FV_S
                                         + (j8 >> 1) * 8) << 1);

    // Q tile: 128 rows x 64 halves
#pragma unroll
    for (int i = 0; i < 4; i++) {
        const int idx = i * 256 + tid;
        const int r   = idx >> 3;
        const int c8  = (idx & 7) * 8;
        *(uint4*)(Qs + r * FQ_S + c8) =
            *(const uint4*)(q + (size_t)(tileQ + r) * DH + c8);
    }

    float mrow0 = -1e30f, mrow1 = -1e30f;
    float lrow0 = 0.f, lrow1 = 0.f;
    float oacc[8][4];
#pragma unroll
    for (int i = 0; i < 8; i++)
#pragma unroll
        for (int c = 0; c < 4; c++) oacc[i][c] = 0.f;

    for (int kt = 0; kt < 8; kt++) {
        const int k0 = kt * 128;
        __syncthreads();
        // K and V tiles, natural (seq, d) layout
#pragma unroll
        for (int i = 0; i < 4; i++) {
            const int idx = i * 256 + tid;
            const int r   = idx >> 3;
            const int c8  = (idx & 7) * 8;
            *(uint4*)(Ks + r * FQ_S + c8) =
                *(const uint4*)(kp + (size_t)(k0 + r) * DH + c8);
            *(uint4*)(Vs + r * FV_S + c8) =
                *(const uint4*)(vp + (size_t)(k0 + r) * DH + c8);
        }
        if (tid < 128) Ms[tid] = mb[k0 + tid];
        __syncthreads();

        // S = Q K^T  (4 k-steps of 16; ldmatrix fragments)
        float sacc[16][4];
#pragma unroll
        for (int ni = 0; ni < 16; ni++)
#pragma unroll
            for (int c = 0; c < 4; c++) sacc[ni][c] = 0.f;
#pragma unroll
        for (int ks = 0; ks < 4; ks++) {
            const int k = ks * 16;
            uint32_t af[4];
            ldsm_x4(af, qa + (k << 1));
#pragma unroll
            for (int ni2 = 0; ni2 < 8; ni2++) {
                uint32_t bq[4];
                ldsm_x4(bq, ka + (uint32_t)(ni2 * (16 * FQ_S * 2)) + (k << 1));
                mma_f16(sacc[2 * ni2    ], af, bq);
                mma_f16(sacc[2 * ni2 + 1], af, bq + 2);
            }
        }

        float tm0 = -1e30f, tm1 = -1e30f;
#pragma unroll
        for (int ni = 0; ni < 16; ni++) {
            const int c0 = ni * 8 + t4 * 2, c1 = c0 + 1;
            const bool m0 = (Ms[c0] == 0), m1 = (Ms[c1] == 0);
            float s0 = sacc[ni][0] * 0.125f; if (m0) s0 = -1e10f;
            float s1 = sacc[ni][1] * 0.125f; if (m1) s1 = -1e10f;
            float s2 = sacc[ni][2] * 0.125f; if (m0) s2 = -1e10f;
            float s3 = sacc[ni][3] * 0.125f; if (m1) s3 = -1e10f;
            sacc[ni][0] = s0; sacc[ni][1] = s1; sacc[ni][2] = s2; sacc[ni][3] = s3;
            tm0 = fmaxf(tm0, fmaxf(s0, s1));
            tm1 = fmaxf(tm1, fmaxf(s2, s3));
        }
        tm0 = fmaxf(tm0, __shfl_xor_sync(0xffffffffu, tm0, 1));
        tm0 = fmaxf(tm0, __shfl_xor_sync(0xffffffffu, tm0, 2));
        tm1 = fmaxf(tm1, __shfl_xor_sync(0xffffffffu, tm1, 1));
        tm1 = fmaxf(tm1, __shfl_xor_sync(0xffffffffu, tm1, 2));

        const float mn0 = fmaxf(mrow0, tm0), mn1 = fmaxf(mrow1, tm1);
        const float a0 = __expf(mrow0 - mn0), a1 = __expf(mrow1 - mn1);

        float ps0 = 0.f, ps1 = 0.f;
#pragma unroll
        for (int ni = 0; ni < 16; ni++) {
            const float e0 = __expf(sacc[ni][0] - mn0);
            const float e1 = __expf(sacc[ni][1] - mn0);
            const float e2 = __expf(sacc[ni][2] - mn1);
            const float e3 = __expf(sacc[ni][3] - mn1);
            ps0 += e0 + e1; ps1 += e2 + e3;
            *(__half2*)(Ps + (rb + g    ) * FP_S + ni * 8 + t4 * 2) =
                __floats2half2_rn(e0, e1);
            *(__half2*)(Ps + (rb + g + 8) * FP_S + ni * 8 + t4 * 2) =
                __floats2half2_rn(e2, e3);
        }
        ps0 += __shfl_xor_sync(0xffffffffu, ps0, 1);
        ps0 += __shfl_xor_sync(0xffffffffu, ps0, 2);
        ps1 += __shfl_xor_sync(0xffffffffu, ps1, 1);
        ps1 += __shfl_xor_sync(0xffffffffu, ps1, 2);

        lrow0 = lrow0 * a0 + ps0;
        lrow1 = lrow1 * a1 + ps1;
        mrow0 = mn0; mrow1 = mn1;
#pragma unroll
        for (int ni = 0; ni < 8; ni++) {
            oacc[ni][0] *= a0; oacc[ni][1] *= a0;
            oacc[ni][2] *= a1; oacc[ni][3] *= a1;
        }
        __syncwarp();   // P rows are per-warp

        // O += P V  (8 k-steps of 16; V B-fragments via ldmatrix.trans)
#pragma unroll
        for (int ks = 0; ks < 8; ks++) {
            const int k = ks * 16;
            uint32_t af[4];
            ldsm_x4(af, pa + (k << 1));
#pragma unroll
            for (int ni2 = 0; ni2 < 4; ni2++) {
                uint32_t bv[4];
                ldsm_x4_t(bv, va + (uint32_t)(k * (FV_S * 2)) + (uint32_t)(ni2 * 32));
                mma_f16(oacc[2 * ni2    ], af, bv);
                mma_f16(oacc[2 * ni2 + 1], af, bv + 2);
            }
        }
    }

    const float i0 = 1.f / lrow0, i1 = 1.f / lrow1;
    const int r0 = tileQ + rb + g, r1 = r0 + 8;
#pragma unroll
    for (int ni = 0; ni < 8; ni++) {
        const int d = ni * 8 + t4 * 2;
        *(__half2*)(H + (size_t)(b * LSEQ + r0) * D_MODEL + h * DH + d) =
            __floats2half2_rn(oacc[ni][0] * i0, oacc[ni][1] * i0);
        *(__half2*)(H + (size_t)(b * LSEQ + r1) * D_MODEL + h * DH + d) =
            __floats2half2_rn(oacc[ni][2] * i1, oacc[ni][3] * i1);
    }
}

// ---------------- weight transposes (convert to fp16 on store) ---------------
__global__ __launch_bounds__(256) void transpose_k(
    const float* __restrict__ in, __half* __restrict__ out, int K, int N)
{
    __shared__ float t[32][33];
    const int bn = blockIdx.x * 32, bk = blockIdx.y * 32;
    const int tx = threadIdx.x, ty = threadIdx.y;
#pragma unroll
    for (int i = ty; i < 32; i += 8)
        t[i][tx] = in[(size_t)(bk + i) * N + bn + tx];
    __syncthreads();
#pragma unroll
    for (int i = ty; i < 32; i += 8)
        out[(size_t)(bn + i) * K + bk + tx] = __float2half_rn(t[tx][i]);
}

__global__ __launch_bounds__(256) void transpose_k4(
    const float* __restrict__ i0, const float* __restrict__ i1,
    const float* __restrict__ i2, const float* __restrict__ i3,
    __half* __restrict__ o0, __half* __restrict__ o1,
    __half* __restrict__ o2, __half* __restrict__ o3)
{
    __shared__ float t[32][33];
    const float* in = (blockIdx.z == 0) ? i0 : (blockIdx.z == 1) ? i1 :
                      (blockIdx.z == 2) ? i2 : i3;
    __half* out = (blockIdx.z == 0) ? o0 : (blockIdx.z == 1) ? o1 :
                  (blockIdx.z == 2) ? o2 : o3;
    const int bn = blockIdx.x * 32, bk = blockIdx.y * 32;
    const int tx = threadIdx.x, ty = threadIdx.y;
#pragma unroll
    for (int i = ty; i < 32; i += 8)
        t[i][tx] = in[(size_t)(bk + i) * 1024 + bn + tx];
    __syncthreads();
#pragma unroll
    for (int i = ty; i < 32; i += 8)
        out[(size_t)(bn + i) * 1024 + bk + tx] = __float2half_rn(t[tx][i]);
}

// ---------------- half-copy (x -> fp16 twin) ---------------------------------
__global__ __launch_bounds__(256) void half_copy(
    const float* __restrict__ in, __half* __restrict__ out)
{
    const size_t i = ((size_t)blockIdx.x * 256 + threadIdx.x) * 4;
    float4 v = *(const float4*)(in + i);
    *(__half2*)(out + i)     = __floats2half2_rn(v.x, v.y);
    *(__half2*)(out + i + 2) = __floats2half2_rn(v.z, v.w);
}

// ---------------- layernorm (optional fp16 twin output) ----------------------
__global__ __launch_bounds__(256) void layernorm(
    const float* __restrict__ X, const float* __restrict__ g,
    const float* __restrict__ be, float* __restrict__ O,
    __half* __restrict__ Or)
{
    __shared__ float red[8];
    const int r = blockIdx.x;
    const int tid = threadIdx.x;
    const float4 v = *(const float4*)(X + (size_t)r * D_MODEL + tid * 4);

    float s = v.x + v.y + v.z + v.w;
#pragma unroll
    for (int o = 16; o > 0; o >>= 1) s += __shfl_xor_sync(0xffffffffu, s, o);
    if ((tid & 31) == 0) red[tid >> 5] = s;
    __syncthreads();
    s = 0.f;
#pragma unroll
    for (int i = 0; i < 8; i++) s += red[i];
    const float mu = s * (1.f / D_MODEL);
    __syncthreads();

    float dx = v.x - mu, dy = v.y - mu, dz = v.z - mu, dw = v.w - mu;
    float sq = dx * dx + dy * dy + dz * dz + dw * dw;
#pragma unroll
    for (int o = 16; o > 0; o >>= 1) sq += __shfl_xor_sync(0xffffffffu, sq, o);
    if ((tid & 31) == 0) red[tid >> 5] = sq;
    __syncthreads();
    sq = 0.f;
#pragma unroll
    for (int i = 0; i < 8; i++) sq += red[i];
    const float rs = rsqrtf(sq * (1.f / D_MODEL) + 1e-5f);

    const float4 gg = *(const float4*)(g + tid * 4);
    const float4 bb = *(const float4*)(be + tid * 4);
    float4 o;
    o.x = dx * rs * gg.x + bb.x;
    o.y = dy * rs * gg.y + bb.y;
    o.z = dz * rs * gg.z + bb.z;
    o.w = dw * rs * gg.w + bb.w;
    *(float4*)(O + (size_t)r * D_MODEL + tid * 4) = o;
    if (Or) {
        *(__half2*)(Or + (size_t)r * D_MODEL + tid * 4)     = __floats2half2_rn(o.x, o.y);
        *(__half2*)(Or + (size_t)r * D_MODEL + tid * 4 + 2) = __floats2half2_rn(o.z, o.w);
    }
}

// ---------------- launch -----------------------------------------------------
extern "C" void kernel_launch(void* const* d_in, const int* in_sizes, int n_in,
                              void* d_out, int out_size)
{
    const float* x   = (const float*)d_in[0];
    const int*   msk = (const int*)d_in[1];
    const float* Wq  = (const float*)d_in[2];
    const float* Wk  = (const float*)d_in[3];
    const float* Wv  = (const float*)d_in[4];
    const float* Wp  = (const float*)d_in[5];
    const float* bp  = (const float*)d_in[6];
    const float* W1  = (const float*)d_in[7];
    const float* b1  = (const float*)d_in[8];
    const float* W2  = (const float*)d_in[9];
    const float* b2  = (const float*)d_in[10];
    const float* g1  = (const float*)d_in[11];
    const float* be1 = (const float*)d_in[12];
    const float* g2  = (const float*)d_in[13];
    const float* be2 = (const float*)d_in[14];
    float* out = (float*)d_out;

    float *tmp, *h;
    __half *q, *k, *v, *hd, *hh, *xh, *ff, *wtqkv, *wtp, *wt1, *wt2;
    cudaGetSymbolAddress((void**)&q,     g_q);
    cudaGetSymbolAddress((void**)&k,     g_k);
    cudaGetSymbolAddress((void**)&v,     g_v);
    cudaGetSymbolAddress((void**)&hd,    g_heads);
    cudaGetSymbolAddress((void**)&tmp,   g_tmp);
    cudaGetSymbolAddress((void**)&h,     g_h);
    cudaGetSymbolAddress((void**)&hh,    g_hh);
    cudaGetSymbolAddress((void**)&xh,    g_xh);
    cudaGetSymbolAddress((void**)&ff,    g_ff);
    cudaGetSymbolAddress((void**)&wtqkv, g_wtqkv);
    cudaGetSymbolAddress((void**)&wtp,   g_wtp);
    cudaGetSymbolAddress((void**)&wt1,   g_wt1);
    cudaGetSymbolAddress((void**)&wt2,   g_wt2);

    static bool attr_done = false;
    if (!attr_done) {
        cudaFuncSetAttribute(gemm_mma<EPI_QKV>,
                             cudaFuncAttributeMaxDynamicSharedMemorySize, GM_SMEM_B);
        cudaFuncSetAttribute(gemm_mma<EPI_BIAS_RESID>,
                             cudaFuncAttributeMaxDynamicSharedMemorySize, GM_SMEM_B);
        cudaFuncSetAttribute(gemm_mma<EPI_BIAS_RELU>,
                             cudaFuncAttributeMaxDynamicSharedMemorySize, GM_SMEM_B);
        cudaFuncSetAttribute(flash_attn,
                             cudaFuncAttributeMaxDynamicSharedMemorySize, FA_SMEM_B);
        attr_done = true;
    }

    dim3 blk(256);
    dim3 tb(32, 8);

    transpose_k4<<<dim3(32, 32, 4), tb>>>(
        Wq, Wk, Wv, Wp,
        wtqkv + 0 * 1024 * 1024, wtqkv + 1 * 1024 * 1024,
        wtqkv + 2 * 1024 * 1024, wtp);
    transpose_k<<<dim3(128, 32), tb>>>(W1, wt1, D_MODEL, DFF);
    transpose_k<<<dim3(32, 128), tb>>>(W2, wt2, DFF, D_MODEL);
    half_copy<<<MROWS * D_MODEL / 1024, blk>>>(x, xh);

    // fused QKV projection (fp16 in/out), scatter to head layout
    gemm_mma<EPI_QKV><<<dim3(24, 32), blk, GM_SMEM_B>>>(
        xh, wtqkv, nullptr, nullptr, 3072, 1024, nullptr, nullptr, q, k, v);

    // fused attention (fp16 MMA + ldmatrix, fp32 softmax)
    flash_attn<<<dim3(8, ZHEADS), blk, FA_SMEM_B>>>(q, k, v, msk, hd);

    // proj + bias + residual(x fp32), LN1 (h fp32 + hh fp16)
    gemm_mma<EPI_BIAS_RESID><<<dim3(8, 32), blk, GM_SMEM_B>>>(
        hd, wtp, tmp, nullptr, 1024, 1024, bp, x, nullptr, nullptr, nullptr);
    layernorm<<<MROWS, blk>>>(tmp, g1, be1, h, hh);

    // FF1 (ReLU -> fp16 ff), FF2 + bias + residual(h fp32), LN2
    gemm_mma<EPI_BIAS_RELU><<<dim3(32, 32), blk, GM_SMEM_B>>>(
        hh, wt1, nullptr, ff, 4096, 1024, b1, nullptr, nullptr, nullptr, nullptr);
    gemm_mma<EPI_BIAS_RESID><<<dim3(8, 32), blk, GM_SMEM_B>>>(
        ff, wt2, tmp, nullptr, 1024, 4096, b2, h, nullptr, nullptr, nullptr);
    layernorm<<<MROWS, blk>>>(tmp, g2, be2, out, nullptr);
}

// round 12
// speedup vs baseline: 2.6234x; 1.1159x over previous
#include <cuda_runtime.h>
#include <cuda_fp16.h>
#include <cstdint>
#include <math.h>

#define D_MODEL 1024
#define NH      16
#define DH      64
#define DFF     4096
#define BATCH   4
#define LSEQ    1024
#define MROWS   (BATCH*LSEQ)       // 4096
#define ZHEADS  (BATCH*NH)         // 64

// ---------------- scratch (device globals; no runtime allocation) ----------
__device__ __half g_q[(size_t)ZHEADS*LSEQ*DH];          // fp16 (b,h,l,d)
__device__ __half g_k[(size_t)ZHEADS*LSEQ*DH];
__device__ __half g_v[(size_t)ZHEADS*LSEQ*DH];
__device__ __half g_heads[(size_t)MROWS*D_MODEL];       // fp16 (flash epi)
__device__ float  g_tmp[(size_t)MROWS*D_MODEL];
__device__ float  g_h[(size_t)MROWS*D_MODEL];           // fp32 residual
__device__ __half g_hh[(size_t)MROWS*D_MODEL];          // fp16 twin of h
__device__ __half g_xh[(size_t)MROWS*D_MODEL];          // fp16 twin of x
__device__ __half g_ff[(size_t)MROWS*DFF];              // fp16 (FF1 epi)
__device__ __half g_wtqkv[(size_t)3*D_MODEL*D_MODEL];   // fp16, (N,K)
__device__ __half g_wtp[(size_t)D_MODEL*D_MODEL];
__device__ __half g_wt1[(size_t)DFF*D_MODEL];
__device__ __half g_wt2[(size_t)D_MODEL*DFF];

// ---------------- helpers ----------------------------------------------------
__device__ __forceinline__ uint32_t smem_u32(const void* p) {
    uint32_t a;
    asm("{ .reg .u64 t; cvta.to.shared.u64 t, %1; cvt.u32.u64 %0, t; }"
        : "=r"(a) : "l"(p));
    return a;
}
__device__ __forceinline__ void cp16(uint32_t s, const void* g) {
    asm volatile("cp.async.cg.shared.global [%0], [%1], 16;" :: "r"(s), "l"(g));
}
#define CP_COMMIT() asm volatile("cp.async.commit_group;" ::: "memory")
#define CP_WAIT1()  asm volatile("cp.async.wait_group 1;" ::: "memory")

__device__ __forceinline__ void mma_f16(float* d, const uint32_t* a,
                                        const uint32_t* b) {
    asm volatile(
        "mma.sync.aligned.m16n8k16.row.col.f32.f16.f16.f32 "
        "{%0,%1,%2,%3}, {%4,%5,%6,%7}, {%8,%9}, {%0,%1,%2,%3};"
        : "+f"(d[0]), "+f"(d[1]), "+f"(d[2]), "+f"(d[3])
        : "r"(a[0]), "r"(a[1]), "r"(a[2]), "r"(a[3]), "r"(b[0]), "r"(b[1]));
}
__device__ __forceinline__ void ldsm_x4(uint32_t* r, uint32_t addr) {
    asm volatile("ldmatrix.sync.aligned.m8n8.x4.shared.b16 {%0,%1,%2,%3}, [%4];"
        : "=r"(r[0]), "=r"(r[1]), "=r"(r[2]), "=r"(r[3]) : "r"(addr));
}
__device__ __forceinline__ void ldsm_x4_t(uint32_t* r, uint32_t addr) {
    asm volatile("ldmatrix.sync.aligned.m8n8.x4.trans.shared.b16 {%0,%1,%2,%3}, [%4];"
        : "=r"(r[0]), "=r"(r[1]), "=r"(r[2]), "=r"(r[3]) : "r"(addr));
}

// ---------------- fp16 mma GEMM: C = A[M,K] @ BT[N,K]^T ---------------------
// 128x128 CTA tile, 8 warps (2x4), warp tile 64x32, K-chunk 32.
// 3-stage cp.async pipeline; fragments via ldmatrix.x4 (conflict-free @ GM_S=40).
enum { EPI_QKV = 0, EPI_BIAS_RESID = 1, EPI_BIAS_RELU = 2 };

#define GM_S      40
#define GM_TILE_H (128 * GM_S)
#define GM_BUF_H  (2 * GM_TILE_H)
#define GM_SMEM_B (3 * GM_BUF_H * 2)      // 61440 bytes

template<int EPI>
__global__ __launch_bounds__(256, 2) void gemm_mma(
    const __half* __restrict__ A, const __half* __restrict__ BT,
    float* __restrict__ Cf, __half* __restrict__ Ch, int N, int K,
    const float* __restrict__ bias, const float* __restrict__ resid,
    __half* __restrict__ qp, __half* __restrict__ kp, __half* __restrict__ vp)
{
    extern __shared__ __half smemh[];
    const uint32_t sb = smem_u32(smemh);

    const int tid  = threadIdx.x;
    const int wid  = tid >> 5;
    const int lane = tid & 31;
    const int g    = lane >> 2;
    const int t4   = lane & 3;
    const int wm   = wid >> 2;
    const int wn   = wid & 3;
    const int tileM = blockIdx.y * 128;
    const int tileN = blockIdx.x * 128;

    const int lr  = tid >> 2;
    const int lc8 = (tid & 3) * 8;
    const int j8  = lane >> 3;
    const int r8  = lane & 7;

    // per-lane ldmatrix base offsets (bytes, within one stage buffer)
    // A: mat j -> row wm*64 + (j&1)*8 + r8, col (j>>1)*8   (+ mi*16 rows, + k cols)
    const uint32_t a_l = ((uint32_t)((wm * 64 + (j8 & 1) * 8 + r8) * GM_S
                                     + (j8 >> 1) * 8)) << 1;
    // B: mat j -> row wn*32 + (j>>1)*8 + r8, col (j&1)*8   (+ nb2*16 rows, + k cols)
    const uint32_t b_l = ((uint32_t)(GM_TILE_H + (wn * 32 + (j8 >> 1) * 8 + r8) * GM_S
                                     + (j8 & 1) * 8)) << 1;

    float acc[4][4][4];
#pragma unroll
    for (int i = 0; i < 4; i++)
#pragma unroll
        for (int j = 0; j < 4; j++)
#pragma unroll
            for (int c = 0; c < 4; c++) acc[i][j][c] = 0.f;

    const int KT = K >> 5;

#pragma unroll
    for (int s = 0; s < 2; s++) {
        const int k0 = s << 5;
        const uint32_t sba = sb + (uint32_t)(s * GM_BUF_H) * 2;
#pragma unroll
        for (int i = 0; i < 2; i++) {
            const int r = lr + i * 64;
            cp16(sba + (r * GM_S + lc8) * 2,
                 A + (size_t)(tileM + r) * K + k0 + lc8);
            cp16(sba + (GM_TILE_H + r * GM_S + lc8) * 2,
                 BT + (size_t)(tileN + r) * K + k0 + lc8);
        }
        CP_COMMIT();
    }

    for (int kt = 0; kt < KT; kt++) {
        CP_WAIT1();
        __syncthreads();

        if (kt + 2 < KT) {
            const int k0 = (kt + 2) << 5;
            const uint32_t sba = sb + (uint32_t)(((kt + 2) % 3) * GM_BUF_H) * 2;
#pragma unroll
            for (int i = 0; i < 2; i++) {
                const int r = lr + i * 64;
                cp16(sba + (r * GM_S + lc8) * 2,
                     A + (size_t)(tileM + r) * K + k0 + lc8);
                cp16(sba + (GM_TILE_H + r * GM_S + lc8) * 2,
                     BT + (size_t)(tileN + r) * K + k0 + lc8);
            }
        }
        CP_COMMIT();

        const uint32_t buf = sb + (uint32_t)((kt % 3) * GM_BUF_H) * 2;
#pragma unroll
        for (int ks = 0; ks < 2; ks++) {
            const uint32_t kB = (uint32_t)(ks * 16) << 1;   // byte offset of k cols
            uint32_t af[4][4], bq[2][4];
#pragma unroll
            for (int mi = 0; mi < 4; mi++)
                ldsm_x4(af[mi], buf + a_l + ((uint32_t)(mi * 16 * GM_S) << 1) + kB);
#pragma unroll
            for (int nb2 = 0; nb2 < 2; nb2++)
                ldsm_x4(bq[nb2], buf + b_l + ((uint32_t)(nb2 * 16 * GM_S) << 1) + kB);
#pragma unroll
            for (int mi = 0; mi < 4; mi++) {
#pragma unroll
                for (int nb2 = 0; nb2 < 2; nb2++) {
                    mma_f16(acc[mi][2 * nb2    ], af[mi], bq[nb2]);
                    mma_f16(acc[mi][2 * nb2 + 1], af[mi], bq[nb2] + 2);
                }
            }
        }
    }

#pragma unroll
    for (int mi = 0; mi < 4; mi++) {
#pragma unroll
        for (int half = 0; half < 2; half++) {
            const int m = tileM + wm * 64 + mi * 16 + g + half * 8;
#pragma unroll
            for (int ni = 0; ni < 4; ni++) {
                const int n = tileN + wn * 32 + ni * 8 + t4 * 2;
                float v0 = acc[mi][ni][half * 2 + 0];
                float v1 = acc[mi][ni][half * 2 + 1];
                if (EPI == EPI_QKV) {
                    const int b = m >> 10, l = m & 1023;
                    const int which = n >> 10, rem = n & 1023;
                    const int h = rem >> 6, d = rem & 63;
                    __half* dst = (which == 0) ? qp : (which == 1) ? kp : vp;
                    *(__half2*)(dst + ((size_t)((b * NH + h) * LSEQ + l)) * DH + d) =
                        __floats2half2_rn(v0, v1);
                } else {
                    const size_t idx = (size_t)m * N + n;
                    const float2 bb = *(const float2*)(bias + n);
                    v0 += bb.x; v1 += bb.y;
                    if (EPI == EPI_BIAS_RESID) {
                        const float2 rr = *(const float2*)(resid + idx);
                        v0 += rr.x; v1 += rr.y;
                        *(float2*)(Cf + idx) = make_float2(v0, v1);
                    } else {
                        v0 = fmaxf(v0, 0.f); v1 = fmaxf(v1, 0.f);
                        *(__half2*)(Ch + idx) = __floats2half2_rn(v0, v1);
                    }
                }
            }
        }
    }
}

// ---------------- fused flash attention (fp16 MMA + ldmatrix) ----------------
#define FQ_S   72
#define FV_S   72
#define FP_S   136
#define FQ_OFF  0
#define FK_OFF  (FQ_OFF + 128 * FQ_S)          // 9216
#define FV_OFF  (FK_OFF + 128 * FQ_S)          // 18432
#define FP_OFF  (FV_OFF + 128 * FV_S)          // 27648
#define FM_OFF  (FP_OFF + 128 * FP_S)          // 45056 halves
#define FA_SMEM_B (FM_OFF * 2 + 128 * 4)       // 90624 bytes

__global__ __launch_bounds__(256, 2) void flash_attn(
    const __half* __restrict__ Qg, const __half* __restrict__ Kg,
    const __half* __restrict__ Vg, const int* __restrict__ mask,
    __half* __restrict__ H)
{
    extern __shared__ __half smh[];
    __half* Qs = smh + FQ_OFF;
    __half* Ks = smh + FK_OFF;
    __half* Vs = smh + FV_OFF;
    __half* Ps = smh + FP_OFF;
    int*    Ms = (int*)(smh + FM_OFF);
    const uint32_t sb = smem_u32(smh);

    const int z = blockIdx.y;
    const int b = z >> 4, h = z & 15;
    const __half* q  = Qg + (size_t)z * LSEQ * DH;
    const __half* kp = Kg + (size_t)z * LSEQ * DH;
    const __half* vp = Vg + (size_t)z * LSEQ * DH;
    const int* mb = mask + (size_t)b * LSEQ;
    const int tileQ = blockIdx.x * 128;

    const int tid  = threadIdx.x;
    const int wid  = tid >> 5;
    const int lane = tid & 31;
    const int g    = lane >> 2;
    const int t4   = lane & 3;
    const int rb   = wid * 16;
    const int j8   = lane >> 3;
    const int r8   = lane & 7;

    const uint32_t qa = sb + (uint32_t)((FQ_OFF + (rb + (j8 & 1) * 8 + r8) * FQ_S
                                         + (j8 >> 1) * 8) << 1);
    const uint32_t pa = sb + (uint32_t)((FP_OFF + (rb + (j8 & 1) * 8 + r8) * FP_S
                                         + (j8 >> 1) * 8) << 1);
    const uint32_t ka = sb + (uint32_t)((FK_OFF + ((j8 >> 1) * 8 + r8) * FQ_S
                                         + (j8 & 1) * 8) << 1);
    const uint32_t va = sb + (uint32_t)((FV_OFF + ((j8 & 1) * 8 + r8) * FV_S
                                         + (j8 >> 1) * 8) << 1);

#pragma unroll
    for (int i = 0; i < 4; i++) {
        const int idx = i * 256 + tid;
        const int r   = idx >> 3;
        const int c8  = (idx & 7) * 8;
        *(uint4*)(Qs + r * FQ_S + c8) =
            *(const uint4*)(q + (size_t)(tileQ + r) * DH + c8);
    }

    float mrow0 = -1e30f, mrow1 = -1e30f;
    float lrow0 = 0.f, lrow1 = 0.f;
    float oacc[8][4];
#pragma unroll
    for (int i = 0; i < 8; i++)
#pragma unroll
        for (int c = 0; c < 4; c++) oacc[i][c] = 0.f;

    for (int kt = 0; kt < 8; kt++) {
        const int k0 = kt * 128;
        __syncthreads();
#pragma unroll
        for (int i = 0; i < 4; i++) {
            const int idx = i * 256 + tid;
            const int r   = idx >> 3;
            const int c8  = (idx & 7) * 8;
            *(uint4*)(Ks + r * FQ_S + c8) =
                *(const uint4*)(kp + (size_t)(k0 + r) * DH + c8);
            *(uint4*)(Vs + r * FV_S + c8) =
                *(const uint4*)(vp + (size_t)(k0 + r) * DH + c8);
        }
        if (tid < 128) Ms[tid] = mb[k0 + tid];
        __syncthreads();

        float sacc[16][4];
#pragma unroll
        for (int ni = 0; ni < 16; ni++)
#pragma unroll
            for (int c = 0; c < 4; c++) sacc[ni][c] = 0.f;
#pragma unroll
        for (int ks = 0; ks < 4; ks++) {
            const int k = ks * 16;
            uint32_t af[4];
            ldsm_x4(af, qa + (k << 1));
#pragma unroll
            for (int ni2 = 0; ni2 < 8; ni2++) {
                uint32_t bq[4];
                ldsm_x4(bq, ka + (uint32_t)(ni2 * (16 * FQ_S * 2)) + (k << 1));
                mma_f16(sacc[2 * ni2    ], af, bq);
                mma_f16(sacc[2 * ni2 + 1], af, bq + 2);
            }
        }

        float tm0 = -1e30f, tm1 = -1e30f;
#pragma unroll
        for (int ni = 0; ni < 16; ni++) {
            const int c0 = ni * 8 + t4 * 2, c1 = c0 + 1;
            const bool m0 = (Ms[c0] == 0), m1 = (Ms[c1] == 0);
            float s0 = sacc[ni][0] * 0.125f; if (m0) s0 = -1e10f;
            float s1 = sacc[ni][1] * 0.125f; if (m1) s1 = -1e10f;
            float s2 = sacc[ni][2] * 0.125f; if (m0) s2 = -1e10f;
            float s3 = sacc[ni][3] * 0.125f; if (m1) s3 = -1e10f;
            sacc[ni][0] = s0; sacc[ni][1] = s1; sacc[ni][2] = s2; sacc[ni][3] = s3;
            tm0 = fmaxf(tm0, fmaxf(s0, s1));
            tm1 = fmaxf(tm1, fmaxf(s2, s3));
        }
        tm0 = fmaxf(tm0, __shfl_xor_sync(0xffffffffu, tm0, 1));
        tm0 = fmaxf(tm0, __shfl_xor_sync(0xffffffffu, tm0, 2));
        tm1 = fmaxf(tm1, __shfl_xor_sync(0xffffffffu, tm1, 1));
        tm1 = fmaxf(tm1, __shfl_xor_sync(0xffffffffu, tm1, 2));

        const float mn0 = fmaxf(mrow0, tm0), mn1 = fmaxf(mrow1, tm1);
        const float a0 = __expf(mrow0 - mn0), a1 = __expf(mrow1 - mn1);

        float ps0 = 0.f, ps1 = 0.f;
#pragma unroll
        for (int ni = 0; ni < 16; ni++) {
            const float e0 = __expf(sacc[ni][0] - mn0);
            const float e1 = __expf(sacc[ni][1] - mn0);
            const float e2 = __expf(sacc[ni][2] - mn1);
            const float e3 = __expf(sacc[ni][3] - mn1);
            ps0 += e0 + e1; ps1 += e2 + e3;
            *(__half2*)(Ps + (rb + g    ) * FP_S + ni * 8 + t4 * 2) =
                __floats2half2_rn(e0, e1);
            *(__half2*)(Ps + (rb + g + 8) * FP_S + ni * 8 + t4 * 2) =
                __floats2half2_rn(e2, e3);
        }
        ps0 += __shfl_xor_sync(0xffffffffu, ps0, 1);
        ps0 += __shfl_xor_sync(0xffffffffu, ps0, 2);
        ps1 += __shfl_xor_sync(0xffffffffu, ps1, 1);
        ps1 += __shfl_xor_sync(0xffffffffu, ps1, 2);

        lrow0 = lrow0 * a0 + ps0;
        lrow1 = lrow1 * a1 + ps1;
        mrow0 = mn0; mrow1 = mn1;
#pragma unroll
        for (int ni = 0; ni < 8; ni++) {
            oacc[ni][0] *= a0; oacc[ni][1] *= a0;
            oacc[ni][2] *= a1; oacc[ni][3] *= a1;
        }
        __syncwarp();

#pragma unroll
        for (int ks = 0; ks < 8; ks++) {
            const int k = ks * 16;
            uint32_t af[4];
            ldsm_x4(af, pa + (k << 1));
#pragma unroll
            for (int ni2 = 0; ni2 < 4; ni2++) {
                uint32_t bv[4];
                ldsm_x4_t(bv, va + (uint32_t)(k * (FV_S * 2)) + (uint32_t)(ni2 * 32));
                mma_f16(oacc[2 * ni2    ], af, bv);
                mma_f16(oacc[2 * ni2 + 1], af, bv + 2);
            }
        }
    }

    const float i0 = 1.f / lrow0, i1 = 1.f / lrow1;
    const int r0 = tileQ + rb + g, r1 = r0 + 8;
#pragma unroll
    for (int ni = 0; ni < 8; ni++) {
        const int d = ni * 8 + t4 * 2;
        *(__half2*)(H + (size_t)(b * LSEQ + r0) * D_MODEL + h * DH + d) =
            __floats2half2_rn(oacc[ni][0] * i0, oacc[ni][1] * i0);
        *(__half2*)(H + (size_t)(b * LSEQ + r1) * D_MODEL + h * DH + d) =
            __floats2half2_rn(oacc[ni][2] * i1, oacc[ni][3] * i1);
    }
}

// ---------------- weight transposes (convert to fp16 on store) ---------------
__global__ __launch_bounds__(256) void transpose_k(
    const float* __restrict__ in, __half* __restrict__ out, int K, int N)
{
    __shared__ float t[32][33];
    const int bn = blockIdx.x * 32, bk = blockIdx.y * 32;
    const int tx = threadIdx.x, ty = threadIdx.y;
#pragma unroll
    for (int i = ty; i < 32; i += 8)
        t[i][tx] = in[(size_t)(bk + i) * N + bn + tx];
    __syncthreads();
#pragma unroll
    for (int i = ty; i < 32; i += 8)
        out[(size_t)(bn + i) * K + bk + tx] = __float2half_rn(t[tx][i]);
}

__global__ __launch_bounds__(256) void transpose_k4(
    const float* __restrict__ i0, const float* __restrict__ i1,
    const float* __restrict__ i2, const float* __restrict__ i3,
    __half* __restrict__ o0, __half* __restrict__ o1,
    __half* __restrict__ o2, __half* __restrict__ o3)
{
    __shared__ float t[32][33];
    const float* in = (blockIdx.z == 0) ? i0 : (blockIdx.z == 1) ? i1 :
                      (blockIdx.z == 2) ? i2 : i3;
    __half* out = (blockIdx.z == 0) ? o0 : (blockIdx.z == 1) ? o1 :
                  (blockIdx.z == 2) ? o2 : o3;
    const int bn = blockIdx.x * 32, bk = blockIdx.y * 32;
    const int tx = threadIdx.x, ty = threadIdx.y;
#pragma unroll
    for (int i = ty; i < 32; i += 8)
        t[i][tx] = in[(size_t)(bk + i) * 1024 + bn + tx];
    __syncthreads();
#pragma unroll
    for (int i = ty; i < 32; i += 8)
        out[(size_t)(bn + i) * 1024 + bk + tx] = __float2half_rn(t[tx][i]);
}

// ---------------- half-copy (x -> fp16 twin) ---------------------------------
__global__ __launch_bounds__(256) void half_copy(
    const float* __restrict__ in, __half* __restrict__ out)
{
    const size_t i = ((size_t)blockIdx.x * 256 + threadIdx.x) * 4;
    float4 v = *(const float4*)(in + i);
    *(__half2*)(out + i)     = __floats2half2_rn(v.x, v.y);
    *(__half2*)(out + i + 2) = __floats2half2_rn(v.z, v.w);
}

// ---------------- layernorm (optional fp16 twin output) ----------------------
__global__ __launch_bounds__(256) void layernorm(
    const float* __restrict__ X, const float* __restrict__ g,
    const float* __restrict__ be, float* __restrict__ O,
    __half* __restrict__ Or)
{
    __shared__ float red[8];
    const int r = blockIdx.x;
    const int tid = threadIdx.x;
    const float4 v = *(const float4*)(X + (size_t)r * D_MODEL + tid * 4);

    float s = v.x + v.y + v.z + v.w;
#pragma unroll
    for (int o = 16; o > 0; o >>= 1) s += __shfl_xor_sync(0xffffffffu, s, o);
    if ((tid & 31) == 0) red[tid >> 5] = s;
    __syncthreads();
    s = 0.f;
#pragma unroll
    for (int i = 0; i < 8; i++) s += red[i];
    const float mu = s * (1.f / D_MODEL);
    __syncthreads();

    float dx = v.x - mu, dy = v.y - mu, dz = v.z - mu, dw = v.w - mu;
    float sq = dx * dx + dy * dy + dz * dz + dw * dw;
#pragma unroll
    for (int o = 16; o > 0; o >>= 1) sq += __shfl_xor_sync(0xffffffffu, sq, o);
    if ((tid & 31) == 0) red[tid >> 5] = sq;
    __syncthreads();
    sq = 0.f;
#pragma unroll
    for (int i = 0; i < 8; i++) sq += red[i];
    const float rs = rsqrtf(sq * (1.f / D_MODEL) + 1e-5f);

    const float4 gg = *(const float4*)(g + tid * 4);
    const float4 bb = *(const float4*)(be + tid * 4);
    float4 o;
    o.x = dx * rs * gg.x + bb.x;
    o.y = dy * rs * gg.y + bb.y;
    o.z = dz * rs * gg.z + bb.z;
    o.w = dw * rs * gg.w + bb.w;
    *(float4*)(O + (size_t)r * D_MODEL + tid * 4) = o;
    if (Or) {
        *(__half2*)(Or + (size_t)r * D_MODEL + tid * 4)     = __floats2half2_rn(o.x, o.y);
        *(__half2*)(Or + (size_t)r * D_MODEL + tid * 4 + 2) = __floats2half2_rn(o.z, o.w);
    }
}

// ---------------- launch -----------------------------------------------------
extern "C" void kernel_launch(void* const* d_in, const int* in_sizes, int n_in,
                              void* d_out, int out_size)
{
    const float* x   = (const float*)d_in[0];
    const int*   msk = (const int*)d_in[1];
    const float* Wq  = (const float*)d_in[2];
    const float* Wk  = (const float*)d_in[3];
    const float* Wv  = (const float*)d_in[4];
    const float* Wp  = (const float*)d_in[5];
    const float* bp  = (const float*)d_in[6];
    const float* W1  = (const float*)d_in[7];
    const float* b1  = (const float*)d_in[8];
    const float* W2  = (const float*)d_in[9];
    const float* b2  = (const float*)d_in[10];
    const float* g1  = (const float*)d_in[11];
    const float* be1 = (const float*)d_in[12];
    const float* g2  = (const float*)d_in[13];
    const float* be2 = (const float*)d_in[14];
    float* out = (float*)d_out;

    float *tmp, *h;
    __half *q, *k, *v, *hd, *hh, *xh, *ff, *wtqkv, *wtp, *wt1, *wt2;
    cudaGetSymbolAddress((void**)&q,     g_q);
    cudaGetSymbolAddress((void**)&k,     g_k);
    cudaGetSymbolAddress((void**)&v,     g_v);
    cudaGetSymbolAddress((void**)&hd,    g_heads);
    cudaGetSymbolAddress((void**)&tmp,   g_tmp);
    cudaGetSymbolAddress((void**)&h,     g_h);
    cudaGetSymbolAddress((void**)&hh,    g_hh);
    cudaGetSymbolAddress((void**)&xh,    g_xh);
    cudaGetSymbolAddress((void**)&ff,    g_ff);
    cudaGetSymbolAddress((void**)&wtqkv, g_wtqkv);
    cudaGetSymbolAddress((void**)&wtp,   g_wtp);
    cudaGetSymbolAddress((void**)&wt1,   g_wt1);
    cudaGetSymbolAddress((void**)&wt2,   g_wt2);

    static bool attr_done = false;
    if (!attr_done) {
        cudaFuncSetAttribute(gemm_mma<EPI_QKV>,
                             cudaFuncAttributeMaxDynamicSharedMemorySize, GM_SMEM_B);
        cudaFuncSetAttribute(gemm_mma<EPI_BIAS_RESID>,
                             cudaFuncAttributeMaxDynamicSharedMemorySize, GM_SMEM_B);
        cudaFuncSetAttribute(gemm_mma<EPI_BIAS_RELU>,
                             cudaFuncAttributeMaxDynamicSharedMemorySize, GM_SMEM_B);
        cudaFuncSetAttribute(flash_attn,
                             cudaFuncAttributeMaxDynamicSharedMemorySize, FA_SMEM_B);
        attr_done = true;
    }

    dim3 blk(256);
    dim3 tb(32, 8);

    transpose_k4<<<dim3(32, 32, 4), tb>>>(
        Wq, Wk, Wv, Wp,
        wtqkv + 0 * 1024 * 1024, wtqkv + 1 * 1024 * 1024,
        wtqkv + 2 * 1024 * 1024, wtp);
    transpose_k<<<dim3(128, 32), tb>>>(W1, wt1, D_MODEL, DFF);
    transpose_k<<<dim3(32, 128), tb>>>(W2, wt2, DFF, D_MODEL);
    half_copy<<<MROWS * D_MODEL / 1024, blk>>>(x, xh);

    // fused QKV projection (fp16 in/out), scatter to head layout
    gemm_mma<EPI_QKV><<<dim3(24, 32), blk, GM_SMEM_B>>>(
        xh, wtqkv, nullptr, nullptr, 3072, 1024, nullptr, nullptr, q, k, v);

    // fused attention (fp16 MMA + ldmatrix, fp32 softmax)
    flash_attn<<<dim3(8, ZHEADS), blk, FA_SMEM_B>>>(q, k, v, msk, hd);

    // proj + bias + residual(x fp32), LN1 (h fp32 + hh fp16)
    gemm_mma<EPI_BIAS_RESID><<<dim3(8, 32), blk, GM_SMEM_B>>>(
        hd, wtp, tmp, nullptr, 1024, 1024, bp, x, nullptr, nullptr, nullptr);
    layernorm<<<MROWS, blk>>>(tmp, g1, be1, h, hh);

    // FF1 (ReLU -> fp16 ff), FF2 + bias + residual(h fp32), LN2
    gemm_mma<EPI_BIAS_RELU><<<dim3(32, 32), blk, GM_SMEM_B>>>(
        hh, wt1, nullptr, ff, 4096, 1024, b1, nullptr, nullptr, nullptr, nullptr);
    gemm_mma<EPI_BIAS_RESID><<<dim3(8, 32), blk, GM_SMEM_B>>>(
        ff, wt2, tmp, nullptr, 1024, 4096, b2, h, nullptr, nullptr, nullptr);
    layernorm<<<MROWS, blk>>>(tmp, g2, be2, out, nullptr);
}

// round 14
// speedup vs baseline: 2.7935x; 1.0649x over previous
#include <cuda_runtime.h>
#include <cuda_fp16.h>
#include <cstdint>
#include <math.h>

#define D_MODEL 1024
#define NH      16
#define DH      64
#define DFF     4096
#define BATCH   4
#define LSEQ    1024
#define MROWS   (BATCH*LSEQ)       // 4096
#define ZHEADS  (BATCH*NH)         // 64

// ---------------- scratch (device globals; no runtime allocation) ----------
__device__ __half g_q[(size_t)ZHEADS*LSEQ*DH];          // fp16 (b,h,l,d)
__device__ __half g_k[(size_t)ZHEADS*LSEQ*DH];
__device__ __half g_v[(size_t)ZHEADS*LSEQ*DH];
__device__ __half g_heads[(size_t)MROWS*D_MODEL];       // fp16 (flash epi)
__device__ float  g_tmp[(size_t)MROWS*D_MODEL];
__device__ float  g_h[(size_t)MROWS*D_MODEL];           // fp32 residual
__device__ __half g_hh[(size_t)MROWS*D_MODEL];          // fp16 twin of h
__device__ __half g_xh[(size_t)MROWS*D_MODEL];          // fp16 twin of x
__device__ __half g_ff[(size_t)MROWS*DFF];              // fp16 (FF1 epi)
__device__ __half g_wtqkv[(size_t)3*D_MODEL*D_MODEL];   // fp16, (N,K)
__device__ __half g_wtp[(size_t)D_MODEL*D_MODEL];
__device__ __half g_wt1[(size_t)DFF*D_MODEL];
__device__ __half g_wt2[(size_t)D_MODEL*DFF];

// ---------------- helpers ----------------------------------------------------
__device__ __forceinline__ uint32_t smem_u32(const void* p) {
    uint32_t a;
    asm("{ .reg .u64 t; cvta.to.shared.u64 t, %1; cvt.u32.u64 %0, t; }"
        : "=r"(a) : "l"(p));
    return a;
}
__device__ __forceinline__ void cp16(uint32_t s, const void* g) {
    asm volatile("cp.async.cg.shared.global [%0], [%1], 16;" :: "r"(s), "l"(g));
}
#define CP_COMMIT() asm volatile("cp.async.commit_group;" ::: "memory")
#define CP_WAIT1()  asm volatile("cp.async.wait_group 1;" ::: "memory")

__device__ __forceinline__ void mma_f16(float* d, const uint32_t* a,
                                        const uint32_t* b) {
    asm volatile(
        "mma.sync.aligned.m16n8k16.row.col.f32.f16.f16.f32 "
        "{%0,%1,%2,%3}, {%4,%5,%6,%7}, {%8,%9}, {%0,%1,%2,%3};"
        : "+f"(d[0]), "+f"(d[1]), "+f"(d[2]), "+f"(d[3])
        : "r"(a[0]), "r"(a[1]), "r"(a[2]), "r"(a[3]), "r"(b[0]), "r"(b[1]));
}
__device__ __forceinline__ void ldsm_x4(uint32_t* r, uint32_t addr) {
    asm volatile("ldmatrix.sync.aligned.m8n8.x4.shared.b16 {%0,%1,%2,%3}, [%4];"
        : "=r"(r[0]), "=r"(r[1]), "=r"(r[2]), "=r"(r[3]) : "r"(addr));
}
__device__ __forceinline__ void ldsm_x4_t(uint32_t* r, uint32_t addr) {
    asm volatile("ldmatrix.sync.aligned.m8n8.x4.trans.shared.b16 {%0,%1,%2,%3}, [%4];"
        : "=r"(r[0]), "=r"(r[1]), "=r"(r[2]), "=r"(r[3]) : "r"(addr));
}

// ---------------- fp16 mma GEMM: C = A[M,K] @ BT[N,K]^T ---------------------
// 128x128 CTA tile, 8 warps (2x4), warp tile 64x32, K-chunk 64 (4 k-steps).
// 3-stage cp.async pipeline; fragments via ldmatrix.x4 (stride 72, conflict-free).
enum { EPI_QKV = 0, EPI_BIAS_RESID = 1, EPI_BIAS_RELU = 2 };

#define GM_S      72
#define GM_TILE_H (128 * GM_S)            // 9216 halves
#define GM_BUF_H  (2 * GM_TILE_H)         // 18432 halves
#define GM_SMEM_B (3 * GM_BUF_H * 2)      // 110592 bytes

template<int EPI>
__global__ __launch_bounds__(256, 2) void gemm_mma(
    const __half* __restrict__ A, const __half* __restrict__ BT,
    float* __restrict__ Cf, __half* __restrict__ Ch, int N, int K,
    const float* __restrict__ bias, const float* __restrict__ resid,
    __half* __restrict__ qp, __half* __restrict__ kp, __half* __restrict__ vp)
{
    extern __shared__ __half smemh[];
    const uint32_t sb = smem_u32(smemh);

    const int tid  = threadIdx.x;
    const int wid  = tid >> 5;
    const int lane = tid & 31;
    const int g    = lane >> 2;
    const int t4   = lane & 3;
    const int wm   = wid >> 2;
    const int wn   = wid & 3;
    const int tileM = blockIdx.y * 128;
    const int tileN = blockIdx.x * 128;

    const int j8  = lane >> 3;
    const int r8  = lane & 7;

    // ldmatrix base offsets (bytes, within one stage buffer)
    const uint32_t a_l = ((uint32_t)((wm * 64 + (j8 & 1) * 8 + r8) * GM_S
                                     + (j8 >> 1) * 8)) << 1;
    const uint32_t b_l = ((uint32_t)(GM_TILE_H + (wn * 32 + (j8 >> 1) * 8 + r8) * GM_S
                                     + (j8 & 1) * 8)) << 1;

    float acc[4][4][4];
#pragma unroll
    for (int i = 0; i < 4; i++)
#pragma unroll
        for (int j = 0; j < 4; j++)
#pragma unroll
            for (int c = 0; c < 4; c++) acc[i][j][c] = 0.f;

    const int KT = K >> 6;     // 64-wide chunks

    // prologue: stages 0,1  (per tile: 128 rows x 8 segs = 1024 segs, 4/thread)
#pragma unroll
    for (int s = 0; s < 2; s++) {
        const int k0 = s << 6;
        const uint32_t sba = sb + (uint32_t)(s * GM_BUF_H) * 2;
#pragma unroll
        for (int i = 0; i < 4; i++) {
            const int idx = i * 256 + tid;
            const int r   = idx >> 3;
            const int c8  = (idx & 7) * 8;
            cp16(sba + (r * GM_S + c8) * 2,
                 A + (size_t)(tileM + r) * K + k0 + c8);
            cp16(sba + (GM_TILE_H + r * GM_S + c8) * 2,
                 BT + (size_t)(tileN + r) * K + k0 + c8);
        }
        CP_COMMIT();
    }

    for (int kt = 0; kt < KT; kt++) {
        CP_WAIT1();
        __syncthreads();

        if (kt + 2 < KT) {
            const int k0 = (kt + 2) << 6;
            const uint32_t sba = sb + (uint32_t)(((kt + 2) % 3) * GM_BUF_H) * 2;
#pragma unroll
            for (int i = 0; i < 4; i++) {
                const int idx = i * 256 + tid;
                const int r   = idx >> 3;
                const int c8  = (idx & 7) * 8;
                cp16(sba + (r * GM_S + c8) * 2,
                     A + (size_t)(tileM + r) * K + k0 + c8);
                cp16(sba + (GM_TILE_H + r * GM_S + c8) * 2,
                     BT + (size_t)(tileN + r) * K + k0 + c8);
            }
        }
        CP_COMMIT();

        const uint32_t buf = sb + (uint32_t)((kt % 3) * GM_BUF_H) * 2;
#pragma unroll
        for (int ks = 0; ks < 4; ks++) {
            const uint32_t kB = (uint32_t)(ks * 16) << 1;
            uint32_t af[4][4], bq[2][4];
#pragma unroll
            for (int mi = 0; mi < 4; mi++)
                ldsm_x4(af[mi], buf + a_l + ((uint32_t)(mi * 16 * GM_S) << 1) + kB);
#pragma unroll
            for (int nb2 = 0; nb2 < 2; nb2++)
                ldsm_x4(bq[nb2], buf + b_l + ((uint32_t)(nb2 * 16 * GM_S) << 1) + kB);
#pragma unroll
            for (int mi = 0; mi < 4; mi++) {
#pragma unroll
                for (int nb2 = 0; nb2 < 2; nb2++) {
                    mma_f16(acc[mi][2 * nb2    ], af[mi], bq[nb2]);
                    mma_f16(acc[mi][2 * nb2 + 1], af[mi], bq[nb2] + 2);
                }
            }
        }
    }

#pragma unroll
    for (int mi = 0; mi < 4; mi++) {
#pragma unroll
        for (int half = 0; half < 2; half++) {
            const int m = tileM + wm * 64 + mi * 16 + g + half * 8;
#pragma unroll
            for (int ni = 0; ni < 4; ni++) {
                const int n = tileN + wn * 32 + ni * 8 + t4 * 2;
                float v0 = acc[mi][ni][half * 2 + 0];
                float v1 = acc[mi][ni][half * 2 + 1];
                if (EPI == EPI_QKV) {
                    const int b = m >> 10, l = m & 1023;
                    const int which = n >> 10, rem = n & 1023;
                    const int h = rem >> 6, d = rem & 63;
                    __half* dst = (which == 0) ? qp : (which == 1) ? kp : vp;
                    *(__half2*)(dst + ((size_t)((b * NH + h) * LSEQ + l)) * DH + d) =
                        __floats2half2_rn(v0, v1);
                } else {
                    const size_t idx = (size_t)m * N + n;
                    const float2 bb = *(const float2*)(bias + n);
                    v0 += bb.x; v1 += bb.y;
                    if (EPI == EPI_BIAS_RESID) {
                        const float2 rr = *(const float2*)(resid + idx);
                        v0 += rr.x; v1 += rr.y;
                        *(float2*)(Cf + idx) = make_float2(v0, v1);
                    } else {
                        v0 = fmaxf(v0, 0.f); v1 = fmaxf(v1, 0.f);
                        *(__half2*)(Ch + idx) = __floats2half2_rn(v0, v1);
                    }
                }
            }
        }
    }
}

// ---------------- fused flash attention (fp16 MMA + ldmatrix) ----------------
#define FQ_S   72
#define FV_S   72
#define FP_S   136
#define FQ_OFF  0
#define FK_OFF  (FQ_OFF + 128 * FQ_S)          // 9216
#define FV_OFF  (FK_OFF + 128 * FQ_S)          // 18432
#define FP_OFF  (FV_OFF + 128 * FV_S)          // 27648
#define FM_OFF  (FP_OFF + 128 * FP_S)          // 45056 halves
#define FA_SMEM_B (FM_OFF * 2 + 128 * 4)       // 90624 bytes

__global__ __launch_bounds__(256, 2) void flash_attn(
    const __half* __restrict__ Qg, const __half* __restrict__ Kg,
    const __half* __restrict__ Vg, const int* __restrict__ mask,
    __half* __restrict__ H)
{
    extern __shared__ __half smh[];
    __half* Qs = smh + FQ_OFF;
    __half* Ks = smh + FK_OFF;
    __half* Vs = smh + FV_OFF;
    __half* Ps = smh + FP_OFF;
    int*    Ms = (int*)(smh + FM_OFF);
    const uint32_t sb = smem_u32(smh);

    const int z = blockIdx.y;
    const int b = z >> 4, h = z & 15;
    const __half* q  = Qg + (size_t)z * LSEQ * DH;
    const __half* kp = Kg + (size_t)z * LSEQ * DH;
    const __half* vp = Vg + (size_t)z * LSEQ * DH;
    const int* mb = mask + (size_t)b * LSEQ;
    const int tileQ = blockIdx.x * 128;

    const int tid  = threadIdx.x;
    const int wid  = tid >> 5;
    const int lane = tid & 31;
    const int g    = lane >> 2;
    const int t4   = lane & 3;
    const int rb   = wid * 16;
    const int j8   = lane >> 3;
    const int r8   = lane & 7;

    const uint32_t qa = sb + (uint32_t)((FQ_OFF + (rb + (j8 & 1) * 8 + r8) * FQ_S
                                         + (j8 >> 1) * 8) << 1);
    const uint32_t pa = sb + (uint32_t)((FP_OFF + (rb + (j8 & 1) * 8 + r8) * FP_S
                                         + (j8 >> 1) * 8) << 1);
    const uint32_t ka = sb + (uint32_t)((FK_OFF + ((j8 >> 1) * 8 + r8) * FQ_S
                                         + (j8 & 1) * 8) << 1);
    const uint32_t va = sb + (uint32_t)((FV_OFF + ((j8 & 1) * 8 + r8) * FV_S
                                         + (j8 >> 1) * 8) << 1);

#pragma unroll
    for (int i = 0; i < 4; i++) {
        const int idx = i * 256 + tid;
        const int r   = idx >> 3;
        const int c8  = (idx & 7) * 8;
        *(uint4*)(Qs + r * FQ_S + c8) =
            *(const uint4*)(q + (size_t)(tileQ + r) * DH + c8);
    }

    float mrow0 = -1e30f, mrow1 = -1e30f;
    float lrow0 = 0.f, lrow1 = 0.f;
    float oacc[8][4];
#pragma unroll
    for (int i = 0; i < 8; i++)
#pragma unroll
        for (int c = 0; c < 4; c++) oacc[i][c] = 0.f;

    for (int kt = 0; kt < 8; kt++) {
        const int k0 = kt * 128;
        __syncthreads();
#pragma unroll
        for (int i = 0; i < 4; i++) {
            const int idx = i * 256 + tid;
            const int r   = idx >> 3;
            const int c8  = (idx & 7) * 8;
            *(uint4*)(Ks + r * FQ_S + c8) =
                *(const uint4*)(kp + (size_t)(k0 + r) * DH + c8);
            *(uint4*)(Vs + r * FV_S + c8) =
                *(const uint4*)(vp + (size_t)(k0 + r) * DH + c8);
        }
        if (tid < 128) Ms[tid] = mb[k0 + tid];
        __syncthreads();

        float sacc[16][4];
#pragma unroll
        for (int ni = 0; ni < 16; ni++)
#pragma unroll
            for (int c = 0; c < 4; c++) sacc[ni][c] = 0.f;
#pragma unroll
        for (int ks = 0; ks < 4; ks++) {
            const int k = ks * 16;
            uint32_t af[4];
            ldsm_x4(af, qa + (k << 1));
#pragma unroll
            for (int ni2 = 0; ni2 < 8; ni2++) {
                uint32_t bq[4];
                ldsm_x4(bq, ka + (uint32_t)(ni2 * (16 * FQ_S * 2)) + (k << 1));
                mma_f16(sacc[2 * ni2    ], af, bq);
                mma_f16(sacc[2 * ni2 + 1], af, bq + 2);
            }
        }

        float tm0 = -1e30f, tm1 = -1e30f;
#pragma unroll
        for (int ni = 0; ni < 16; ni++) {
            const int c0 = ni * 8 + t4 * 2, c1 = c0 + 1;
            const bool m0 = (Ms[c0] == 0), m1 = (Ms[c1] == 0);
            float s0 = sacc[ni][0] * 0.125f; if (m0) s0 = -1e10f;
            float s1 = sacc[ni][1] * 0.125f; if (m1) s1 = -1e10f;
            float s2 = sacc[ni][2] * 0.125f; if (m0) s2 = -1e10f;
            float s3 = sacc[ni][3] * 0.125f; if (m1) s3 = -1e10f;
            sacc[ni][0] = s0; sacc[ni][1] = s1; sacc[ni][2] = s2; sacc[ni][3] = s3;
            tm0 = fmaxf(tm0, fmaxf(s0, s1));
            tm1 = fmaxf(tm1, fmaxf(s2, s3));
        }
        tm0 = fmaxf(tm0, __shfl_xor_sync(0xffffffffu, tm0, 1));
        tm0 = fmaxf(tm0, __shfl_xor_sync(0xffffffffu, tm0, 2));
        tm1 = fmaxf(tm1, __shfl_xor_sync(0xffffffffu, tm1, 1));
        tm1 = fmaxf(tm1, __shfl_xor_sync(0xffffffffu, tm1, 2));

        const float mn0 = fmaxf(mrow0, tm0), mn1 = fmaxf(mrow1, tm1);
        const float a0 = __expf(mrow0 - mn0), a1 = __expf(mrow1 - mn1);

        float ps0 = 0.f, ps1 = 0.f;
#pragma unroll
        for (int ni = 0; ni < 16; ni++) {
            const float e0 = __expf(sacc[ni][0] - mn0);
            const float e1 = __expf(sacc[ni][1] - mn0);
            const float e2 = __expf(sacc[ni][2] - mn1);
            const float e3 = __expf(sacc[ni][3] - mn1);
            ps0 += e0 + e1; ps1 += e2 + e3;
            *(__half2*)(Ps + (rb + g    ) * FP_S + ni * 8 + t4 * 2) =
                __floats2half2_rn(e0, e1);
            *(__half2*)(Ps + (rb + g + 8) * FP_S + ni * 8 + t4 * 2) =
                __floats2half2_rn(e2, e3);
        }
        ps0 += __shfl_xor_sync(0xffffffffu, ps0, 1);
        ps0 += __shfl_xor_sync(0xffffffffu, ps0, 2);
        ps1 += __shfl_xor_sync(0xffffffffu, ps1, 1);
        ps1 += __shfl_xor_sync(0xffffffffu, ps1, 2);

        lrow0 = lrow0 * a0 + ps0;
        lrow1 = lrow1 * a1 + ps1;
        mrow0 = mn0; mrow1 = mn1;
#pragma unroll
        for (int ni = 0; ni < 8; ni++) {
            oacc[ni][0] *= a0; oacc[ni][1] *= a0;
            oacc[ni][2] *= a1; oacc[ni][3] *= a1;
        }
        __syncwarp();

#pragma unroll
        for (int ks = 0; ks < 8; ks++) {
            const int k = ks * 16;
            uint32_t af[4];
            ldsm_x4(af, pa + (k << 1));
#pragma unroll
            for (int ni2 = 0; ni2 < 4; ni2++) {
                uint32_t bv[4];
                ldsm_x4_t(bv, va + (uint32_t)(k * (FV_S * 2)) + (uint32_t)(ni2 * 32));
                mma_f16(oacc[2 * ni2    ], af, bv);
                mma_f16(oacc[2 * ni2 + 1], af, bv + 2);
            }
        }
    }

    const float i0 = 1.f / lrow0, i1 = 1.f / lrow1;
    const int r0 = tileQ + rb + g, r1 = r0 + 8;
#pragma unroll
    for (int ni = 0; ni < 8; ni++) {
        const int d = ni * 8 + t4 * 2;
        *(__half2*)(H + (size_t)(b * LSEQ + r0) * D_MODEL + h * DH + d) =
            __floats2half2_rn(oacc[ni][0] * i0, oacc[ni][1] * i0);
        *(__half2*)(H + (size_t)(b * LSEQ + r1) * D_MODEL + h * DH + d) =
            __floats2half2_rn(oacc[ni][2] * i1, oacc[ni][3] * i1);
    }
}

// ---------------- weight transposes (convert to fp16 on store) ---------------
__global__ __launch_bounds__(256) void transpose_k(
    const float* __restrict__ in, __half* __restrict__ out, int K, int N)
{
    __shared__ float t[32][33];
    const int bn = blockIdx.x * 32, bk = blockIdx.y * 32;
    const int tx = threadIdx.x, ty = threadIdx.y;
#pragma unroll
    for (int i = ty; i < 32; i += 8)
        t[i][tx] = in[(size_t)(bk + i) * N + bn + tx];
    __syncthreads();
#pragma unroll
    for (int i = ty; i < 32; i += 8)
        out[(size_t)(bn + i) * K + bk + tx] = __float2half_rn(t[tx][i]);
}

__global__ __launch_bounds__(256) void transpose_k4(
    const float* __restrict__ i0, const float* __restrict__ i1,
    const float* __restrict__ i2, const float* __restrict__ i3,
    __half* __restrict__ o0, __half* __restrict__ o1,
    __half* __restrict__ o2, __half* __restrict__ o3)
{
    __shared__ float t[32][33];
    const float* in = (blockIdx.z == 0) ? i0 : (blockIdx.z == 1) ? i1 :
                      (blockIdx.z == 2) ? i2 : i3;
    __half* out = (blockIdx.z == 0) ? o0 : (blockIdx.z == 1) ? o1 :
                  (blockIdx.z == 2) ? o2 : o3;
    const int bn = blockIdx.x * 32, bk = blockIdx.y * 32;
    const int tx = threadIdx.x, ty = threadIdx.y;
#pragma unroll
    for (int i = ty; i < 32; i += 8)
        t[i][tx] = in[(size_t)(bk + i) * 1024 + bn + tx];
    __syncthreads();
#pragma unroll
    for (int i = ty; i < 32; i += 8)
        out[(size_t)(bn + i) * 1024 + bk + tx] = __float2half_rn(t[tx][i]);
}

// ---------------- half-copy (x -> fp16 twin) ---------------------------------
__global__ __launch_bounds__(256) void half_copy(
    const float* __restrict__ in, __half* __restrict__ out)
{
    const size_t i = ((size_t)blockIdx.x * 256 + threadIdx.x) * 4;
    float4 v = *(const float4*)(in + i);
    *(__half2*)(out + i)     = __floats2half2_rn(v.x, v.y);
    *(__half2*)(out + i + 2) = __floats2half2_rn(v.z, v.w);
}

// ---------------- layernorm (optional fp16 twin output) ----------------------
__global__ __launch_bounds__(256) void layernorm(
    const float* __restrict__ X, const float* __restrict__ g,
    const float* __restrict__ be, float* __restrict__ O,
    __half* __restrict__ Or)
{
    __shared__ float red[8];
    const int r = blockIdx.x;
    const int tid = threadIdx.x;
    const float4 v = *(const float4*)(X + (size_t)r * D_MODEL + tid * 4);

    float s = v.x + v.y + v.z + v.w;
#pragma unroll
    for (int o = 16; o > 0; o >>= 1) s += __shfl_xor_sync(0xffffffffu, s, o);
    if ((tid & 31) == 0) red[tid >> 5] = s;
    __syncthreads();
    s = 0.f;
#pragma unroll
    for (int i = 0; i < 8; i++) s += red[i];
    const float mu = s * (1.f / D_MODEL);
    __syncthreads();

    float dx = v.x - mu, dy = v.y - mu, dz = v.z - mu, dw = v.w - mu;
    float sq = dx * dx + dy * dy + dz * dz + dw * dw;
#pragma unroll
    for (int o = 16; o > 0; o >>= 1) sq += __shfl_xor_sync(0xffffffffu, sq, o);
    if ((tid & 31) == 0) red[tid >> 5] = sq;
    __syncthreads();
    sq = 0.f;
#pragma unroll
    for (int i = 0; i < 8; i++) sq += red[i];
    const float rs = rsqrtf(sq * (1.f / D_MODEL) + 1e-5f);

    const float4 gg = *(const float4*)(g + tid * 4);
    const float4 bb = *(const float4*)(be + tid * 4);
    float4 o;
    o.x = dx * rs * gg.x + bb.x;
    o.y = dy * rs * gg.y + bb.y;
    o.z = dz * rs * gg.z + bb.z;
    o.w = dw * rs * gg.w + bb.w;
    *(float4*)(O + (size_t)r * D_MODEL + tid * 4) = o;
    if (Or) {
        *(__half2*)(Or + (size_t)r * D_MODEL + tid * 4)     = __floats2half2_rn(o.x, o.y);
        *(__half2*)(Or + (size_t)r * D_MODEL + tid * 4 + 2) = __floats2half2_rn(o.z, o.w);
    }
}

// ---------------- launch -----------------------------------------------------
extern "C" void kernel_launch(void* const* d_in, const int* in_sizes, int n_in,
                              void* d_out, int out_size)
{
    const float* x   = (const float*)d_in[0];
    const int*   msk = (const int*)d_in[1];
    const float* Wq  = (const float*)d_in[2];
    const float* Wk  = (const float*)d_in[3];
    const float* Wv  = (const float*)d_in[4];
    const float* Wp  = (const float*)d_in[5];
    const float* bp  = (const float*)d_in[6];
    const float* W1  = (const float*)d_in[7];
    const float* b1  = (const float*)d_in[8];
    const float* W2  = (const float*)d_in[9];
    const float* b2  = (const float*)d_in[10];
    const float* g1  = (const float*)d_in[11];
    const float* be1 = (const float*)d_in[12];
    const float* g2  = (const float*)d_in[13];
    const float* be2 = (const float*)d_in[14];
    float* out = (float*)d_out;

    float *tmp, *h;
    __half *q, *k, *v, *hd, *hh, *xh, *ff, *wtqkv, *wtp, *wt1, *wt2;
    cudaGetSymbolAddress((void**)&q,     g_q);
    cudaGetSymbolAddress((void**)&k,     g_k);
    cudaGetSymbolAddress((void**)&v,     g_v);
    cudaGetSymbolAddress((void**)&hd,    g_heads);
    cudaGetSymbolAddress((void**)&tmp,   g_tmp);
    cudaGetSymbolAddress((void**)&h,     g_h);
    cudaGetSymbolAddress((void**)&hh,    g_hh);
    cudaGetSymbolAddress((void**)&xh,    g_xh);
    cudaGetSymbolAddress((void**)&ff,    g_ff);
    cudaGetSymbolAddress((void**)&wtqkv, g_wtqkv);
    cudaGetSymbolAddress((void**)&wtp,   g_wtp);
    cudaGetSymbolAddress((void**)&wt1,   g_wt1);
    cudaGetSymbolAddress((void**)&wt2,   g_wt2);

    static cudaStream_t s_side = nullptr;
    static cudaEvent_t ev_fork = nullptr, ev_join = nullptr;
    static bool attr_done = false;
    if (!attr_done) {
        cudaFuncSetAttribute(gemm_mma<EPI_QKV>,
                             cudaFuncAttributeMaxDynamicSharedMemorySize, GM_SMEM_B);
        cudaFuncSetAttribute(gemm_mma<EPI_BIAS_RESID>,
                             cudaFuncAttributeMaxDynamicSharedMemorySize, GM_SMEM_B);
        cudaFuncSetAttribute(gemm_mma<EPI_BIAS_RELU>,
                             cudaFuncAttributeMaxDynamicSharedMemorySize, GM_SMEM_B);
        cudaFuncSetAttribute(flash_attn,
                             cudaFuncAttributeMaxDynamicSharedMemorySize, FA_SMEM_B);
        cudaStreamCreateWithFlags(&s_side, cudaStreamNonBlocking);
        cudaEventCreateWithFlags(&ev_fork, cudaEventDisableTiming);
        cudaEventCreateWithFlags(&ev_join, cudaEventDisableTiming);
        attr_done = true;
    }

    dim3 blk(256);
    dim3 tb(32, 8);

    // Fork: W1/W2 transposes run on the side stream, overlapped with the
    // QKV + attention + proj chain. Joined before FF1.
    cudaEventRecord(ev_fork, 0);
    cudaStreamWaitEvent(s_side, ev_fork, 0);
    transpose_k<<<dim3(128, 32), tb, 0, s_side>>>(W1, wt1, D_MODEL, DFF);
    transpose_k<<<dim3(32, 128), tb, 0, s_side>>>(W2, wt2, DFF, D_MODEL);
    cudaEventRecord(ev_join, s_side);

    // main stream: QKV-path prologue
    transpose_k4<<<dim3(32, 32, 4), tb>>>(
        Wq, Wk, Wv, Wp,
        wtqkv + 0 * 1024 * 1024, wtqkv + 1 * 1024 * 1024,
        wtqkv + 2 * 1024 * 1024, wtp);
    half_copy<<<MROWS * D_MODEL / 1024, blk>>>(x, xh);

    // fused QKV projection (fp16 in/out), scatter to head layout
    gemm_mma<EPI_QKV><<<dim3(24, 32), blk, GM_SMEM_B>>>(
        xh, wtqkv, nullptr, nullptr, 3072, 1024, nullptr, nullptr, q, k, v);

    // fused attention (fp16 MMA + ldmatrix, fp32 softmax)
    flash_attn<<<dim3(8, ZHEADS), blk, FA_SMEM_B>>>(q, k, v, msk, hd);

    // proj + bias + residual(x fp32), LN1 (h fp32 + hh fp16)
    gemm_mma<EPI_BIAS_RESID><<<dim3(8, 32), blk, GM_SMEM_B>>>(
        hd, wtp, tmp, nullptr, 1024, 1024, bp, x, nullptr, nullptr, nullptr);
    layernorm<<<MROWS, blk>>>(tmp, g1, be1, h, hh);

    // join side stream (wt1/wt2 ready), then FF1/FF2
    cudaStreamWaitEvent(0, ev_join, 0);
    gemm_mma<EPI_BIAS_RELU><<<dim3(32, 32), blk, GM_SMEM_B>>>(
        hh, wt1, nullptr, ff, 4096, 1024, b1, nullptr, nullptr, nullptr, nullptr);
    gemm_mma<EPI_BIAS_RESID><<<dim3(8, 32), blk, GM_SMEM_B>>>(
        ff, wt2, tmp, nullptr, 1024, 4096, b2, h, nullptr, nullptr, nullptr);
    layernorm<<<MROWS, blk>>>(tmp, g2, be2, out, nullptr);
}

// round 17
// speedup vs baseline: 2.8259x; 1.0116x over previous
#include <cuda_runtime.h>
#include <cuda_fp16.h>
#include <cstdint>
#include <math.h>

#define D_MODEL 1024
#define NH      16
#define DH      64
#define DFF     4096
#define BATCH   4
#define LSEQ    1024
#define MROWS   (BATCH*LSEQ)       // 4096
#define ZHEADS  (BATCH*NH)         // 64

// ---------------- scratch (device globals; no runtime allocation) ----------
__device__ __half g_q[(size_t)ZHEADS*LSEQ*DH];          // fp16 (b,h,l,d)
__device__ __half g_k[(size_t)ZHEADS*LSEQ*DH];
__device__ __half g_v[(size_t)ZHEADS*LSEQ*DH];
__device__ __half g_heads[(size_t)MROWS*D_MODEL];       // fp16 (flash epi)
__device__ float  g_tmp[(size_t)MROWS*D_MODEL];
__device__ float  g_h[(size_t)MROWS*D_MODEL];           // fp32 residual
__device__ __half g_hh[(size_t)MROWS*D_MODEL];          // fp16 twin of h
__device__ __half g_xh[(size_t)MROWS*D_MODEL];          // fp16 twin of x
__device__ __half g_ff[(size_t)MROWS*DFF];              // fp16 (FF1 epi)
__device__ __half g_wtqkv[(size_t)3*D_MODEL*D_MODEL];   // fp16, (N,K)
__device__ __half g_wtp[(size_t)D_MODEL*D_MODEL];
__device__ __half g_wt1[(size_t)DFF*D_MODEL];
__device__ __half g_wt2[(size_t)D_MODEL*DFF];

// ---------------- helpers ----------------------------------------------------
__device__ __forceinline__ uint32_t smem_u32(const void* p) {
    uint32_t a;
    asm("{ .reg .u64 t; cvta.to.shared.u64 t, %1; cvt.u32.u64 %0, t; }"
        : "=r"(a) : "l"(p));
    return a;
}
__device__ __forceinline__ void cp16(uint32_t s, const void* g) {
    asm volatile("cp.async.cg.shared.global [%0], [%1], 16;" :: "r"(s), "l"(g));
}
#define CP_COMMIT() asm volatile("cp.async.commit_group;" ::: "memory")
#define CP_WAIT1()  asm volatile("cp.async.wait_group 1;" ::: "memory")
#define CP_WAIT0()  asm volatile("cp.async.wait_group 0;" ::: "memory")

__device__ __forceinline__ void mma_f16(float* d, const uint32_t* a,
                                        const uint32_t* b) {
    asm volatile(
        "mma.sync.aligned.m16n8k16.row.col.f32.f16.f16.f32 "
        "{%0,%1,%2,%3}, {%4,%5,%6,%7}, {%8,%9}, {%0,%1,%2,%3};"
        : "+f"(d[0]), "+f"(d[1]), "+f"(d[2]), "+f"(d[3])
        : "r"(a[0]), "r"(a[1]), "r"(a[2]), "r"(a[3]), "r"(b[0]), "r"(b[1]));
}
__device__ __forceinline__ void ldsm_x4(uint32_t* r, uint32_t addr) {
    asm volatile("ldmatrix.sync.aligned.m8n8.x4.shared.b16 {%0,%1,%2,%3}, [%4];"
        : "=r"(r[0]), "=r"(r[1]), "=r"(r[2]), "=r"(r[3]) : "r"(addr));
}
__device__ __forceinline__ void ldsm_x4_t(uint32_t* r, uint32_t addr) {
    asm volatile("ldmatrix.sync.aligned.m8n8.x4.trans.shared.b16 {%0,%1,%2,%3}, [%4];"
        : "=r"(r[0]), "=r"(r[1]), "=r"(r[2]), "=r"(r[3]) : "r"(addr));
}

// ---------------- fp16 mma GEMM: C = A[M,K] @ BT[N,K]^T ---------------------
// 128x128 CTA tile, 8 warps (2x4), warp tile 64x32, K-chunk 64 (4 k-steps).
// 3-stage cp.async pipeline; fragments via ldmatrix.x4 (stride 72, conflict-free).
enum { EPI_QKV = 0, EPI_BIAS_RESID = 1, EPI_BIAS_RELU = 2 };

#define GM_S      72
#define GM_TILE_H (128 * GM_S)            // 9216 halves
#define GM_BUF_H  (2 * GM_TILE_H)         // 18432 halves
#define GM_SMEM_B (3 * GM_BUF_H * 2)      // 110592 bytes

template<int EPI>
__global__ __launch_bounds__(256, 2) void gemm_mma(
    const __half* __restrict__ A, const __half* __restrict__ BT,
    float* __restrict__ Cf, __half* __restrict__ Ch, int N, int K,
    const float* __restrict__ bias, const float* __restrict__ resid,
    __half* __restrict__ qp, __half* __restrict__ kp, __half* __restrict__ vp)
{
    extern __shared__ __half smemh[];
    const uint32_t sb = smem_u32(smemh);

    const int tid  = threadIdx.x;
    const int wid  = tid >> 5;
    const int lane = tid & 31;
    const int g    = lane >> 2;
    const int t4   = lane & 3;
    const int wm   = wid >> 2;
    const int wn   = wid & 3;
    const int tileM = blockIdx.y * 128;
    const int tileN = blockIdx.x * 128;

    const int j8  = lane >> 3;
    const int r8  = lane & 7;

    const uint32_t a_l = ((uint32_t)((wm * 64 + (j8 & 1) * 8 + r8) * GM_S
                                     + (j8 >> 1) * 8)) << 1;
    const uint32_t b_l = ((uint32_t)(GM_TILE_H + (wn * 32 + (j8 >> 1) * 8 + r8) * GM_S
                                     + (j8 & 1) * 8)) << 1;

    float acc[4][4][4];
#pragma unroll
    for (int i = 0; i < 4; i++)
#pragma unroll
        for (int j = 0; j < 4; j++)
#pragma unroll
            for (int c = 0; c < 4; c++) acc[i][j][c] = 0.f;

    const int KT = K >> 6;

#pragma unroll
    for (int s = 0; s < 2; s++) {
        const int k0 = s << 6;
        const uint32_t sba = sb + (uint32_t)(s * GM_BUF_H) * 2;
#pragma unroll
        for (int i = 0; i < 4; i++) {
            const int idx = i * 256 + tid;
            const int r   = idx >> 3;
            const int c8  = (idx & 7) * 8;
            cp16(sba + (r * GM_S + c8) * 2,
                 A + (size_t)(tileM + r) * K + k0 + c8);
            cp16(sba + (GM_TILE_H + r * GM_S + c8) * 2,
                 BT + (size_t)(tileN + r) * K + k0 + c8);
        }
        CP_COMMIT();
    }

    for (int kt = 0; kt < KT; kt++) {
        CP_WAIT1();
        __syncthreads();

        if (kt + 2 < KT) {
            const int k0 = (kt + 2) << 6;
            const uint32_t sba = sb + (uint32_t)(((kt + 2) % 3) * GM_BUF_H) * 2;
#pragma unroll
            for (int i = 0; i < 4; i++) {
                const int idx = i * 256 + tid;
                const int r   = idx >> 3;
                const int c8  = (idx & 7) * 8;
                cp16(sba + (r * GM_S + c8) * 2,
                     A + (size_t)(tileM + r) * K + k0 + c8);
                cp16(sba + (GM_TILE_H + r * GM_S + c8) * 2,
                     BT + (size_t)(tileN + r) * K + k0 + c8);
            }
        }
        CP_COMMIT();

        const uint32_t buf = sb + (uint32_t)((kt % 3) * GM_BUF_H) * 2;
#pragma unroll
        for (int ks = 0; ks < 4; ks++) {
            const uint32_t kB = (uint32_t)(ks * 16) << 1;
            uint32_t af[4][4], bq[2][4];
#pragma unroll
            for (int mi = 0; mi < 4; mi++)
                ldsm_x4(af[mi], buf + a_l + ((uint32_t)(mi * 16 * GM_S) << 1) + kB);
#pragma unroll
            for (int nb2 = 0; nb2 < 2; nb2++)
                ldsm_x4(bq[nb2], buf + b_l + ((uint32_t)(nb2 * 16 * GM_S) << 1) + kB);
#pragma unroll
            for (int mi = 0; mi < 4; mi++) {
#pragma unroll
                for (int nb2 = 0; nb2 < 2; nb2++) {
                    mma_f16(acc[mi][2 * nb2    ], af[mi], bq[nb2]);
                    mma_f16(acc[mi][2 * nb2 + 1], af[mi], bq[nb2] + 2);
                }
            }
        }
    }

#pragma unroll
    for (int mi = 0; mi < 4; mi++) {
#pragma unroll
        for (int half = 0; half < 2; half++) {
            const int m = tileM + wm * 64 + mi * 16 + g + half * 8;
#pragma unroll
            for (int ni = 0; ni < 4; ni++) {
                const int n = tileN + wn * 32 + ni * 8 + t4 * 2;
                float v0 = acc[mi][ni][half * 2 + 0];
                float v1 = acc[mi][ni][half * 2 + 1];
                if (EPI == EPI_QKV) {
                    const int b = m >> 10, l = m & 1023;
                    const int which = n >> 10, rem = n & 1023;
                    const int h = rem >> 6, d = rem & 63;
                    __half* dst = (which == 0) ? qp : (which == 1) ? kp : vp;
                    *(__half2*)(dst + ((size_t)((b * NH + h) * LSEQ + l)) * DH + d) =
                        __floats2half2_rn(v0, v1);
                } else {
                    const size_t idx = (size_t)m * N + n;
                    const float2 bb = *(const float2*)(bias + n);
                    v0 += bb.x; v1 += bb.y;
                    if (EPI == EPI_BIAS_RESID) {
                        const float2 rr = *(const float2*)(resid + idx);
                        v0 += rr.x; v1 += rr.y;
                        *(float2*)(Cf + idx) = make_float2(v0, v1);
                    } else {
                        v0 = fmaxf(v0, 0.f); v1 = fmaxf(v1, 0.f);
                        *(__half2*)(Ch + idx) = __floats2half2_rn(v0, v1);
                    }
                }
            }
        }
    }
}

// ---------------- fused flash attention (fp16 MMA + ldmatrix + cp.async) -----
// Qs/Ks: [128][72]; Vs: double-buffered 2x[128][72]; Ps: [128][136];
// mask: double-buffered 2x128 ints. Next tile's K/V/mask prefetched via
// cp.async during softmax+PV of current tile.
#define FQ_S   72
#define FP_S   136
#define FQ_OFF  0
#define FK_OFF  (128 * FQ_S)                   // 9216
#define FV_OFF  (2 * 128 * FQ_S)               // 18432
#define FV_BUF  (128 * FQ_S)                   // 9216 halves per V buffer
#define FP_OFF  (FV_OFF + 2 * FV_BUF)          // 36864
#define FM_OFF  (FP_OFF + 128 * FP_S)          // 54272 halves
#define FA_SMEM_B (FM_OFF * 2 + 2 * 128 * 4)   // 109568 bytes

__global__ __launch_bounds__(256, 2) void flash_attn(
    const __half* __restrict__ Qg, const __half* __restrict__ Kg,
    const __half* __restrict__ Vg, const int* __restrict__ mask,
    __half* __restrict__ H)
{
    extern __shared__ __half smh[];
    __half* Qs = smh + FQ_OFF;
    int*    Ms = (int*)(smh + FM_OFF);
    const uint32_t sb = smem_u32(smh);

    const int z = blockIdx.y;
    const int b = z >> 4, h = z & 15;
    const __half* q  = Qg + (size_t)z * LSEQ * DH;
    const __half* kp = Kg + (size_t)z * LSEQ * DH;
    const __half* vp = Vg + (size_t)z * LSEQ * DH;
    const int* mb = mask + (size_t)b * LSEQ;
    const int tileQ = blockIdx.x * 128;

    const int tid  = threadIdx.x;
    const int wid  = tid >> 5;
    const int lane = tid & 31;
    const int g    = lane >> 2;
    const int t4   = lane & 3;
    const int rb   = wid * 16;
    const int j8   = lane >> 3;
    const int r8   = lane & 7;

    const uint32_t qa = sb + (uint32_t)((FQ_OFF + (rb + (j8 & 1) * 8 + r8) * FQ_S
                                         + (j8 >> 1) * 8) << 1);
    const uint32_t pa = sb + (uint32_t)((FP_OFF + (rb + (j8 & 1) * 8 + r8) * FP_S
                                         + (j8 >> 1) * 8) << 1);
    const uint32_t ka = sb + (uint32_t)((FK_OFF + ((j8 >> 1) * 8 + r8) * FQ_S
                                         + (j8 & 1) * 8) << 1);
    const uint32_t va = sb + (uint32_t)((FV_OFF + ((j8 & 1) * 8 + r8) * FQ_S
                                         + (j8 >> 1) * 8) << 1);

    // Q tile (plain loads, once)
#pragma unroll
    for (int i = 0; i < 4; i++) {
        const int idx = i * 256 + tid;
        const int r   = idx >> 3;
        const int c8  = (idx & 7) * 8;
        *(uint4*)(Qs + r * FQ_S + c8) =
            *(const uint4*)(q + (size_t)(tileQ + r) * DH + c8);
    }

    // prefetch tile 0: K -> Ks, V -> Vs buf0, mask -> Ms buf0
#pragma unroll
    for (int i = 0; i < 4; i++) {
        const int idx = i * 256 + tid;
        const int r   = idx >> 3;
        const int c8  = (idx & 7) * 8;
        cp16(sb + (uint32_t)((FK_OFF + r * FQ_S + c8) << 1),
             kp + (size_t)r * DH + c8);
        cp16(sb + (uint32_t)((FV_OFF + r * FQ_S + c8) << 1),
             vp + (size_t)r * DH + c8);
    }
    if (tid < 32)
        cp16(sb + (uint32_t)(FM_OFF << 1) + (uint32_t)(tid * 16), mb + tid * 4);
    CP_COMMIT();

    float mrow0 = -1e30f, mrow1 = -1e30f;
    float lrow0 = 0.f, lrow1 = 0.f;
    float oacc[8][4];
#pragma unroll
    for (int i = 0; i < 8; i++)
#pragma unroll
        for (int c = 0; c < 4; c++) oacc[i][c] = 0.f;

    for (int kt = 0; kt < 8; kt++) {
        CP_WAIT0();
        __syncthreads();

        // S = Q K^T  (consumes Ks)
        float sacc[16][4];
#pragma unroll
        for (int ni = 0; ni < 16; ni++)
#pragma unroll
            for (int c = 0; c < 4; c++) sacc[ni][c] = 0.f;
#pragma unroll
        for (int ks = 0; ks < 4; ks++) {
            const int k = ks * 16;
            uint32_t af[4];
            ldsm_x4(af, qa + (k << 1));
#pragma unroll
            for (int ni2 = 0; ni2 < 8; ni2++) {
                uint32_t bq[4];
                ldsm_x4(bq, ka + (uint32_t)(ni2 * (16 * FQ_S * 2)) + (k << 1));
                mma_f16(sacc[2 * ni2    ], af, bq);
                mma_f16(sacc[2 * ni2 + 1], af, bq + 2);
            }
        }
        __syncthreads();   // all warps done with Ks -> safe to overwrite

        // prefetch tile kt+1 (overlaps softmax + PV below)
        if (kt + 1 < 8) {
            const int kn = (kt + 1) * 128;
            const uint32_t vbb = sb +
                (uint32_t)((FV_OFF + ((kt + 1) & 1) * FV_BUF) << 1);
#pragma unroll
            for (int i = 0; i < 4; i++) {
                const int idx = i * 256 + tid;
                const int r   = idx >> 3;
                const int c8  = (idx & 7) * 8;
                cp16(sb + (uint32_t)((FK_OFF + r * FQ_S + c8) << 1),
                     kp + (size_t)(kn + r) * DH + c8);
                cp16(vbb + (uint32_t)((r * FQ_S + c8) << 1),
                     vp + (size_t)(kn + r) * DH + c8);
            }
            if (tid < 32)
                cp16(sb + (uint32_t)(FM_OFF << 1) +
                         (uint32_t)(((kt + 1) & 1) * 512) + (uint32_t)(tid * 16),
                     mb + kn + tid * 4);
            CP_COMMIT();
        }

        const int* Mc = Ms + (kt & 1) * 128;
        float tm0 = -1e30f, tm1 = -1e30f;
#pragma unroll
        for (int ni = 0; ni < 16; ni++) {
            const int c0 = ni * 8 + t4 * 2, c1 = c0 + 1;
            const bool m0 = (Mc[c0] == 0), m1 = (Mc[c1] == 0);
            float s0 = sacc[ni][0] * 0.125f; if (m0) s0 = -1e10f;
            float s1 = sacc[ni][1] * 0.125f; if (m1) s1 = -1e10f;
            float s2 = sacc[ni][2] * 0.125f; if (m0) s2 = -1e10f;
            float s3 = sacc[ni][3] * 0.125f; if (m1) s3 = -1e10f;
            sacc[ni][0] = s0; sacc[ni][1] = s1; sacc[ni][2] = s2; sacc[ni][3] = s3;
            tm0 = fmaxf(tm0, fmaxf(s0, s1));
            tm1 = fmaxf(tm1, fmaxf(s2, s3));
        }
        tm0 = fmaxf(tm0, __shfl_xor_sync(0xffffffffu, tm0, 1));
        tm0 = fmaxf(tm0, __shfl_xor_sync(0xffffffffu, tm0, 2));
        tm1 = fmaxf(tm1, __shfl_xor_sync(0xffffffffu, tm1, 1));
        tm1 = fmaxf(tm1, __shfl_xor_sync(0xffffffffu, tm1, 2));

        const float mn0 = fmaxf(mrow0, tm0), mn1 = fmaxf(mrow1, tm1);
        const float a0 = __expf(mrow0 - mn0), a1 = __expf(mrow1 - mn1);

        __half* Ps = smh + FP_OFF;
        float ps0 = 0.f, ps1 = 0.f;
#pragma unroll
        for (int ni = 0; ni < 16; ni++) {
            const float e0 = __expf(sacc[ni][0] - mn0);
            const float e1 = __expf(sacc[ni][1] - mn0);
            const float e2 = __expf(sacc[ni][2] - mn1);
            const float e3 = __expf(sacc[ni][3] - mn1);
            ps0 += e0 + e1; ps1 += e2 + e3;
            *(__half2*)(Ps + (rb + g    ) * FP_S + ni * 8 + t4 * 2) =
                __floats2half2_rn(e0, e1);
            *(__half2*)(Ps + (rb + g + 8) * FP_S + ni * 8 + t4 * 2) =
                __floats2half2_rn(e2, e3);
        }
        ps0 += __shfl_xor_sync(0xffffffffu, ps0, 1);
        ps0 += __shfl_xor_sync(0xffffffffu, ps0, 2);
        ps1 += __shfl_xor_sync(0xffffffffu, ps1, 1);
        ps1 += __shfl_xor_sync(0xffffffffu, ps1, 2);

        lrow0 = lrow0 * a0 + ps0;
        lrow1 = lrow1 * a1 + ps1;
        mrow0 = mn0; mrow1 = mn1;
#pragma unroll
        for (int ni = 0; ni < 8; ni++) {
            oacc[ni][0] *= a0; oacc[ni][1] *= a0;
            oacc[ni][2] *= a1; oacc[ni][3] *= a1;
        }
        __syncwarp();   // P rows are per-warp

        // O += P V  (V from buffer kt&1)
        const uint32_t vab = va + (uint32_t)(((kt & 1) * FV_BUF) << 1);
#pragma unroll
        for (int ks = 0; ks < 8; ks++) {
            const int k = ks * 16;
            uint32_t af[4];
            ldsm_x4(af, pa + (k << 1));
#pragma unroll
            for (int ni2 = 0; ni2 < 4; ni2++) {
                uint32_t bv[4];
                ldsm_x4_t(bv, vab + (uint32_t)(k * (FQ_S * 2)) + (uint32_t)(ni2 * 32));
                mma_f16(oacc[2 * ni2    ], af, bv);
                mma_f16(oacc[2 * ni2 + 1], af, bv + 2);
            }
        }
    }

    const float i0 = 1.f / lrow0, i1 = 1.f / lrow1;
    const int r0 = tileQ + rb + g, r1 = r0 + 8;
#pragma unroll
    for (int ni = 0; ni < 8; ni++) {
        const int d = ni * 8 + t4 * 2;
        *(__half2*)(H + (size_t)(b * LSEQ + r0) * D_MODEL + h * DH + d) =
            __floats2half2_rn(oacc[ni][0] * i0, oacc[ni][1] * i0);
        *(__half2*)(H + (size_t)(b * LSEQ + r1) * D_MODEL + h * DH + d) =
            __floats2half2_rn(oacc[ni][2] * i1, oacc[ni][3] * i1);
    }
}

// ---------------- weight transposes (convert to fp16 on store) ---------------
__global__ __launch_bounds__(256) void transpose_k(
    const float* __restrict__ in, __half* __restrict__ out, int K, int N)
{
    __shared__ float t[32][33];
    const int bn = blockIdx.x * 32, bk = blockIdx.y * 32;
    const int tx = threadIdx.x, ty = threadIdx.y;
#pragma unroll
    for (int i = ty; i < 32; i += 8)
        t[i][tx] = in[(size_t)(bk + i) * N + bn + tx];
    __syncthreads();
#pragma unroll
    for (int i = ty; i < 32; i += 8)
        out[(size_t)(bn + i) * K + bk + tx] = __float2half_rn(t[tx][i]);
}

__global__ __launch_bounds__(256) void transpose_k4(
    const float* __restrict__ i0, const float* __restrict__ i1,
    const float* __restrict__ i2, const float* __restrict__ i3,
    __half* __restrict__ o0, __half* __restrict__ o1,
    __half* __restrict__ o2, __half* __restrict__ o3)
{
    __shared__ float t[32][33];
    const float* in = (blockIdx.z == 0) ? i0 : (blockIdx.z == 1) ? i1 :
                      (blockIdx.z == 2) ? i2 : i3;
    __half* out = (blockIdx.z == 0) ? o0 : (blockIdx.z == 1) ? o1 :
                  (blockIdx.z == 2) ? o2 : o3;
    const int bn = blockIdx.x * 32, bk = blockIdx.y * 32;
    const int tx = threadIdx.x, ty = threadIdx.y;
#pragma unroll
    for (int i = ty; i < 32; i += 8)
        t[i][tx] = in[(size_t)(bk + i) * 1024 + bn + tx];
    __syncthreads();
#pragma unroll
    for (int i = ty; i < 32; i += 8)
        out[(size_t)(bn + i) * 1024 + bk + tx] = __float2half_rn(t[tx][i]);
}

// ---------------- half-copy (x -> fp16 twin) ---------------------------------
__global__ __launch_bounds__(256) void half_copy(
    const float* __restrict__ in, __half* __restrict__ out)
{
    const size_t i = ((size_t)blockIdx.x * 256 + threadIdx.x) * 4;
    float4 v = *(const float4*)(in + i);
    *(__half2*)(out + i)     = __floats2half2_rn(v.x, v.y);
    *(__half2*)(out + i + 2) = __floats2half2_rn(v.z, v.w);
}

// ---------------- layernorm (optional fp16 twin output) ----------------------
__global__ __launch_bounds__(256) void layernorm(
    const float* __restrict__ X, const float* __restrict__ g,
    const float* __restrict__ be, float* __restrict__ O,
    __half* __restrict__ Or)
{
    __shared__ float red[8];
    const int r = blockIdx.x;
    const int tid = threadIdx.x;
    const float4 v = *(const float4*)(X + (size_t)r * D_MODEL + tid * 4);

    float s = v.x + v.y + v.z + v.w;
#pragma unroll
    for (int o = 16; o > 0; o >>= 1) s += __shfl_xor_sync(0xffffffffu, s, o);
    if ((tid & 31) == 0) red[tid >> 5] = s;
    __syncthreads();
    s = 0.f;
#pragma unroll
    for (int i = 0; i < 8; i++) s += red[i];
    const float mu = s * (1.f / D_MODEL);
    __syncthreads();

    float dx = v.x - mu, dy = v.y - mu, dz = v.z - mu, dw = v.w - mu;
    float sq = dx * dx + dy * dy + dz * dz + dw * dw;
#pragma unroll
    for (int o = 16; o > 0; o >>= 1) sq += __shfl_xor_sync(0xffffffffu, sq, o);
    if ((tid & 31) == 0) red[tid >> 5] = sq;
    __syncthreads();
    sq = 0.f;
#pragma unroll
    for (int i = 0; i < 8; i++) sq += red[i];
    const float rs = rsqrtf(sq * (1.f / D_MODEL) + 1e-5f);

    const float4 gg = *(const float4*)(g + tid * 4);
    const float4 bb = *(const float4*)(be + tid * 4);
    float4 o;
    o.x = dx * rs * gg.x + bb.x;
    o.y = dy * rs * gg.y + bb.y;
    o.z = dz * rs * gg.z + bb.z;
    o.w = dw * rs * gg.w + bb.w;
    *(float4*)(O + (size_t)r * D_MODEL + tid * 4) = o;
    if (Or) {
        *(__half2*)(Or + (size_t)r * D_MODEL + tid * 4)     = __floats2half2_rn(o.x, o.y);
        *(__half2*)(Or + (size_t)r * D_MODEL + tid * 4 + 2) = __floats2half2_rn(o.z, o.w);
    }
}

// ---------------- launch -----------------------------------------------------
extern "C" void kernel_launch(void* const* d_in, const int* in_sizes, int n_in,
                              void* d_out, int out_size)
{
    const float* x   = (const float*)d_in[0];
    const int*   msk = (const int*)d_in[1];
    const float* Wq  = (const float*)d_in[2];
    const float* Wk  = (const float*)d_in[3];
    const float* Wv  = (const float*)d_in[4];
    const float* Wp  = (const float*)d_in[5];
    const float* bp  = (const float*)d_in[6];
    const float* W1  = (const float*)d_in[7];
    const float* b1  = (const float*)d_in[8];
    const float* W2  = (const float*)d_in[9];
    const float* b2  = (const float*)d_in[10];
    const float* g1  = (const float*)d_in[11];
    const float* be1 = (const float*)d_in[12];
    const float* g2  = (const float*)d_in[13];
    const float* be2 = (const float*)d_in[14];
    float* out = (float*)d_out;

    float *tmp, *h;
    __half *q, *k, *v, *hd, *hh, *xh, *ff, *wtqkv, *wtp, *wt1, *wt2;
    cudaGetSymbolAddress((void**)&q,     g_q);
    cudaGetSymbolAddress((void**)&k,     g_k);
    cudaGetSymbolAddress((void**)&v,     g_v);
    cudaGetSymbolAddress((void**)&hd,    g_heads);
    cudaGetSymbolAddress((void**)&tmp,   g_tmp);
    cudaGetSymbolAddress((void**)&h,     g_h);
    cudaGetSymbolAddress((void**)&hh,    g_hh);
    cudaGetSymbolAddress((void**)&xh,    g_xh);
    cudaGetSymbolAddress((void**)&ff,    g_ff);
    cudaGetSymbolAddress((void**)&wtqkv, g_wtqkv);
    cudaGetSymbolAddress((void**)&wtp,   g_wtp);
    cudaGetSymbolAddress((void**)&wt1,   g_wt1);
    cudaGetSymbolAddress((void**)&wt2,   g_wt2);

    static cudaStream_t s_side = nullptr, s_side2 = nullptr;
    static cudaEvent_t ev_fork = nullptr, ev_join = nullptr, ev_join2 = nullptr;
    static bool attr_done = false;
    if (!attr_done) {
        cudaFuncSetAttribute(gemm_mma<EPI_QKV>,
                             cudaFuncAttributeMaxDynamicSharedMemorySize, GM_SMEM_B);
        cudaFuncSetAttribute(gemm_mma<EPI_BIAS_RESID>,
                             cudaFuncAttributeMaxDynamicSharedMemorySize, GM_SMEM_B);
        cudaFuncSetAttribute(gemm_mma<EPI_BIAS_RELU>,
                             cudaFuncAttributeMaxDynamicSharedMemorySize, GM_SMEM_B);
        cudaFuncSetAttribute(flash_attn,
                             cudaFuncAttributeMaxDynamicSharedMemorySize, FA_SMEM_B);
        cudaStreamCreateWithFlags(&s_side, cudaStreamNonBlocking);
        cudaStreamCreateWithFlags(&s_side2, cudaStreamNonBlocking);
        cudaEventCreateWithFlags(&ev_fork, cudaEventDisableTiming);
        cudaEventCreateWithFlags(&ev_join, cudaEventDisableTiming);
        cudaEventCreateWithFlags(&ev_join2, cudaEventDisableTiming);
        attr_done = true;
    }

    dim3 blk(256);
    dim3 tb(32, 8);

    // Fork: W1/W2 transposes on s_side (joined before FF1); half_copy on
    // s_side2 (joined before QKV), overlapping transpose_k4 on the main stream.
    cudaEventRecord(ev_fork, 0);
    cudaStreamWaitEvent(s_side, ev_fork, 0);
    cudaStreamWaitEvent(s_side2, ev_fork, 0);
    transpose_k<<<dim3(128, 32), tb, 0, s_side>>>(W1, wt1, D_MODEL, DFF);
    transpose_k<<<dim3(32, 128), tb, 0, s_side>>>(W2, wt2, DFF, D_MODEL);
    cudaEventRecord(ev_join, s_side);
    half_copy<<<MROWS * D_MODEL / 1024, blk, 0, s_side2>>>(x, xh);
    cudaEventRecord(ev_join2, s_side2);

    // main stream: QKV-path weights
    transpose_k4<<<dim3(32, 32, 4), tb>>>(
        Wq, Wk, Wv, Wp,
        wtqkv + 0 * 1024 * 1024, wtqkv + 1 * 1024 * 1024,
        wtqkv + 2 * 1024 * 1024, wtp);

    // join xh, then fused QKV projection (fp16 in/out), scatter to head layout
    cudaStreamWaitEvent(0, ev_join2, 0);
    gemm_mma<EPI_QKV><<<dim3(24, 32), blk, GM_SMEM_B>>>(
        xh, wtqkv, nullptr, nullptr, 3072, 1024, nullptr, nullptr, q, k, v);

    // fused attention (fp16 MMA + ldmatrix + cp.async prefetch)
    flash_attn<<<dim3(8, ZHEADS), blk, FA_SMEM_B>>>(q, k, v, msk, hd);

    // proj + bias + residual(x fp32), LN1 (h fp32 + hh fp16)
    gemm_mma<EPI_BIAS_RESID><<<dim3(8, 32), blk, GM_SMEM_B>>>(
        hd, wtp, tmp, nullptr, 1024, 1024, bp, x, nullptr, nullptr, nullptr);
    layernorm<<<MROWS, blk>>>(tmp, g1, be1, h, hh);

    // join side stream (wt1/wt2 ready), then FF1/FF2
    cudaStreamWaitEvent(0, ev_join, 0);
    gemm_mma<EPI_BIAS_RELU><<<dim3(32, 32), blk, GM_SMEM_B>>>(
        hh, wt1, nullptr, ff, 4096, 1024, b1, nullptr, nullptr, nullptr, nullptr);
    gemm_mma<EPI_BIAS_RESID><<<dim3(8, 32), blk, GM_SMEM_B>>>(
        ff, wt2, tmp, nullptr, 1024, 4096, b2, h, nullptr, nullptr, nullptr);
    layernorm<<<MROWS, blk>>>(tmp, g2, be2, out, nullptr);
}